// round 3
// baseline (speedup 1.0000x reference)
#include <cuda_runtime.h>
#include <math.h>

#define BB 4
#define LL 1024
#define DD 1024
#define NN 16
#define HH 64
#define RR 2048

// ---------------- scratch (static device globals: no allocations allowed) ---
__device__ float g_qh[BB*NN*LL*HH];   // [b][n][l][h]
__device__ float g_kh[BB*NN*LL*HH];
__device__ float g_vh[BB*NN*LL*HH];
__device__ float g_r [NN*RR*HH];      // [n][j][h]
__device__ float g_o [BB*NN*LL*HH];   // attention output [b][n][l][h]
__device__ float g_x [BB*LL*DD];      // pre-layernorm residual sum

// ---------------- generic 128x128x16 fp32 GEMM ------------------------------
enum { MODE_PROJ = 0, MODE_RPOS = 1, MODE_POST = 2 };

template<int MODE>
__global__ __launch_bounds__(256)
void gemm128(const float* __restrict__ A, const float* __restrict__ W,
             const float* __restrict__ bias, const float* __restrict__ resid,
             float* __restrict__ C, int K)
{
    __shared__ float As[16][132];
    __shared__ float Ws[16][132];
    const int tid  = threadIdx.x;
    const int row0 = blockIdx.y * 128;
    const int col0 = blockIdx.x * 128;
    const int ty = tid >> 4, tx = tid & 15;

    float acc[8][8];
    #pragma unroll
    for (int i = 0; i < 8; i++)
        #pragma unroll
        for (int j = 0; j < 8; j++) acc[i][j] = 0.f;

    const int am = tid >> 1;          // A row within tile
    const int ak = (tid & 1) * 8;     // A k offset (8 contiguous)
    const int wk = tid >> 4;          // W k row
    const int wc = (tid & 15) * 8;    // W col offset (8 contiguous)

    for (int k0 = 0; k0 < K; k0 += 16) {
        // ---- load A tile (128 x 16), store K-major As[kk][m]
        {
            const int row = row0 + am;
            long base;
            if (MODE == MODE_POST) {
                const int k = k0 + ak;
                base = (long)(row >> 10) * (NN*LL*HH) + (long)(k >> 6) * (LL*HH)
                     + (long)(row & 1023) * HH + (k & 63);
            } else {
                base = (long)row * K + (k0 + ak);
            }
            float4 v0 = *reinterpret_cast<const float4*>(A + base);
            float4 v1 = *reinterpret_cast<const float4*>(A + base + 4);
            As[ak+0][am] = v0.x; As[ak+1][am] = v0.y;
            As[ak+2][am] = v0.z; As[ak+3][am] = v0.w;
            As[ak+4][am] = v1.x; As[ak+5][am] = v1.y;
            As[ak+6][am] = v1.z; As[ak+7][am] = v1.w;
        }
        // ---- load W tile (16 x 128)
        {
            const int k   = k0 + wk;
            const int col = col0 + wc;
            long base;
            if (MODE == MODE_RPOS) {
                base = (long)(col >> 6) * (DD*HH) + (long)k * HH + (col & 63);
            } else {
                base = (long)k * 1024 + col;
            }
            float4 v0 = *reinterpret_cast<const float4*>(W + base);
            float4 v1 = *reinterpret_cast<const float4*>(W + base + 4);
            *reinterpret_cast<float4*>(&Ws[wk][wc])     = v0;
            *reinterpret_cast<float4*>(&Ws[wk][wc + 4]) = v1;
        }
        __syncthreads();

        #pragma unroll
        for (int kk = 0; kk < 16; kk++) {
            float a[8], w[8];
            *reinterpret_cast<float4*>(a)     = *reinterpret_cast<const float4*>(&As[kk][ty*8]);
            *reinterpret_cast<float4*>(a + 4) = *reinterpret_cast<const float4*>(&As[kk][ty*8 + 4]);
            *reinterpret_cast<float4*>(w)     = *reinterpret_cast<const float4*>(&Ws[kk][tx*8]);
            *reinterpret_cast<float4*>(w + 4) = *reinterpret_cast<const float4*>(&Ws[kk][tx*8 + 4]);
            #pragma unroll
            for (int i = 0; i < 8; i++)
                #pragma unroll
                for (int j = 0; j < 8; j++)
                    acc[i][j] = fmaf(a[i], w[j], acc[i][j]);
        }
        __syncthreads();
    }

    // ---- epilogue
    #pragma unroll
    for (int i = 0; i < 8; i++) {
        const int row = row0 + ty*8 + i;
        #pragma unroll
        for (int j = 0; j < 8; j++) {
            const int col = col0 + tx*8 + j;
            float val = acc[i][j];
            if (MODE == MODE_PROJ) {
                if (bias) val += bias[col];
                long o = (long)((row >> 10) * NN + (col >> 6)) * (LL*HH)
                       + (long)(row & 1023) * HH + (col & 63);
                C[o] = val;
            } else if (MODE == MODE_RPOS) {
                long o = (long)(col >> 6) * (RR*HH) + (long)row * HH + (col & 63);
                C[o] = val;
            } else {
                long o = (long)row * 1024 + col;
                val += bias[col] + resid[o];
                C[o] = val;
            }
        }
    }
}

// ---------------- fused attention (scores + rel-pos + mask + softmax + PV) --
#define ATT_SMEM_FLOATS 25856

__global__ __launch_bounds__(256)
void attn_kernel(const int* __restrict__ padding,   // 4-byte elements, nonzero = masked
                 const float* __restrict__ rwb,
                 const float* __restrict__ rrb)
{
    extern __shared__ float sm[];
    float* QW     = sm;                    // [64][68]
    float* KT     = QW + 64*68;            // [64][68]
    float* RB     = KT + 64*68;            // [64][128] (aliases G2s)
    float* G2s    = RB;                    // [128][65]
    float* Ps     = RB + 8320;             // [64][68]
    float* Vs     = Ps + 64*68;            // [64][68]
    float* deltas = Vs + 64*68;            // [64]
    float* maskv  = deltas + 64;           // [64]

    const int tid = threadIdx.x;
    const int ty = tid >> 4, tx = tid & 15;
    const int bn = blockIdx.y;             // b*N + n
    const int l0 = blockIdx.x * 64;
    const int b  = bn >> 4;
    const int n  = bn & 15;
    const float scale = 0.125f;            // 64^{-1/2}

    const float* qh = g_qh + (long)bn * (LL*HH);
    const float* kh = g_kh + (long)bn * (LL*HH);
    const float* vh = g_vh + (long)bn * (LL*HH);
    const float* rp = g_r  + (long)n  * (RR*HH);
    float*       op = g_o  + (long)bn * (LL*HH);

    const int hq  = (tid & 15) * 4;        // h offset for loaders
    const int r16 = tid >> 4;              // row group for loaders

    if (tid < 64) deltas[tid] = rrb[n*64 + tid] - rwb[n*64 + tid];

    // load QW transposed, add r_w_bias
    {
        float bw0 = rwb[n*64 + hq + 0];
        float bw1 = rwb[n*64 + hq + 1];
        float bw2 = rwb[n*64 + hq + 2];
        float bw3 = rwb[n*64 + hq + 3];
        #pragma unroll
        for (int it = 0; it < 4; it++) {
            const int l = r16 + it*16;
            float4 v = *reinterpret_cast<const float4*>(qh + (long)(l0 + l)*64 + hq);
            QW[(hq+0)*68 + l] = v.x + bw0;
            QW[(hq+1)*68 + l] = v.y + bw1;
            QW[(hq+2)*68 + l] = v.z + bw2;
            QW[(hq+3)*68 + l] = v.w + bw3;
        }
    }

    float O[4][4];
    float mi[4], li[4];
    #pragma unroll
    for (int i = 0; i < 4; i++) {
        mi[i] = -1e30f; li[i] = 0.f;
        #pragma unroll
        for (int j = 0; j < 4; j++) O[i][j] = 0.f;
    }
    __syncthreads();

    for (int m0 = 0; m0 < LL; m0 += 64) {
        // ---- phase 1: load KT (transposed), RB band (transposed), Vs, maskv
        #pragma unroll
        for (int it = 0; it < 4; it++) {
            const int m = r16 + it*16;
            float4 v = *reinterpret_cast<const float4*>(kh + (long)(m0 + m)*64 + hq);
            KT[(hq+0)*68 + m] = v.x;
            KT[(hq+1)*68 + m] = v.y;
            KT[(hq+2)*68 + m] = v.z;
            KT[(hq+3)*68 + m] = v.w;
        }
        const int jmin = LL + m0 - l0 - 63;
        #pragma unroll
        for (int it = 0; it < 8; it++) {
            const int u = r16 + it*16;
            float4 v = make_float4(0.f, 0.f, 0.f, 0.f);
            if (u < 127)
                v = *reinterpret_cast<const float4*>(rp + (long)(jmin + u)*64 + hq);
            RB[(hq+0)*128 + u] = v.x;
            RB[(hq+1)*128 + u] = v.y;
            RB[(hq+2)*128 + u] = v.z;
            RB[(hq+3)*128 + u] = v.w;
        }
        #pragma unroll
        for (int it = 0; it < 4; it++) {
            const int m = r16 + it*16;
            float4 v = *reinterpret_cast<const float4*>(vh + (long)(m0 + m)*64 + hq);
            *reinterpret_cast<float4*>(&Vs[m*68 + hq]) = v;
        }
        if (tid < 64)
            maskv[tid] = (padding[b*LL + m0 + tid] != 0) ? -1000000.0f : 0.0f;
        __syncthreads();

        // ---- phase 2: G1[l,m] = qw.k  and  G2[l,u] = (qw+delta).r_band
        float g1[4][4], g2[4][8];
        #pragma unroll
        for (int i = 0; i < 4; i++) {
            #pragma unroll
            for (int j = 0; j < 4; j++) g1[i][j] = 0.f;
            #pragma unroll
            for (int j = 0; j < 8; j++) g2[i][j] = 0.f;
        }
        for (int h = 0; h < 64; h++) {
            float a[4], kx[4], rv[8];
            *reinterpret_cast<float4*>(a)      = *reinterpret_cast<const float4*>(&QW[h*68 + ty*4]);
            *reinterpret_cast<float4*>(kx)     = *reinterpret_cast<const float4*>(&KT[h*68 + tx*4]);
            *reinterpret_cast<float4*>(rv)     = *reinterpret_cast<const float4*>(&RB[h*128 + tx*8]);
            *reinterpret_cast<float4*>(rv + 4) = *reinterpret_cast<const float4*>(&RB[h*128 + tx*8 + 4]);
            const float d = deltas[h];
            #pragma unroll
            for (int i = 0; i < 4; i++) {
                const float ar = a[i] + d;
                #pragma unroll
                for (int j = 0; j < 4; j++) g1[i][j] = fmaf(a[i], kx[j], g1[i][j]);
                #pragma unroll
                for (int j = 0; j < 8; j++) g2[i][j] = fmaf(ar, rv[j], g2[i][j]);
            }
        }
        __syncthreads();           // everyone done reading RB

        // ---- phase 3: spill G2 -> smem [u][l]
        #pragma unroll
        for (int iu = 0; iu < 8; iu++)
            #pragma unroll
            for (int i = 0; i < 4; i++)
                G2s[(tx*8 + iu)*65 + (ty*4 + i)] = g2[i][iu];
        __syncthreads();

        // ---- phase 4: assemble S, online softmax, write P transposed
        float p[4][4];
        #pragma unroll
        for (int i = 0; i < 4; i++) {
            float s[4];
            #pragma unroll
            for (int j = 0; j < 4; j++) {
                const int u = (tx*4 + j) - (ty*4 + i) + 63;
                s[j] = scale * (g1[i][j] + G2s[u*65 + ty*4 + i]) + maskv[tx*4 + j];
            }
            float tm = fmaxf(fmaxf(s[0], s[1]), fmaxf(s[2], s[3]));
            #pragma unroll
            for (int off = 8; off > 0; off >>= 1)
                tm = fmaxf(tm, __shfl_xor_sync(0xffffffffu, tm, off));
            const float nm    = fmaxf(mi[i], tm);
            const float alpha = __expf(mi[i] - nm);
            mi[i] = nm;
            float ts = 0.f;
            #pragma unroll
            for (int j = 0; j < 4; j++) { p[i][j] = __expf(s[j] - nm); ts += p[i][j]; }
            #pragma unroll
            for (int off = 8; off > 0; off >>= 1)
                ts += __shfl_xor_sync(0xffffffffu, ts, off);
            li[i] = li[i] * alpha + ts;
            #pragma unroll
            for (int j = 0; j < 4; j++) O[i][j] *= alpha;
            #pragma unroll
            for (int j = 0; j < 4; j++)
                Ps[(tx*4 + j)*68 + (ty*4 + i)] = p[i][j];
        }
        __syncthreads();

        // ---- phase 5: O += P @ V
        #pragma unroll 4
        for (int m = 0; m < 64; m++) {
            float pa[4], vv[4];
            *reinterpret_cast<float4*>(pa) = *reinterpret_cast<const float4*>(&Ps[m*68 + ty*4]);
            *reinterpret_cast<float4*>(vv) = *reinterpret_cast<const float4*>(&Vs[m*68 + tx*4]);
            #pragma unroll
            for (int i = 0; i < 4; i++)
                #pragma unroll
                for (int j = 0; j < 4; j++)
                    O[i][j] = fmaf(pa[i], vv[j], O[i][j]);
        }
        __syncthreads();
    }

    // ---- write normalized output
    #pragma unroll
    for (int i = 0; i < 4; i++) {
        const float inv = 1.f / li[i];
        #pragma unroll
        for (int j = 0; j < 4; j++)
            op[(long)(l0 + ty*4 + i)*64 + tx*4 + j] = O[i][j] * inv;
    }
}

// ---------------- layernorm over D per (b,l) row -----------------------------
__global__ __launch_bounds__(256)
void ln_kernel(const float* __restrict__ lng, const float* __restrict__ lnb,
               float* __restrict__ out)
{
    __shared__ float red[256];
    const int row = blockIdx.x;
    const int tid = threadIdx.x;
    const float* x = g_x + (long)row * DD;

    float v[4]; float s = 0.f;
    #pragma unroll
    for (int i = 0; i < 4; i++) { v[i] = x[tid + i*256]; s += v[i]; }
    red[tid] = s; __syncthreads();
    #pragma unroll
    for (int off = 128; off > 0; off >>= 1) {
        if (tid < off) red[tid] += red[tid + off];
        __syncthreads();
    }
    const float mu = red[0] * (1.f / DD);
    __syncthreads();

    float vs = 0.f;
    #pragma unroll
    for (int i = 0; i < 4; i++) { const float d = v[i] - mu; vs += d*d; }
    red[tid] = vs; __syncthreads();
    #pragma unroll
    for (int off = 128; off > 0; off >>= 1) {
        if (tid < off) red[tid] += red[tid + off];
        __syncthreads();
    }
    const float inv = rsqrtf(red[0] * (1.f / DD) + 1e-5f);

    #pragma unroll
    for (int i = 0; i < 4; i++) {
        const int d0 = tid + i*256;
        out[(long)row*DD + d0] = (v[i] - mu) * inv * lng[d0] + lnb[d0];
    }
}

// ---------------- launcher ---------------------------------------------------
extern "C" void kernel_launch(void* const* d_in, const int* in_sizes, int n_in,
                              void* d_out, int out_size)
{
    const float* q   = (const float*)d_in[0];
    const float* k   = (const float*)d_in[1];
    const float* v   = (const float*)d_in[2];
    const float* pe  = (const float*)d_in[3];
    const int*   pad = (const int*)d_in[4];
    const float* q_w = (const float*)d_in[5];
    const float* k_w = (const float*)d_in[6];
    const float* k_b = (const float*)d_in[7];
    const float* v_w = (const float*)d_in[8];
    const float* v_b = (const float*)d_in[9];
    const float* rwb = (const float*)d_in[10];
    const float* rrb = (const float*)d_in[11];
    const float* rk  = (const float*)d_in[12];
    const float* pw  = (const float*)d_in[13];
    const float* pb  = (const float*)d_in[14];
    const float* lng = (const float*)d_in[15];
    const float* lnb = (const float*)d_in[16];

    void *p_qh, *p_kh, *p_vh, *p_r, *p_o, *p_x;
    cudaGetSymbolAddress(&p_qh, g_qh);
    cudaGetSymbolAddress(&p_kh, g_kh);
    cudaGetSymbolAddress(&p_vh, g_vh);
    cudaGetSymbolAddress(&p_r,  g_r);
    cudaGetSymbolAddress(&p_o,  g_o);
    cudaGetSymbolAddress(&p_x,  g_x);

    const dim3 blk(256);

    gemm128<MODE_PROJ><<<dim3(8, 32), blk>>>(q, q_w, nullptr, nullptr, (float*)p_qh, DD);
    gemm128<MODE_PROJ><<<dim3(8, 32), blk>>>(k, k_w, k_b,     nullptr, (float*)p_kh, DD);
    gemm128<MODE_PROJ><<<dim3(8, 32), blk>>>(v, v_w, v_b,     nullptr, (float*)p_vh, DD);
    gemm128<MODE_RPOS><<<dim3(8, 16), blk>>>(pe, rk, nullptr, nullptr, (float*)p_r,  DD);

    const int att_smem = ATT_SMEM_FLOATS * 4;
    cudaFuncSetAttribute(attn_kernel, cudaFuncAttributeMaxDynamicSharedMemorySize, att_smem);
    attn_kernel<<<dim3(LL/64, BB*NN), blk, att_smem>>>(pad, rwb, rrb);

    gemm128<MODE_POST><<<dim3(8, 32), blk>>>((const float*)p_o, pw, pb, q, (float*)p_x, NN*HH);

    ln_kernel<<<BB*LL, blk>>>(lng, lnb, (float*)d_out);
}

// round 4
// speedup vs baseline: 2.4036x; 2.4036x over previous
#include <cuda_runtime.h>
#include <math.h>
#include <stdint.h>

#define BB 4
#define LL 1024
#define DD 1024
#define NN 16
#define HH 64
#define RR 2048

// ---------------- scratch (static device globals: no allocations allowed) ---
__device__ float g_qh[BB*NN*LL*HH];   // [b][n][l][h]
__device__ float g_kh[BB*NN*LL*HH];
__device__ float g_vh[BB*NN*LL*HH];
__device__ float g_r [NN*RR*HH];      // [n][j][h]
__device__ float g_o [BB*NN*LL*HH];   // attention output (tf32-rounded)
__device__ float g_x [BB*LL*DD];      // pre-layernorm residual sum

// tf32-rounded operand copies
__device__ float g_tq [BB*LL*DD];
__device__ float g_tk [BB*LL*DD];
__device__ float g_tv [BB*LL*DD];
__device__ float g_tpe[RR*DD];
__device__ float g_tqw[DD*NN*HH];
__device__ float g_tkw[DD*NN*HH];
__device__ float g_tvw[DD*NN*HH];
__device__ float g_trk[NN*DD*HH];
__device__ float g_tpw[NN*HH*DD];

// ---------------- helpers ---------------------------------------------------
__device__ __forceinline__ float tf32r(float x) {
    uint32_t u;
    asm("cvt.rna.tf32.f32 %0, %1;" : "=r"(u) : "f"(x));
    return __uint_as_float(u);
}

__device__ __forceinline__ void mma_tf32(float* d, const uint32_t* a, const uint32_t* b) {
    asm volatile(
        "mma.sync.aligned.m16n8k8.row.col.f32.tf32.tf32.f32 "
        "{%0,%1,%2,%3}, {%4,%5,%6,%7}, {%8,%9}, {%0,%1,%2,%3};\n"
        : "+f"(d[0]), "+f"(d[1]), "+f"(d[2]), "+f"(d[3])
        : "r"(a[0]), "r"(a[1]), "r"(a[2]), "r"(a[3]), "r"(b[0]), "r"(b[1]));
}

// ---------------- fused tf32 rounding pass (all GEMM operands) --------------
struct R9 {
    const float* in[9];
    float*       out[9];
    int          n[9];
};

__global__ __launch_bounds__(256)
void roundk(R9 r)
{
    const int seg = blockIdx.y;
    const float* in  = r.in[seg];
    float*       out = r.out[seg];
    const int n = r.n[seg];
    for (int i = (blockIdx.x*256 + threadIdx.x)*4; i < n; i += gridDim.x*256*4) {
        float4 v = *reinterpret_cast<const float4*>(in + i);
        v.x = tf32r(v.x); v.y = tf32r(v.y); v.z = tf32r(v.z); v.w = tf32r(v.w);
        *reinterpret_cast<float4*>(out + i) = v;
    }
}

// ---------------- tf32 tensor-core GEMM (128x128 tile, K=1024) --------------
// MODE_PROJ: C scatter to [b][n][l][h], optional bias[col]
// MODE_RPOS: A=[R,D], W=r_kernel [N,D,H] gather, C scatter to [n][j][h]
// MODE_POST: A=g_o gather, W row-major, C = A@W + bias + resid (row-major)
enum { MODE_PROJ = 0, MODE_RPOS = 1, MODE_POST = 2 };

struct GemmArgs {
    const float* A;
    const float* W;
    const float* bias;
    const float* resid;
    float*       C;
};

#define AS_STRIDE 36           // 32 + 4 pad (floats)
#define BS_STRIDE 136          // 128 + 8 pad (floats)
#define AS_FLOATS (128*AS_STRIDE)   // per stage
#define BS_FLOATS (32*BS_STRIDE)
#define GEMM_SMEM ((2*AS_FLOATS + 2*BS_FLOATS)*4)   // 71680 bytes

template<int MODE>
__device__ __forceinline__ void stage_copy(
    const float* __restrict__ A, const float* __restrict__ W,
    uint32_t asB, uint32_t bsB, int row0, int col0, int k0, int tid)
{
    #pragma unroll
    for (int i = 0; i < 4; i++) {
        const int c = tid + i*256;
        // A chunk: 128 rows x 8 chunks of 4 floats
        const int arow = c >> 3, akc = (c & 7) * 4;
        const float* srcA;
        if (MODE == MODE_POST) {
            const int row = row0 + arow, k = k0 + akc;
            srcA = A + (long)(row >> 10)*(NN*LL*HH) + (long)(k >> 6)*(LL*HH)
                     + (long)(row & 1023)*HH + (k & 63);
        } else {
            srcA = A + (long)(row0 + arow)*1024 + k0 + akc;
        }
        asm volatile("cp.async.cg.shared.global [%0], [%1], 16;\n"
                     :: "r"(asB + (uint32_t)((arow*AS_STRIDE + akc)*4)), "l"(srcA));
        // B chunk: 32 k x 32 chunks of 4 floats
        const int bk = c >> 5, bnc = (c & 31) * 4;
        const float* srcB;
        if (MODE == MODE_RPOS) {
            const int col = col0 + bnc;
            srcB = W + (long)(col >> 6)*(DD*HH) + (long)(k0 + bk)*HH + (col & 63);
        } else {
            srcB = W + (long)(k0 + bk)*1024 + col0 + bnc;
        }
        asm volatile("cp.async.cg.shared.global [%0], [%1], 16;\n"
                     :: "r"(bsB + (uint32_t)((bk*BS_STRIDE + bnc)*4)), "l"(srcB));
    }
    asm volatile("cp.async.commit_group;\n");
}

template<int MODE>
__global__ __launch_bounds__(256, 2)
void gemm_tf32(GemmArgs g0, GemmArgs g1, GemmArgs g2)
{
    const GemmArgs ga = (blockIdx.z == 0) ? g0 : (blockIdx.z == 1) ? g1 : g2;
    extern __shared__ float smem[];
    float* As = smem;                         // [2][128][AS_STRIDE]
    float* Bs = smem + 2*AS_FLOATS;           // [2][32][BS_STRIDE]

    const int tid  = threadIdx.x;
    const int lane = tid & 31;
    const int w    = tid >> 5;
    const int wm   = w & 1;                   // 2 warp-rows of 64
    const int wn   = w >> 1;                  // 4 warp-cols of 32
    const int row0 = blockIdx.y * 128;
    const int col0 = blockIdx.x * 128;

    const uint32_t asB = (uint32_t)__cvta_generic_to_shared(As);
    const uint32_t bsB = (uint32_t)__cvta_generic_to_shared(Bs);

    float acc[4][4][4];
    #pragma unroll
    for (int i = 0; i < 4; i++)
        #pragma unroll
        for (int j = 0; j < 4; j++)
            #pragma unroll
            for (int q = 0; q < 4; q++) acc[i][j][q] = 0.f;

    stage_copy<MODE>(ga.A, ga.W, asB, bsB, row0, col0, 0, tid);

    const int NIT = 1024/32;
    for (int it = 0; it < NIT; it++) {
        const int s = it & 1;
        if (it + 1 < NIT) {
            stage_copy<MODE>(ga.A, ga.W,
                             asB + (uint32_t)((s^1)*AS_FLOATS*4),
                             bsB + (uint32_t)((s^1)*BS_FLOATS*4),
                             row0, col0, (it+1)*32, tid);
            asm volatile("cp.async.wait_group 1;\n");
        } else {
            asm volatile("cp.async.wait_group 0;\n");
        }
        __syncthreads();

        const float* as = As + s*AS_FLOATS;
        const float* bs = Bs + s*BS_FLOATS;
        #pragma unroll
        for (int k8 = 0; k8 < 32; k8 += 8) {
            uint32_t af[4][4], bf[4][2];
            const int fr = lane >> 2;         // 0..7
            const int fc = lane & 3;          // 0..3
            #pragma unroll
            for (int im = 0; im < 4; im++) {
                const int r = wm*64 + im*16 + fr;
                const int c = k8 + fc;
                af[im][0] = __float_as_uint(as[r*AS_STRIDE + c]);
                af[im][1] = __float_as_uint(as[(r+8)*AS_STRIDE + c]);
                af[im][2] = __float_as_uint(as[r*AS_STRIDE + c + 4]);
                af[im][3] = __float_as_uint(as[(r+8)*AS_STRIDE + c + 4]);
            }
            #pragma unroll
            for (int jn = 0; jn < 4; jn++) {
                const int n = wn*32 + jn*8 + fr;
                const int kk = k8 + fc;
                bf[jn][0] = __float_as_uint(bs[kk*BS_STRIDE + n]);
                bf[jn][1] = __float_as_uint(bs[(kk+4)*BS_STRIDE + n]);
            }
            #pragma unroll
            for (int im = 0; im < 4; im++)
                #pragma unroll
                for (int jn = 0; jn < 4; jn++)
                    mma_tf32(acc[im][jn], af[im], bf[jn]);
        }
        __syncthreads();
    }

    // ---- epilogue: fragment scatter (column pairs are contiguous) ----
    const int fr = lane >> 2;
    const int fc = lane & 3;
    #pragma unroll
    for (int jn = 0; jn < 4; jn++) {
        const int colp = col0 + wn*32 + jn*8 + fc*2;
        float b0 = 0.f, b1 = 0.f;
        if (MODE != MODE_RPOS && ga.bias != nullptr) {
            b0 = ga.bias[colp]; b1 = ga.bias[colp + 1];
        }
        #pragma unroll
        for (int im = 0; im < 4; im++) {
            #pragma unroll
            for (int half = 0; half < 2; half++) {
                const int row = row0 + wm*64 + im*16 + fr + half*8;
                float v0 = acc[im][jn][half*2 + 0] + b0;
                float v1 = acc[im][jn][half*2 + 1] + b1;
                if (MODE == MODE_PROJ) {
                    long o = (long)((row >> 10)*NN + (colp >> 6))*(LL*HH)
                           + (long)(row & 1023)*HH + (colp & 63);
                    *reinterpret_cast<float2*>(ga.C + o) = make_float2(v0, v1);
                } else if (MODE == MODE_RPOS) {
                    long o = (long)(colp >> 6)*(RR*HH) + (long)row*HH + (colp & 63);
                    *reinterpret_cast<float2*>(ga.C + o) = make_float2(v0, v1);
                } else {
                    long o = (long)row*1024 + colp;
                    float2 rr = *reinterpret_cast<const float2*>(ga.resid + o);
                    *reinterpret_cast<float2*>(ga.C + o) = make_float2(v0 + rr.x, v1 + rr.y);
                }
            }
        }
    }
}

// ---------------- fused attention (scores + rel-pos + mask + softmax + PV) --
#define ATT_SMEM_FLOATS 25856

__global__ __launch_bounds__(256)
void attn_kernel(const int* __restrict__ padding,   // 4-byte elements, nonzero = masked
                 const float* __restrict__ rwb,
                 const float* __restrict__ rrb)
{
    extern __shared__ float sm[];
    float* QW     = sm;                    // [64][68]
    float* KT     = QW + 64*68;            // [64][68]
    float* RB     = KT + 64*68;            // [64][128] (aliases G2s)
    float* G2s    = RB;                    // [128][65]
    float* Ps     = RB + 8320;             // [64][68]
    float* Vs     = Ps + 64*68;            // [64][68]
    float* deltas = Vs + 64*68;            // [64]
    float* maskv  = deltas + 64;           // [64]

    const int tid = threadIdx.x;
    const int ty = tid >> 4, tx = tid & 15;
    const int bn = blockIdx.y;             // b*N + n
    const int l0 = blockIdx.x * 64;
    const int b  = bn >> 4;
    const int n  = bn & 15;
    const float scale = 0.125f;            // 64^{-1/2}

    const float* qh = g_qh + (long)bn * (LL*HH);
    const float* kh = g_kh + (long)bn * (LL*HH);
    const float* vh = g_vh + (long)bn * (LL*HH);
    const float* rp = g_r  + (long)n  * (RR*HH);
    float*       op = g_o  + (long)bn * (LL*HH);

    const int hq  = (tid & 15) * 4;        // h offset for loaders
    const int r16 = tid >> 4;              // row group for loaders

    if (tid < 64) deltas[tid] = rrb[n*64 + tid] - rwb[n*64 + tid];

    // load QW transposed, add r_w_bias
    {
        float bw0 = rwb[n*64 + hq + 0];
        float bw1 = rwb[n*64 + hq + 1];
        float bw2 = rwb[n*64 + hq + 2];
        float bw3 = rwb[n*64 + hq + 3];
        #pragma unroll
        for (int it = 0; it < 4; it++) {
            const int l = r16 + it*16;
            float4 v = *reinterpret_cast<const float4*>(qh + (long)(l0 + l)*64 + hq);
            QW[(hq+0)*68 + l] = v.x + bw0;
            QW[(hq+1)*68 + l] = v.y + bw1;
            QW[(hq+2)*68 + l] = v.z + bw2;
            QW[(hq+3)*68 + l] = v.w + bw3;
        }
    }

    float O[4][4];
    float mi[4], li[4];
    #pragma unroll
    for (int i = 0; i < 4; i++) {
        mi[i] = -1e30f; li[i] = 0.f;
        #pragma unroll
        for (int j = 0; j < 4; j++) O[i][j] = 0.f;
    }
    __syncthreads();

    for (int m0 = 0; m0 < LL; m0 += 64) {
        // ---- phase 1: load KT (transposed), RB band (transposed), Vs, maskv
        #pragma unroll
        for (int it = 0; it < 4; it++) {
            const int m = r16 + it*16;
            float4 v = *reinterpret_cast<const float4*>(kh + (long)(m0 + m)*64 + hq);
            KT[(hq+0)*68 + m] = v.x;
            KT[(hq+1)*68 + m] = v.y;
            KT[(hq+2)*68 + m] = v.z;
            KT[(hq+3)*68 + m] = v.w;
        }
        const int jmin = LL + m0 - l0 - 63;
        #pragma unroll
        for (int it = 0; it < 8; it++) {
            const int u = r16 + it*16;
            float4 v = make_float4(0.f, 0.f, 0.f, 0.f);
            if (u < 127)
                v = *reinterpret_cast<const float4*>(rp + (long)(jmin + u)*64 + hq);
            RB[(hq+0)*128 + u] = v.x;
            RB[(hq+1)*128 + u] = v.y;
            RB[(hq+2)*128 + u] = v.z;
            RB[(hq+3)*128 + u] = v.w;
        }
        #pragma unroll
        for (int it = 0; it < 4; it++) {
            const int m = r16 + it*16;
            float4 v = *reinterpret_cast<const float4*>(vh + (long)(m0 + m)*64 + hq);
            *reinterpret_cast<float4*>(&Vs[m*68 + hq]) = v;
        }
        if (tid < 64)
            maskv[tid] = (padding[b*LL + m0 + tid] != 0) ? -1000000.0f : 0.0f;
        __syncthreads();

        // ---- phase 2: G1[l,m] = qw.k  and  G2[l,u] = (qw+delta).r_band
        float g1[4][4], g2[4][8];
        #pragma unroll
        for (int i = 0; i < 4; i++) {
            #pragma unroll
            for (int j = 0; j < 4; j++) g1[i][j] = 0.f;
            #pragma unroll
            for (int j = 0; j < 8; j++) g2[i][j] = 0.f;
        }
        for (int h = 0; h < 64; h++) {
            float a[4], kx[4], rv[8];
            *reinterpret_cast<float4*>(a)      = *reinterpret_cast<const float4*>(&QW[h*68 + ty*4]);
            *reinterpret_cast<float4*>(kx)     = *reinterpret_cast<const float4*>(&KT[h*68 + tx*4]);
            *reinterpret_cast<float4*>(rv)     = *reinterpret_cast<const float4*>(&RB[h*128 + tx*8]);
            *reinterpret_cast<float4*>(rv + 4) = *reinterpret_cast<const float4*>(&RB[h*128 + tx*8 + 4]);
            const float d = deltas[h];
            #pragma unroll
            for (int i = 0; i < 4; i++) {
                const float ar = a[i] + d;
                #pragma unroll
                for (int j = 0; j < 4; j++) g1[i][j] = fmaf(a[i], kx[j], g1[i][j]);
                #pragma unroll
                for (int j = 0; j < 8; j++) g2[i][j] = fmaf(ar, rv[j], g2[i][j]);
            }
        }
        __syncthreads();           // everyone done reading RB

        // ---- phase 3: spill G2 -> smem [u][l]
        #pragma unroll
        for (int iu = 0; iu < 8; iu++)
            #pragma unroll
            for (int i = 0; i < 4; i++)
                G2s[(tx*8 + iu)*65 + (ty*4 + i)] = g2[i][iu];
        __syncthreads();

        // ---- phase 4: assemble S, online softmax, write P transposed
        float p[4][4];
        #pragma unroll
        for (int i = 0; i < 4; i++) {
            float s[4];
            #pragma unroll
            for (int j = 0; j < 4; j++) {
                const int u = (tx*4 + j) - (ty*4 + i) + 63;
                s[j] = scale * (g1[i][j] + G2s[u*65 + ty*4 + i]) + maskv[tx*4 + j];
            }
            float tm = fmaxf(fmaxf(s[0], s[1]), fmaxf(s[2], s[3]));
            #pragma unroll
            for (int off = 8; off > 0; off >>= 1)
                tm = fmaxf(tm, __shfl_xor_sync(0xffffffffu, tm, off));
            const float nm    = fmaxf(mi[i], tm);
            const float alpha = __expf(mi[i] - nm);
            mi[i] = nm;
            float ts = 0.f;
            #pragma unroll
            for (int j = 0; j < 4; j++) { p[i][j] = __expf(s[j] - nm); ts += p[i][j]; }
            #pragma unroll
            for (int off = 8; off > 0; off >>= 1)
                ts += __shfl_xor_sync(0xffffffffu, ts, off);
            li[i] = li[i] * alpha + ts;
            #pragma unroll
            for (int j = 0; j < 4; j++) O[i][j] *= alpha;
            #pragma unroll
            for (int j = 0; j < 4; j++)
                Ps[(tx*4 + j)*68 + (ty*4 + i)] = p[i][j];
        }
        __syncthreads();

        // ---- phase 5: O += P @ V
        #pragma unroll 4
        for (int m = 0; m < 64; m++) {
            float pa[4], vv[4];
            *reinterpret_cast<float4*>(pa) = *reinterpret_cast<const float4*>(&Ps[m*68 + ty*4]);
            *reinterpret_cast<float4*>(vv) = *reinterpret_cast<const float4*>(&Vs[m*68 + tx*4]);
            #pragma unroll
            for (int i = 0; i < 4; i++)
                #pragma unroll
                for (int j = 0; j < 4; j++)
                    O[i][j] = fmaf(pa[i], vv[j], O[i][j]);
        }
        __syncthreads();
    }

    // ---- write normalized output (tf32-rounded: it is the POST GEMM A operand)
    #pragma unroll
    for (int i = 0; i < 4; i++) {
        const float inv = 1.f / li[i];
        #pragma unroll
        for (int j = 0; j < 4; j++)
            op[(long)(l0 + ty*4 + i)*64 + tx*4 + j] = tf32r(O[i][j] * inv);
    }
}

// ---------------- layernorm over D per (b,l) row -----------------------------
__global__ __launch_bounds__(256)
void ln_kernel(const float* __restrict__ lng, const float* __restrict__ lnb,
               float* __restrict__ out)
{
    __shared__ float red[256];
    const int row = blockIdx.x;
    const int tid = threadIdx.x;
    const float* x = g_x + (long)row * DD;

    float v[4]; float s = 0.f;
    #pragma unroll
    for (int i = 0; i < 4; i++) { v[i] = x[tid + i*256]; s += v[i]; }
    red[tid] = s; __syncthreads();
    #pragma unroll
    for (int off = 128; off > 0; off >>= 1) {
        if (tid < off) red[tid] += red[tid + off];
        __syncthreads();
    }
    const float mu = red[0] * (1.f / DD);
    __syncthreads();

    float vs = 0.f;
    #pragma unroll
    for (int i = 0; i < 4; i++) { const float d = v[i] - mu; vs += d*d; }
    red[tid] = vs; __syncthreads();
    #pragma unroll
    for (int off = 128; off > 0; off >>= 1) {
        if (tid < off) red[tid] += red[tid + off];
        __syncthreads();
    }
    const float inv = rsqrtf(red[0] * (1.f / DD) + 1e-5f);

    #pragma unroll
    for (int i = 0; i < 4; i++) {
        const int d0 = tid + i*256;
        out[(long)row*DD + d0] = (v[i] - mu) * inv * lng[d0] + lnb[d0];
    }
}

// ---------------- launcher ---------------------------------------------------
extern "C" void kernel_launch(void* const* d_in, const int* in_sizes, int n_in,
                              void* d_out, int out_size)
{
    const float* q   = (const float*)d_in[0];
    const float* k   = (const float*)d_in[1];
    const float* v   = (const float*)d_in[2];
    const float* pe  = (const float*)d_in[3];
    const int*   pad = (const int*)d_in[4];
    const float* q_w = (const float*)d_in[5];
    const float* k_w = (const float*)d_in[6];
    const float* k_b = (const float*)d_in[7];
    const float* v_w = (const float*)d_in[8];
    const float* v_b = (const float*)d_in[9];
    const float* rwb = (const float*)d_in[10];
    const float* rrb = (const float*)d_in[11];
    const float* rk  = (const float*)d_in[12];
    const float* pw  = (const float*)d_in[13];
    const float* pb  = (const float*)d_in[14];
    const float* lng = (const float*)d_in[15];
    const float* lnb = (const float*)d_in[16];

    void *p_qh, *p_kh, *p_vh, *p_r, *p_o, *p_x;
    void *p_tq, *p_tk, *p_tv, *p_tpe, *p_tqw, *p_tkw, *p_tvw, *p_trk, *p_tpw;
    cudaGetSymbolAddress(&p_qh, g_qh);
    cudaGetSymbolAddress(&p_kh, g_kh);
    cudaGetSymbolAddress(&p_vh, g_vh);
    cudaGetSymbolAddress(&p_r,  g_r);
    cudaGetSymbolAddress(&p_o,  g_o);
    cudaGetSymbolAddress(&p_x,  g_x);
    cudaGetSymbolAddress(&p_tq,  g_tq);
    cudaGetSymbolAddress(&p_tk,  g_tk);
    cudaGetSymbolAddress(&p_tv,  g_tv);
    cudaGetSymbolAddress(&p_tpe, g_tpe);
    cudaGetSymbolAddress(&p_tqw, g_tqw);
    cudaGetSymbolAddress(&p_tkw, g_tkw);
    cudaGetSymbolAddress(&p_tvw, g_tvw);
    cudaGetSymbolAddress(&p_trk, g_trk);
    cudaGetSymbolAddress(&p_tpw, g_tpw);

    const dim3 blk(256);

    // ---- pass 1: tf32-round all GEMM operands (one fused launch)
    R9 r;
    r.in[0]=q;   r.out[0]=(float*)p_tq;  r.n[0]=BB*LL*DD;
    r.in[1]=k;   r.out[1]=(float*)p_tk;  r.n[1]=BB*LL*DD;
    r.in[2]=v;   r.out[2]=(float*)p_tv;  r.n[2]=BB*LL*DD;
    r.in[3]=pe;  r.out[3]=(float*)p_tpe; r.n[3]=RR*DD;
    r.in[4]=q_w; r.out[4]=(float*)p_tqw; r.n[4]=DD*NN*HH;
    r.in[5]=k_w; r.out[5]=(float*)p_tkw; r.n[5]=DD*NN*HH;
    r.in[6]=v_w; r.out[6]=(float*)p_tvw; r.n[6]=DD*NN*HH;
    r.in[7]=rk;  r.out[7]=(float*)p_trk; r.n[7]=NN*DD*HH;
    r.in[8]=pw;  r.out[8]=(float*)p_tpw; r.n[8]=NN*HH*DD;
    roundk<<<dim3(1024, 9), blk>>>(r);

    // ---- pass 2: projections (q/k/v fused via grid.z) + rpos, tf32 MMA
    cudaFuncSetAttribute(gemm_tf32<MODE_PROJ>, cudaFuncAttributeMaxDynamicSharedMemorySize, GEMM_SMEM);
    cudaFuncSetAttribute(gemm_tf32<MODE_RPOS>, cudaFuncAttributeMaxDynamicSharedMemorySize, GEMM_SMEM);
    cudaFuncSetAttribute(gemm_tf32<MODE_POST>, cudaFuncAttributeMaxDynamicSharedMemorySize, GEMM_SMEM);

    GemmArgs gq = { (const float*)p_tq, (const float*)p_tqw, nullptr, nullptr, (float*)p_qh };
    GemmArgs gk = { (const float*)p_tk, (const float*)p_tkw, k_b,     nullptr, (float*)p_kh };
    GemmArgs gv = { (const float*)p_tv, (const float*)p_tvw, v_b,     nullptr, (float*)p_vh };
    gemm_tf32<MODE_PROJ><<<dim3(8, 32, 3), blk, GEMM_SMEM>>>(gq, gk, gv);

    GemmArgs gr = { (const float*)p_tpe, (const float*)p_trk, nullptr, nullptr, (float*)p_r };
    gemm_tf32<MODE_RPOS><<<dim3(8, 16, 1), blk, GEMM_SMEM>>>(gr, gr, gr);

    // ---- pass 3: fused attention (fp32)
    const int att_smem = ATT_SMEM_FLOATS * 4;
    cudaFuncSetAttribute(attn_kernel, cudaFuncAttributeMaxDynamicSharedMemorySize, att_smem);
    attn_kernel<<<dim3(LL/64, BB*NN), blk, att_smem>>>(pad, rwb, rrb);

    // ---- pass 4: post GEMM (+bias +residual), tf32 MMA
    GemmArgs gp = { (const float*)p_o, (const float*)p_tpw, pb, q, (float*)p_x };
    gemm_tf32<MODE_POST><<<dim3(8, 32, 1), blk, GEMM_SMEM>>>(gp, gp, gp);

    // ---- pass 5: layernorm
    ln_kernel<<<BB*LL, blk>>>(lng, lnb, (float*)d_out);
}

// round 6
// speedup vs baseline: 4.0983x; 1.7051x over previous
#include <cuda_runtime.h>
#include <math.h>
#include <stdint.h>

#define BB 4
#define LL 1024
#define DD 1024
#define NN 16
#define HH 64
#define RR 2048

// ---------------- scratch (static device globals: no allocations allowed) ---
__device__ float g_qh[BB*NN*LL*HH];   // [b][n][l][h] (tf32-rounded)
__device__ float g_kh[BB*NN*LL*HH];   // (tf32-rounded, k_b added)
__device__ float g_vh[BB*NN*LL*HH];   // (tf32-rounded, v_b added)
__device__ float g_r [NN*RR*HH];      // [n][j][h] (tf32-rounded)
__device__ float g_o [BB*NN*LL*HH];   // attention output (tf32-rounded)
__device__ float g_x [BB*LL*DD];      // pre-layernorm residual sum

// tf32-rounded operand copies
__device__ float g_tq [BB*LL*DD];
__device__ float g_tk [BB*LL*DD];
__device__ float g_tv [BB*LL*DD];
__device__ float g_tpe[RR*DD];
__device__ float g_tqw[DD*NN*HH];
__device__ float g_tkw[DD*NN*HH];
__device__ float g_tvw[DD*NN*HH];
__device__ float g_trk[NN*DD*HH];
__device__ float g_tpw[NN*HH*DD];

// ---------------- helpers ---------------------------------------------------
__device__ __forceinline__ float tf32r(float x) {
    uint32_t u;
    asm("cvt.rna.tf32.f32 %0, %1;" : "=r"(u) : "f"(x));
    return __uint_as_float(u);
}
__device__ __forceinline__ uint32_t tf32u(float x) {
    uint32_t u;
    asm("cvt.rna.tf32.f32 %0, %1;" : "=r"(u) : "f"(x));
    return u;
}
__device__ __forceinline__ float ex2f(float x) {
    float y;
    asm("ex2.approx.ftz.f32 %0, %1;" : "=f"(y) : "f"(x));
    return y;
}

__device__ __forceinline__ void mma_tf32(float* d, const uint32_t* a, const uint32_t* b) {
    asm volatile(
        "mma.sync.aligned.m16n8k8.row.col.f32.tf32.tf32.f32 "
        "{%0,%1,%2,%3}, {%4,%5,%6,%7}, {%8,%9}, {%0,%1,%2,%3};\n"
        : "+f"(d[0]), "+f"(d[1]), "+f"(d[2]), "+f"(d[3])
        : "r"(a[0]), "r"(a[1]), "r"(a[2]), "r"(a[3]), "r"(b[0]), "r"(b[1]));
}

// ---------------- fused tf32 rounding pass (all GEMM operands) --------------
struct R9 {
    const float* in[9];
    float*       out[9];
    int          n[9];
};

__global__ __launch_bounds__(256)
void roundk(R9 r)
{
    const int seg = blockIdx.y;
    const float* in  = r.in[seg];
    float*       out = r.out[seg];
    const int n = r.n[seg];
    for (int i = (blockIdx.x*256 + threadIdx.x)*4; i < n; i += gridDim.x*256*4) {
        float4 v = *reinterpret_cast<const float4*>(in + i);
        v.x = tf32r(v.x); v.y = tf32r(v.y); v.z = tf32r(v.z); v.w = tf32r(v.w);
        *reinterpret_cast<float4*>(out + i) = v;
    }
}

// ---------------- tf32 tensor-core GEMM (128x128 tile, K=1024) --------------
enum { MODE_PROJ = 0, MODE_RPOS = 1, MODE_POST = 2 };

struct GemmArgs {
    const float* A;
    const float* W;
    const float* bias;
    const float* resid;
    float*       C;
};

#define AS_STRIDE 36           // 32 + 4 pad (floats)
#define BS_STRIDE 136          // 128 + 8 pad (floats)
#define AS_FLOATS (128*AS_STRIDE)   // per stage
#define BS_FLOATS (32*BS_STRIDE)
#define GEMM_SMEM ((2*AS_FLOATS + 2*BS_FLOATS)*4)   // 71680 bytes

template<int MODE>
__device__ __forceinline__ void stage_copy(
    const float* __restrict__ A, const float* __restrict__ W,
    uint32_t asB, uint32_t bsB, int row0, int col0, int k0, int tid)
{
    #pragma unroll
    for (int i = 0; i < 4; i++) {
        const int c = tid + i*256;
        const int arow = c >> 3, akc = (c & 7) * 4;
        const float* srcA;
        if (MODE == MODE_POST) {
            const int row = row0 + arow, k = k0 + akc;
            srcA = A + (long)(row >> 10)*(NN*LL*HH) + (long)(k >> 6)*(LL*HH)
                     + (long)(row & 1023)*HH + (k & 63);
        } else {
            srcA = A + (long)(row0 + arow)*1024 + k0 + akc;
        }
        asm volatile("cp.async.cg.shared.global [%0], [%1], 16;\n"
                     :: "r"(asB + (uint32_t)((arow*AS_STRIDE + akc)*4)), "l"(srcA));
        const int bk = c >> 5, bnc = (c & 31) * 4;
        const float* srcB;
        if (MODE == MODE_RPOS) {
            const int col = col0 + bnc;
            srcB = W + (long)(col >> 6)*(DD*HH) + (long)(k0 + bk)*HH + (col & 63);
        } else {
            srcB = W + (long)(k0 + bk)*1024 + col0 + bnc;
        }
        asm volatile("cp.async.cg.shared.global [%0], [%1], 16;\n"
                     :: "r"(bsB + (uint32_t)((bk*BS_STRIDE + bnc)*4)), "l"(srcB));
    }
    asm volatile("cp.async.commit_group;\n");
}

template<int MODE>
__global__ __launch_bounds__(256, 2)
void gemm_tf32(GemmArgs g0, GemmArgs g1, GemmArgs g2)
{
    const GemmArgs ga = (blockIdx.z == 0) ? g0 : (blockIdx.z == 1) ? g1 : g2;
    extern __shared__ float smem[];
    float* As = smem;
    float* Bs = smem + 2*AS_FLOATS;

    const int tid  = threadIdx.x;
    const int lane = tid & 31;
    const int w    = tid >> 5;
    const int wm   = w & 1;
    const int wn   = w >> 1;
    const int row0 = blockIdx.y * 128;
    const int col0 = blockIdx.x * 128;

    const uint32_t asB = (uint32_t)__cvta_generic_to_shared(As);
    const uint32_t bsB = (uint32_t)__cvta_generic_to_shared(Bs);

    float acc[4][4][4];
    #pragma unroll
    for (int i = 0; i < 4; i++)
        #pragma unroll
        for (int j = 0; j < 4; j++)
            #pragma unroll
            for (int q = 0; q < 4; q++) acc[i][j][q] = 0.f;

    stage_copy<MODE>(ga.A, ga.W, asB, bsB, row0, col0, 0, tid);

    const int NIT = 1024/32;
    for (int it = 0; it < NIT; it++) {
        const int s = it & 1;
        if (it + 1 < NIT) {
            stage_copy<MODE>(ga.A, ga.W,
                             asB + (uint32_t)((s^1)*AS_FLOATS*4),
                             bsB + (uint32_t)((s^1)*BS_FLOATS*4),
                             row0, col0, (it+1)*32, tid);
            asm volatile("cp.async.wait_group 1;\n");
        } else {
            asm volatile("cp.async.wait_group 0;\n");
        }
        __syncthreads();

        const float* as = As + s*AS_FLOATS;
        const float* bs = Bs + s*BS_FLOATS;
        #pragma unroll
        for (int k8 = 0; k8 < 32; k8 += 8) {
            uint32_t af[4][4], bf[4][2];
            const int fr = lane >> 2;
            const int fc = lane & 3;
            #pragma unroll
            for (int im = 0; im < 4; im++) {
                const int r = wm*64 + im*16 + fr;
                const int c = k8 + fc;
                af[im][0] = __float_as_uint(as[r*AS_STRIDE + c]);
                af[im][1] = __float_as_uint(as[(r+8)*AS_STRIDE + c]);
                af[im][2] = __float_as_uint(as[r*AS_STRIDE + c + 4]);
                af[im][3] = __float_as_uint(as[(r+8)*AS_STRIDE + c + 4]);
            }
            #pragma unroll
            for (int jn = 0; jn < 4; jn++) {
                const int nn = wn*32 + jn*8 + fr;
                const int kk = k8 + fc;
                bf[jn][0] = __float_as_uint(bs[kk*BS_STRIDE + nn]);
                bf[jn][1] = __float_as_uint(bs[(kk+4)*BS_STRIDE + nn]);
            }
            #pragma unroll
            for (int im = 0; im < 4; im++)
                #pragma unroll
                for (int jn = 0; jn < 4; jn++)
                    mma_tf32(acc[im][jn], af[im], bf[jn]);
        }
        __syncthreads();
    }

    const int fr = lane >> 2;
    const int fc = lane & 3;
    #pragma unroll
    for (int jn = 0; jn < 4; jn++) {
        const int colp = col0 + wn*32 + jn*8 + fc*2;
        float b0 = 0.f, b1 = 0.f;
        if (MODE != MODE_RPOS && ga.bias != nullptr) {
            b0 = ga.bias[colp]; b1 = ga.bias[colp + 1];
        }
        #pragma unroll
        for (int im = 0; im < 4; im++) {
            #pragma unroll
            for (int half = 0; half < 2; half++) {
                const int row = row0 + wm*64 + im*16 + fr + half*8;
                float v0 = acc[im][jn][half*2 + 0] + b0;
                float v1 = acc[im][jn][half*2 + 1] + b1;
                if (MODE == MODE_PROJ) {
                    long o = (long)((row >> 10)*NN + (colp >> 6))*(LL*HH)
                           + (long)(row & 1023)*HH + (colp & 63);
                    *reinterpret_cast<float2*>(ga.C + o) = make_float2(tf32r(v0), tf32r(v1));
                } else if (MODE == MODE_RPOS) {
                    long o = (long)(colp >> 6)*(RR*HH) + (long)row*HH + (colp & 63);
                    *reinterpret_cast<float2*>(ga.C + o) = make_float2(tf32r(v0), tf32r(v1));
                } else {
                    long o = (long)row*1024 + colp;
                    float2 rr = *reinterpret_cast<const float2*>(ga.resid + o);
                    *reinterpret_cast<float2*>(ga.C + o) = make_float2(v0 + rr.x, v1 + rr.y);
                }
            }
        }
    }
}

// ---------------- fused attention: tf32 mma + log2-domain online softmax ----
// block 256 (8 warps: 4 warp-rows x 2 warp-cols), grid (16 l-tiles, 64 bn)
// smem (floats):
//   QW[64][68] l-major (rounded, +rwb)        4352
//   KT[64][65] h-major                        4160
//   RB[64][132] h-major band / Vs[64][68]     8448 (union)
//   G2s[128][66] u-major / Ps[64][68]         8448 (union)
//   deltas 64, maskv 64, rmaxs 128, rsums 128  384
#define ATT_FLOATS (4352 + 4160 + 8448 + 8448 + 384)
#define SC_LOG2 0.18033688011112042f   // 0.125 * log2(e)
#define MASK_LOG2 -1442695.04f         // -1e6 * log2(e)

__global__ __launch_bounds__(256, 2)
void attn_mma(const int* __restrict__ padding,
              const float* __restrict__ rwb,
              const float* __restrict__ rrb)
{
    extern __shared__ float sm[];
    float* QW     = sm;                       // stride 68
    float* KT     = QW + 4352;                // stride 65
    float* RB     = KT + 4160;                // stride 132
    float* Vs     = RB;                       // stride 68 (union)
    float* G2s    = RB + 8448;                // stride 66
    float* Ps     = G2s;                      // stride 68 (union)
    float* deltas = G2s + 8448;
    float* maskv  = deltas + 64;
    float* rmaxs  = maskv + 64;               // [2][64]
    float* rsums  = rmaxs + 128;              // [2][64]

    const int tid  = threadIdx.x;
    const int lane = tid & 31;
    const int w    = tid >> 5;
    const int wr   = w >> 1;                  // 0..3
    const int wc   = w & 1;                   // 0..1
    const int fr   = lane >> 2;               // 0..7
    const int fc   = lane & 3;                // 0..3
    const int bn   = blockIdx.y;
    const int l0   = blockIdx.x * 64;
    const int b    = bn >> 4;
    const int n    = bn & 15;

    const float* qh = g_qh + (long)bn * (LL*HH);
    const float* kh = g_kh + (long)bn * (LL*HH);
    const float* vh = g_vh + (long)bn * (LL*HH);
    const float* rp = g_r  + (long)n  * (RR*HH);
    float*       op = g_o  + (long)bn * (LL*HH);

    if (tid < 64) deltas[tid] = rrb[n*64 + tid] - rwb[n*64 + tid];

    // QW: l-major, + r_w_bias, rounded
    #pragma unroll
    for (int i = 0; i < 4; i++) {
        const int idx = tid + i*256;
        const int l = idx >> 4, hc = (idx & 15)*4;
        float4 v = *reinterpret_cast<const float4*>(qh + (long)(l0 + l)*64 + hc);
        QW[l*68 + hc + 0] = tf32r(v.x + rwb[n*64 + hc + 0]);
        QW[l*68 + hc + 1] = tf32r(v.y + rwb[n*64 + hc + 1]);
        QW[l*68 + hc + 2] = tf32r(v.z + rwb[n*64 + hc + 2]);
        QW[l*68 + hc + 3] = tf32r(v.w + rwb[n*64 + hc + 3]);
    }

    float O[4][4];
    float mi[2], li[2];
    #pragma unroll
    for (int jn = 0; jn < 4; jn++)
        #pragma unroll
        for (int q = 0; q < 4; q++) O[jn][q] = 0.f;
    mi[0] = mi[1] = -1e30f;
    li[0] = li[1] = 0.f;

    const int rA = (wr*16 + fr)*68;           // QW/Ps row base (row fr)
    const int rA8 = rA + 8*68;                // row fr+8

    for (int m0 = 0; m0 < LL; m0 += 64) {
        __syncthreads();   // prior tile's G1/PV done before overwriting KT/RB

        // ---- loads: KT (h-major), RB band (h-major), maskv
        #pragma unroll
        for (int i = 0; i < 4; i++) {
            const int idx = tid + i*256;
            const int m = idx >> 4, hc = (idx & 15)*4;
            float4 v = *reinterpret_cast<const float4*>(kh + (long)(m0 + m)*64 + hc);
            KT[(hc+0)*65 + m] = v.x;
            KT[(hc+1)*65 + m] = v.y;
            KT[(hc+2)*65 + m] = v.z;
            KT[(hc+3)*65 + m] = v.w;
        }
        const int jmin = LL + m0 - l0 - 63;
        #pragma unroll
        for (int i = 0; i < 8; i++) {
            const int idx = tid + i*256;
            const int u = idx & 127, hc = (idx >> 7)*4;
            float4 v = make_float4(0.f,0.f,0.f,0.f);
            if (u < 127)
                v = *reinterpret_cast<const float4*>(rp + (long)(jmin + u)*64 + hc);
            RB[(hc+0)*132 + u] = v.x;
            RB[(hc+1)*132 + u] = v.y;
            RB[(hc+2)*132 + u] = v.z;
            RB[(hc+3)*132 + u] = v.w;
        }
        if (tid < 64)
            maskv[tid] = (padding[b*LL + m0 + tid] != 0) ? MASK_LOG2 : 0.0f;
        __syncthreads();

        // ---- G2 mma: 64x128 band, two 64-col halves to limit registers
        #pragma unroll
        for (int jh = 0; jh < 2; jh++) {
            float g2[4][4];
            #pragma unroll
            for (int jn = 0; jn < 4; jn++)
                #pragma unroll
                for (int q = 0; q < 4; q++) g2[jn][q] = 0.f;
            #pragma unroll
            for (int k8 = 0; k8 < 64; k8 += 8) {
                uint32_t a[4];
                a[0] = tf32u(QW[rA  + k8 + fc]     + deltas[k8 + fc]);
                a[1] = tf32u(QW[rA8 + k8 + fc]     + deltas[k8 + fc]);
                a[2] = tf32u(QW[rA  + k8 + fc + 4] + deltas[k8 + fc + 4]);
                a[3] = tf32u(QW[rA8 + k8 + fc + 4] + deltas[k8 + fc + 4]);
                #pragma unroll
                for (int jn = 0; jn < 4; jn++) {
                    const int ncol = wc*64 + jh*32 + jn*8 + fr;
                    uint32_t bfr[2];
                    bfr[0] = __float_as_uint(RB[(k8 + fc)*132 + ncol]);
                    bfr[1] = __float_as_uint(RB[(k8 + fc + 4)*132 + ncol]);
                    mma_tf32(g2[jn], a, bfr);
                }
            }
            // spill to G2s[u][l]
            #pragma unroll
            for (int jn = 0; jn < 4; jn++) {
                const int ub = wc*64 + jh*32 + jn*8 + fc*2;
                const int lb = wr*16 + fr;
                G2s[(ub+0)*66 + lb]     = g2[jn][0];
                G2s[(ub+1)*66 + lb]     = g2[jn][1];
                G2s[(ub+0)*66 + lb + 8] = g2[jn][2];
                G2s[(ub+1)*66 + lb + 8] = g2[jn][3];
            }
        }
        __syncthreads();   // G2s complete; RB free for Vs

        // ---- Vs load (over RB union)
        #pragma unroll
        for (int i = 0; i < 4; i++) {
            const int idx = tid + i*256;
            const int m = idx >> 4, hc = (idx & 15)*4;
            float4 v = *reinterpret_cast<const float4*>(vh + (long)(m0 + m)*64 + hc);
            *reinterpret_cast<float4*>(&Vs[m*68 + hc]) = v;
        }

        // ---- G1 mma: 64x64 scores
        float s1[4][4];
        #pragma unroll
        for (int jn = 0; jn < 4; jn++)
            #pragma unroll
            for (int q = 0; q < 4; q++) s1[jn][q] = 0.f;
        #pragma unroll
        for (int k8 = 0; k8 < 64; k8 += 8) {
            uint32_t a[4];
            a[0] = __float_as_uint(QW[rA  + k8 + fc]);
            a[1] = __float_as_uint(QW[rA8 + k8 + fc]);
            a[2] = __float_as_uint(QW[rA  + k8 + fc + 4]);
            a[3] = __float_as_uint(QW[rA8 + k8 + fc + 4]);
            #pragma unroll
            for (int jn = 0; jn < 4; jn++) {
                const int ncol = wc*32 + jn*8 + fr;
                uint32_t bfr[2];
                bfr[0] = __float_as_uint(KT[(k8 + fc)*65 + ncol]);
                bfr[1] = __float_as_uint(KT[(k8 + fc + 4)*65 + ncol]);
                mma_tf32(s1[jn], a, bfr);
            }
        }

        // ---- assemble S (log2 domain) + per-warp row max
        float sv[4][4];
        float rmx[2] = {-1e30f, -1e30f};
        #pragma unroll
        for (int jn = 0; jn < 4; jn++) {
            #pragma unroll
            for (int q = 0; q < 4; q++) {
                const int ll = wr*16 + fr + (q >> 1)*8;
                const int mc = wc*32 + jn*8 + fc*2 + (q & 1);
                const int u  = mc - ll + 63;
                float x = (s1[jn][q] + G2s[u*66 + ll]) * SC_LOG2 + maskv[mc];
                sv[jn][q] = x;
                rmx[q >> 1] = fmaxf(rmx[q >> 1], x);
            }
        }
        #pragma unroll
        for (int r = 0; r < 2; r++) {
            rmx[r] = fmaxf(rmx[r], __shfl_xor_sync(0xffffffffu, rmx[r], 1));
            rmx[r] = fmaxf(rmx[r], __shfl_xor_sync(0xffffffffu, rmx[r], 2));
        }
        if (fc == 0) {
            rmaxs[wc*64 + wr*16 + fr]     = rmx[0];
            rmaxs[wc*64 + wr*16 + fr + 8] = rmx[1];
        }
        __syncthreads();   // row maxes ready; all G2s gathers done

        // ---- softmax: exp2, P store (tf32-rounded), partial sums
        float nm[2], al[2], psum[2];
        #pragma unroll
        for (int r = 0; r < 2; r++) {
            const int row = wr*16 + fr + r*8;
            const float tm = fmaxf(rmaxs[row], rmaxs[64 + row]);
            nm[r] = fmaxf(mi[r], tm);
            al[r] = ex2f(mi[r] - nm[r]);
            mi[r] = nm[r];
            psum[r] = 0.f;
        }
        #pragma unroll
        for (int jn = 0; jn < 4; jn++) {
            #pragma unroll
            for (int r = 0; r < 2; r++) {
                float p0 = ex2f(sv[jn][r*2 + 0] - nm[r]);
                float p1 = ex2f(sv[jn][r*2 + 1] - nm[r]);
                psum[r] += p0 + p1;
                const int ll = wr*16 + fr + r*8;
                const int mc = wc*32 + jn*8 + fc*2;
                *reinterpret_cast<float2*>(&Ps[ll*68 + mc]) =
                    make_float2(tf32r(p0), tf32r(p1));
            }
        }
        #pragma unroll
        for (int r = 0; r < 2; r++) {
            psum[r] += __shfl_xor_sync(0xffffffffu, psum[r], 1);
            psum[r] += __shfl_xor_sync(0xffffffffu, psum[r], 2);
        }
        if (fc == 0) {
            rsums[wc*64 + wr*16 + fr]     = psum[0];
            rsums[wc*64 + wr*16 + fr + 8] = psum[1];
        }
        __syncthreads();   // Ps + Vs + sums ready

        // ---- li update, O rescale, PV mma
        #pragma unroll
        for (int r = 0; r < 2; r++) {
            const int row = wr*16 + fr + r*8;
            li[r] = li[r]*al[r] + (rsums[row] + rsums[64 + row]);
        }
        #pragma unroll
        for (int jn = 0; jn < 4; jn++) {
            O[jn][0] *= al[0]; O[jn][1] *= al[0];
            O[jn][2] *= al[1]; O[jn][3] *= al[1];
        }
        #pragma unroll
        for (int k8 = 0; k8 < 64; k8 += 8) {
            uint32_t a[4];
            a[0] = __float_as_uint(Ps[rA  + k8 + fc]);
            a[1] = __float_as_uint(Ps[rA8 + k8 + fc]);
            a[2] = __float_as_uint(Ps[rA  + k8 + fc + 4]);
            a[3] = __float_as_uint(Ps[rA8 + k8 + fc + 4]);
            #pragma unroll
            for (int jn = 0; jn < 4; jn++) {
                const int ncol = wc*32 + jn*8 + fr;
                uint32_t bfr[2];
                bfr[0] = __float_as_uint(Vs[(k8 + fc)*68 + ncol]);
                bfr[1] = __float_as_uint(Vs[(k8 + fc + 4)*68 + ncol]);
                mma_tf32(O[jn], a, bfr);
            }
        }
    }

    // ---- final: normalize, round (feeds POST GEMM), write
    const float inv0 = 1.0f / li[0];
    const float inv1 = 1.0f / li[1];
    #pragma unroll
    for (int jn = 0; jn < 4; jn++) {
        const int col = wc*32 + jn*8 + fc*2;
        const int lr0 = l0 + wr*16 + fr;
        *reinterpret_cast<float2*>(op + (long)lr0*64 + col) =
            make_float2(tf32r(O[jn][0]*inv0), tf32r(O[jn][1]*inv0));
        *reinterpret_cast<float2*>(op + (long)(lr0 + 8)*64 + col) =
            make_float2(tf32r(O[jn][2]*inv1), tf32r(O[jn][3]*inv1));
    }
}

// ---------------- layernorm over D per (b,l) row -----------------------------
__global__ __launch_bounds__(256)
void ln_kernel(const float* __restrict__ lng, const float* __restrict__ lnb,
               float* __restrict__ out)
{
    __shared__ float red[256];
    const int row = blockIdx.x;
    const int tid = threadIdx.x;
    const float* x = g_x + (long)row * DD;

    float v[4]; float s = 0.f;
    #pragma unroll
    for (int i = 0; i < 4; i++) { v[i] = x[tid + i*256]; s += v[i]; }
    red[tid] = s; __syncthreads();
    #pragma unroll
    for (int off = 128; off > 0; off >>= 1) {
        if (tid < off) red[tid] += red[tid + off];
        __syncthreads();
    }
    const float mu = red[0] * (1.f / DD);
    __syncthreads();

    float vs = 0.f;
    #pragma unroll
    for (int i = 0; i < 4; i++) { const float d = v[i] - mu; vs += d*d; }
    red[tid] = vs; __syncthreads();
    #pragma unroll
    for (int off = 128; off > 0; off >>= 1) {
        if (tid < off) red[tid] += red[tid + off];
        __syncthreads();
    }
    const float inv = rsqrtf(red[0] * (1.f / DD) + 1e-5f);

    #pragma unroll
    for (int i = 0; i < 4; i++) {
        const int d0 = tid + i*256;
        out[(long)row*DD + d0] = (v[i] - mu) * inv * lng[d0] + lnb[d0];
    }
}

// ---------------- launcher ---------------------------------------------------
extern "C" void kernel_launch(void* const* d_in, const int* in_sizes, int n_in,
                              void* d_out, int out_size)
{
    const float* q   = (const float*)d_in[0];
    const float* k   = (const float*)d_in[1];
    const float* v   = (const float*)d_in[2];
    const float* pe  = (const float*)d_in[3];
    const int*   pad = (const int*)d_in[4];
    const float* q_w = (const float*)d_in[5];
    const float* k_w = (const float*)d_in[6];
    const float* k_b = (const float*)d_in[7];
    const float* v_w = (const float*)d_in[8];
    const float* v_b = (const float*)d_in[9];
    const float* rwb = (const float*)d_in[10];
    const float* rrb = (const float*)d_in[11];
    const float* rk  = (const float*)d_in[12];
    const float* pw  = (const float*)d_in[13];
    const float* pb  = (const float*)d_in[14];
    const float* lng = (const float*)d_in[15];
    const float* lnb = (const float*)d_in[16];

    void *p_qh, *p_kh, *p_vh, *p_r, *p_o, *p_x;
    void *p_tq, *p_tk, *p_tv, *p_tpe, *p_tqw, *p_tkw, *p_tvw, *p_trk, *p_tpw;
    cudaGetSymbolAddress(&p_qh, g_qh);
    cudaGetSymbolAddress(&p_kh, g_kh);
    cudaGetSymbolAddress(&p_vh, g_vh);
    cudaGetSymbolAddress(&p_r,  g_r);
    cudaGetSymbolAddress(&p_o,  g_o);
    cudaGetSymbolAddress(&p_x,  g_x);
    cudaGetSymbolAddress(&p_tq,  g_tq);
    cudaGetSymbolAddress(&p_tk,  g_tk);
    cudaGetSymbolAddress(&p_tv,  g_tv);
    cudaGetSymbolAddress(&p_tpe, g_tpe);
    cudaGetSymbolAddress(&p_tqw, g_tqw);
    cudaGetSymbolAddress(&p_tkw, g_tkw);
    cudaGetSymbolAddress(&p_tvw, g_tvw);
    cudaGetSymbolAddress(&p_trk, g_trk);
    cudaGetSymbolAddress(&p_tpw, g_tpw);

    const dim3 blk(256);

    // ---- pass 1: tf32-round all GEMM operands
    R9 r;
    r.in[0]=q;   r.out[0]=(float*)p_tq;  r.n[0]=BB*LL*DD;
    r.in[1]=k;   r.out[1]=(float*)p_tk;  r.n[1]=BB*LL*DD;
    r.in[2]=v;   r.out[2]=(float*)p_tv;  r.n[2]=BB*LL*DD;
    r.in[3]=pe;  r.out[3]=(float*)p_tpe; r.n[3]=RR*DD;
    r.in[4]=q_w; r.out[4]=(float*)p_tqw; r.n[4]=DD*NN*HH;
    r.in[5]=k_w; r.out[5]=(float*)p_tkw; r.n[5]=DD*NN*HH;
    r.in[6]=v_w; r.out[6]=(float*)p_tvw; r.n[6]=DD*NN*HH;
    r.in[7]=rk;  r.out[7]=(float*)p_trk; r.n[7]=NN*DD*HH;
    r.in[8]=pw;  r.out[8]=(float*)p_tpw; r.n[8]=NN*HH*DD;
    roundk<<<dim3(1024, 9), blk>>>(r);

    // ---- pass 2: projections + rpos (outputs tf32-rounded for attention)
    cudaFuncSetAttribute(gemm_tf32<MODE_PROJ>, cudaFuncAttributeMaxDynamicSharedMemorySize, GEMM_SMEM);
    cudaFuncSetAttribute(gemm_tf32<MODE_RPOS>, cudaFuncAttributeMaxDynamicSharedMemorySize, GEMM_SMEM);
    cudaFuncSetAttribute(gemm_tf32<MODE_POST>, cudaFuncAttributeMaxDynamicSharedMemorySize, GEMM_SMEM);

    GemmArgs gq = { (const float*)p_tq, (const float*)p_tqw, nullptr, nullptr, (float*)p_qh };
    GemmArgs gk = { (const float*)p_tk, (const float*)p_tkw, k_b,     nullptr, (float*)p_kh };
    GemmArgs gv = { (const float*)p_tv, (const float*)p_tvw, v_b,     nullptr, (float*)p_vh };
    gemm_tf32<MODE_PROJ><<<dim3(8, 32, 3), blk, GEMM_SMEM>>>(gq, gk, gv);

    GemmArgs gr = { (const float*)p_tpe, (const float*)p_trk, nullptr, nullptr, (float*)p_r };
    gemm_tf32<MODE_RPOS><<<dim3(8, 16, 1), blk, GEMM_SMEM>>>(gr, gr, gr);

    // ---- pass 3: fused attention (tf32 tensor cores + log2 softmax)
    const int att_smem = ATT_FLOATS * 4;
    cudaFuncSetAttribute(attn_mma, cudaFuncAttributeMaxDynamicSharedMemorySize, att_smem);
    attn_mma<<<dim3(LL/64, BB*NN), blk, att_smem>>>(pad, rwb, rrb);

    // ---- pass 4: post GEMM (+bias +residual)
    GemmArgs gp = { (const float*)p_o, (const float*)p_tpw, pb, q, (float*)p_x };
    gemm_tf32<MODE_POST><<<dim3(8, 32, 1), blk, GEMM_SMEM>>>(gp, gp, gp);

    // ---- pass 5: layernorm
    ln_kernel<<<BB*LL, blk>>>(lng, lnb, (float*)d_out);
}

// round 7
// speedup vs baseline: 5.4967x; 1.3412x over previous
#include <cuda_runtime.h>
#include <math.h>
#include <stdint.h>

#define BB 4
#define LL 1024
#define DD 1024
#define NN 16
#define HH 64
#define RR 2048

// ---------------- scratch (static device globals: no allocations allowed) ---
__device__ float g_qh[BB*NN*LL*HH];   // [b][n][l][h] (tf32-rounded)
__device__ float g_kh[BB*NN*LL*HH];   // (tf32-rounded, k_b added)
__device__ float g_vh[BB*NN*LL*HH];   // (tf32-rounded, v_b added)
__device__ float g_r [NN*RR*HH];      // [n][j][h] (tf32-rounded)
__device__ float g_o [BB*NN*LL*HH];   // attention output (tf32-rounded)
__device__ float g_x [BB*LL*DD];      // pre-layernorm residual sum

// tf32-rounded operand copies
__device__ float g_tq [BB*LL*DD];
__device__ float g_tk [BB*LL*DD];
__device__ float g_tv [BB*LL*DD];
__device__ float g_tpe[RR*DD];
__device__ float g_tqw[DD*NN*HH];
__device__ float g_tkw[DD*NN*HH];
__device__ float g_tvw[DD*NN*HH];
__device__ float g_trk[NN*DD*HH];
__device__ float g_tpw[NN*HH*DD];

// ---------------- helpers ---------------------------------------------------
__device__ __forceinline__ float tf32r(float x) {
    uint32_t u;
    asm("cvt.rna.tf32.f32 %0, %1;" : "=r"(u) : "f"(x));
    return __uint_as_float(u);
}
__device__ __forceinline__ uint32_t tf32u(float x) {
    uint32_t u;
    asm("cvt.rna.tf32.f32 %0, %1;" : "=r"(u) : "f"(x));
    return u;
}
__device__ __forceinline__ float ex2f(float x) {
    float y;
    asm("ex2.approx.ftz.f32 %0, %1;" : "=f"(y) : "f"(x));
    return y;
}

__device__ __forceinline__ void mma_tf32(float* d, const uint32_t* a, const uint32_t* b) {
    asm volatile(
        "mma.sync.aligned.m16n8k8.row.col.f32.tf32.tf32.f32 "
        "{%0,%1,%2,%3}, {%4,%5,%6,%7}, {%8,%9}, {%0,%1,%2,%3};\n"
        : "+f"(d[0]), "+f"(d[1]), "+f"(d[2]), "+f"(d[3])
        : "r"(a[0]), "r"(a[1]), "r"(a[2]), "r"(a[3]), "r"(b[0]), "r"(b[1]));
}

// ---------------- fused tf32 rounding pass (all GEMM operands) --------------
struct R9 {
    const float* in[9];
    float*       out[9];
    int          n[9];
};

__global__ __launch_bounds__(256)
void roundk(R9 r)
{
    const int seg = blockIdx.y;
    const float* in  = r.in[seg];
    float*       out = r.out[seg];
    const int n = r.n[seg];
    for (int i = (blockIdx.x*256 + threadIdx.x)*4; i < n; i += gridDim.x*256*4) {
        float4 v = *reinterpret_cast<const float4*>(in + i);
        v.x = tf32r(v.x); v.y = tf32r(v.y); v.z = tf32r(v.z); v.w = tf32r(v.w);
        *reinterpret_cast<float4*>(out + i) = v;
    }
}

// ---------------- tf32 tensor-core GEMM (128x128 tile, K=1024) --------------
enum { MODE_PROJ = 0, MODE_RPOS = 1, MODE_POST = 2 };

struct GemmArgs {
    const float* A;
    const float* W;
    const float* bias;
    const float* resid;
    float*       C;
};

#define AS_STRIDE 36           // 32 + 4 pad (floats)
#define BS_STRIDE 136          // 128 + 8 pad (floats)
#define AS_FLOATS (128*AS_STRIDE)   // per stage
#define BS_FLOATS (32*BS_STRIDE)
#define GEMM_SMEM ((2*AS_FLOATS + 2*BS_FLOATS)*4)   // 71680 bytes

template<int MODE>
__device__ __forceinline__ void stage_copy(
    const float* __restrict__ A, const float* __restrict__ W,
    uint32_t asB, uint32_t bsB, int row0, int col0, int k0, int tid)
{
    #pragma unroll
    for (int i = 0; i < 4; i++) {
        const int c = tid + i*256;
        const int arow = c >> 3, akc = (c & 7) * 4;
        const float* srcA;
        if (MODE == MODE_POST) {
            const int row = row0 + arow, k = k0 + akc;
            srcA = A + (long)(row >> 10)*(NN*LL*HH) + (long)(k >> 6)*(LL*HH)
                     + (long)(row & 1023)*HH + (k & 63);
        } else {
            srcA = A + (long)(row0 + arow)*1024 + k0 + akc;
        }
        asm volatile("cp.async.cg.shared.global [%0], [%1], 16;\n"
                     :: "r"(asB + (uint32_t)((arow*AS_STRIDE + akc)*4)), "l"(srcA));
        const int bk = c >> 5, bnc = (c & 31) * 4;
        const float* srcB;
        if (MODE == MODE_RPOS) {
            const int col = col0 + bnc;
            srcB = W + (long)(col >> 6)*(DD*HH) + (long)(k0 + bk)*HH + (col & 63);
        } else {
            srcB = W + (long)(k0 + bk)*1024 + col0 + bnc;
        }
        asm volatile("cp.async.cg.shared.global [%0], [%1], 16;\n"
                     :: "r"(bsB + (uint32_t)((bk*BS_STRIDE + bnc)*4)), "l"(srcB));
    }
    asm volatile("cp.async.commit_group;\n");
}

template<int MODE>
__global__ __launch_bounds__(256, 2)
void gemm_tf32(GemmArgs g0, GemmArgs g1, GemmArgs g2)
{
    const GemmArgs ga = (blockIdx.z == 0) ? g0 : (blockIdx.z == 1) ? g1 : g2;
    extern __shared__ float smem[];
    float* As = smem;
    float* Bs = smem + 2*AS_FLOATS;

    const int tid  = threadIdx.x;
    const int lane = tid & 31;
    const int w    = tid >> 5;
    const int wm   = w & 1;
    const int wn   = w >> 1;
    const int row0 = blockIdx.y * 128;
    const int col0 = blockIdx.x * 128;

    const uint32_t asB = (uint32_t)__cvta_generic_to_shared(As);
    const uint32_t bsB = (uint32_t)__cvta_generic_to_shared(Bs);

    float acc[4][4][4];
    #pragma unroll
    for (int i = 0; i < 4; i++)
        #pragma unroll
        for (int j = 0; j < 4; j++)
            #pragma unroll
            for (int q = 0; q < 4; q++) acc[i][j][q] = 0.f;

    stage_copy<MODE>(ga.A, ga.W, asB, bsB, row0, col0, 0, tid);

    const int NIT = 1024/32;
    for (int it = 0; it < NIT; it++) {
        const int s = it & 1;
        if (it + 1 < NIT) {
            stage_copy<MODE>(ga.A, ga.W,
                             asB + (uint32_t)((s^1)*AS_FLOATS*4),
                             bsB + (uint32_t)((s^1)*BS_FLOATS*4),
                             row0, col0, (it+1)*32, tid);
            asm volatile("cp.async.wait_group 1;\n");
        } else {
            asm volatile("cp.async.wait_group 0;\n");
        }
        __syncthreads();

        const float* as = As + s*AS_FLOATS;
        const float* bs = Bs + s*BS_FLOATS;
        #pragma unroll
        for (int k8 = 0; k8 < 32; k8 += 8) {
            uint32_t af[4][4], bf[4][2];
            const int fr = lane >> 2;
            const int fc = lane & 3;
            #pragma unroll
            for (int im = 0; im < 4; im++) {
                const int r = wm*64 + im*16 + fr;
                const int c = k8 + fc;
                af[im][0] = __float_as_uint(as[r*AS_STRIDE + c]);
                af[im][1] = __float_as_uint(as[(r+8)*AS_STRIDE + c]);
                af[im][2] = __float_as_uint(as[r*AS_STRIDE + c + 4]);
                af[im][3] = __float_as_uint(as[(r+8)*AS_STRIDE + c + 4]);
            }
            #pragma unroll
            for (int jn = 0; jn < 4; jn++) {
                const int nn = wn*32 + jn*8 + fr;
                const int kk = k8 + fc;
                bf[jn][0] = __float_as_uint(bs[kk*BS_STRIDE + nn]);
                bf[jn][1] = __float_as_uint(bs[(kk+4)*BS_STRIDE + nn]);
            }
            #pragma unroll
            for (int im = 0; im < 4; im++)
                #pragma unroll
                for (int jn = 0; jn < 4; jn++)
                    mma_tf32(acc[im][jn], af[im], bf[jn]);
        }
        __syncthreads();
    }

    const int fr = lane >> 2;
    const int fc = lane & 3;
    #pragma unroll
    for (int jn = 0; jn < 4; jn++) {
        const int colp = col0 + wn*32 + jn*8 + fc*2;
        float b0 = 0.f, b1 = 0.f;
        if (MODE != MODE_RPOS && ga.bias != nullptr) {
            b0 = ga.bias[colp]; b1 = ga.bias[colp + 1];
        }
        #pragma unroll
        for (int im = 0; im < 4; im++) {
            #pragma unroll
            for (int half = 0; half < 2; half++) {
                const int row = row0 + wm*64 + im*16 + fr + half*8;
                float v0 = acc[im][jn][half*2 + 0] + b0;
                float v1 = acc[im][jn][half*2 + 1] + b1;
                if (MODE == MODE_PROJ) {
                    long o = (long)((row >> 10)*NN + (colp >> 6))*(LL*HH)
                           + (long)(row & 1023)*HH + (colp & 63);
                    *reinterpret_cast<float2*>(ga.C + o) = make_float2(tf32r(v0), tf32r(v1));
                } else if (MODE == MODE_RPOS) {
                    long o = (long)(colp >> 6)*(RR*HH) + (long)row*HH + (colp & 63);
                    *reinterpret_cast<float2*>(ga.C + o) = make_float2(tf32r(v0), tf32r(v1));
                } else {
                    long o = (long)row*1024 + colp;
                    float2 rr = *reinterpret_cast<const float2*>(ga.resid + o);
                    *reinterpret_cast<float2*>(ga.C + o) = make_float2(v0 + rr.x, v1 + rr.y);
                }
            }
        }
    }
}

// ---------------- fused attention: tf32 mma + log2-domain online softmax ----
// block 256 (8 warps: 4 warp-rows x 2 warp-cols), grid (16 l-tiles, 64 bn)
// ALL fragment-feeding smem arrays use stride 68 (== 4 mod 32) so both A-side
// ([row]*68 + k) and B-side ([ncol]*68 + k) loads hit bank 4*fr+fc: conflict-free.
// smem (floats):
//   QW [64][68]  l-major (rounded, +rwb)       4352
//   KT [64][68]  m-major (natural gmem layout) 4352
//   RB [128][68] u-major band / Vs[64][68]     8704 (union)
//   G2s[128][66] u-major / Ps[64][68]          8448 (union)
//   deltas 64, maskv 64, rmaxs 128, rsums 128   384
#define ATT_FLOATS (4352 + 4352 + 8704 + 8448 + 384)
#define SC_LOG2 0.18033688011112042f   // 0.125 * log2(e)
#define MASK_LOG2 -1442695.04f         // -1e6 * log2(e)

__global__ __launch_bounds__(256, 2)
void attn_mma(const int* __restrict__ padding,
              const float* __restrict__ rwb,
              const float* __restrict__ rrb)
{
    extern __shared__ float sm[];
    float* QW     = sm;                       // stride 68
    float* KT     = QW + 4352;                // stride 68, m-major
    float* RB     = KT + 4352;                // stride 68, u-major
    float* Vs     = RB;                       // stride 68 (union)
    float* G2s    = RB + 8704;                // stride 66
    float* Ps     = G2s;                      // stride 68 (union)
    float* deltas = G2s + 8448;
    float* maskv  = deltas + 64;
    float* rmaxs  = maskv + 64;               // [2][64]
    float* rsums  = rmaxs + 128;              // [2][64]

    const int tid  = threadIdx.x;
    const int lane = tid & 31;
    const int w    = tid >> 5;
    const int wr   = w >> 1;                  // 0..3
    const int wc   = w & 1;                   // 0..1
    const int fr   = lane >> 2;               // 0..7
    const int fc   = lane & 3;                // 0..3
    const int bn   = blockIdx.y;
    const int l0   = blockIdx.x * 64;
    const int b    = bn >> 4;
    const int n    = bn & 15;

    const float* qh = g_qh + (long)bn * (LL*HH);
    const float* kh = g_kh + (long)bn * (LL*HH);
    const float* vh = g_vh + (long)bn * (LL*HH);
    const float* rp = g_r  + (long)n  * (RR*HH);
    float*       op = g_o  + (long)bn * (LL*HH);

    if (tid < 64) deltas[tid] = rrb[n*64 + tid] - rwb[n*64 + tid];

    // QW: l-major, + r_w_bias, rounded
    #pragma unroll
    for (int i = 0; i < 4; i++) {
        const int idx = tid + i*256;
        const int l = idx >> 4, hc = (idx & 15)*4;
        float4 v = *reinterpret_cast<const float4*>(qh + (long)(l0 + l)*64 + hc);
        QW[l*68 + hc + 0] = tf32r(v.x + rwb[n*64 + hc + 0]);
        QW[l*68 + hc + 1] = tf32r(v.y + rwb[n*64 + hc + 1]);
        QW[l*68 + hc + 2] = tf32r(v.z + rwb[n*64 + hc + 2]);
        QW[l*68 + hc + 3] = tf32r(v.w + rwb[n*64 + hc + 3]);
    }

    float O[4][4];
    float mi[2], li[2];
    #pragma unroll
    for (int jn = 0; jn < 4; jn++)
        #pragma unroll
        for (int q = 0; q < 4; q++) O[jn][q] = 0.f;
    mi[0] = mi[1] = -1e30f;
    li[0] = li[1] = 0.f;

    const int rA = (wr*16 + fr)*68;           // QW/Ps row base (row fr)
    const int rA8 = rA + 8*68;                // row fr+8

    for (int m0 = 0; m0 < LL; m0 += 64) {
        __syncthreads();   // prior tile's G1/PV done before overwriting KT/RB

        // ---- loads: KT (m-major straight copy), RB band (u-major copy), maskv
        #pragma unroll
        for (int i = 0; i < 4; i++) {
            const int idx = tid + i*256;
            const int m = idx >> 4, hc = (idx & 15)*4;
            float4 v = *reinterpret_cast<const float4*>(kh + (long)(m0 + m)*64 + hc);
            *reinterpret_cast<float4*>(&KT[m*68 + hc]) = v;
        }
        const int jmin = LL + m0 - l0 - 63;
        #pragma unroll
        for (int i = 0; i < 8; i++) {
            const int idx = tid + i*256;
            const int u = idx >> 4, hc = (idx & 15)*4;
            float4 v = make_float4(0.f,0.f,0.f,0.f);
            if (u < 127)
                v = *reinterpret_cast<const float4*>(rp + (long)(jmin + u)*64 + hc);
            *reinterpret_cast<float4*>(&RB[u*68 + hc]) = v;
        }
        if (tid < 64)
            maskv[tid] = (padding[b*LL + m0 + tid] != 0) ? MASK_LOG2 : 0.0f;
        __syncthreads();

        // ---- G2 mma: 64x128 band, two 64-col halves to limit registers
        #pragma unroll
        for (int jh = 0; jh < 2; jh++) {
            float g2[4][4];
            #pragma unroll
            for (int jn = 0; jn < 4; jn++)
                #pragma unroll
                for (int q = 0; q < 4; q++) g2[jn][q] = 0.f;
            #pragma unroll
            for (int k8 = 0; k8 < 64; k8 += 8) {
                uint32_t a[4];
                a[0] = tf32u(QW[rA  + k8 + fc]     + deltas[k8 + fc]);
                a[1] = tf32u(QW[rA8 + k8 + fc]     + deltas[k8 + fc]);
                a[2] = tf32u(QW[rA  + k8 + fc + 4] + deltas[k8 + fc + 4]);
                a[3] = tf32u(QW[rA8 + k8 + fc + 4] + deltas[k8 + fc + 4]);
                #pragma unroll
                for (int jn = 0; jn < 4; jn++) {
                    const int ncol = wc*64 + jh*32 + jn*8 + fr;
                    uint32_t bfr[2];
                    bfr[0] = __float_as_uint(RB[ncol*68 + k8 + fc]);
                    bfr[1] = __float_as_uint(RB[ncol*68 + k8 + fc + 4]);
                    mma_tf32(g2[jn], a, bfr);
                }
            }
            // spill to G2s[u][l]
            #pragma unroll
            for (int jn = 0; jn < 4; jn++) {
                const int ub = wc*64 + jh*32 + jn*8 + fc*2;
                const int lb = wr*16 + fr;
                G2s[(ub+0)*66 + lb]     = g2[jn][0];
                G2s[(ub+1)*66 + lb]     = g2[jn][1];
                G2s[(ub+0)*66 + lb + 8] = g2[jn][2];
                G2s[(ub+1)*66 + lb + 8] = g2[jn][3];
            }
        }
        __syncthreads();   // G2s complete; RB free for Vs

        // ---- Vs load (over RB union)
        #pragma unroll
        for (int i = 0; i < 4; i++) {
            const int idx = tid + i*256;
            const int m = idx >> 4, hc = (idx & 15)*4;
            float4 v = *reinterpret_cast<const float4*>(vh + (long)(m0 + m)*64 + hc);
            *reinterpret_cast<float4*>(&Vs[m*68 + hc]) = v;
        }

        // ---- G1 mma: 64x64 scores
        float s1[4][4];
        #pragma unroll
        for (int jn = 0; jn < 4; jn++)
            #pragma unroll
            for (int q = 0; q < 4; q++) s1[jn][q] = 0.f;
        #pragma unroll
        for (int k8 = 0; k8 < 64; k8 += 8) {
            uint32_t a[4];
            a[0] = __float_as_uint(QW[rA  + k8 + fc]);
            a[1] = __float_as_uint(QW[rA8 + k8 + fc]);
            a[2] = __float_as_uint(QW[rA  + k8 + fc + 4]);
            a[3] = __float_as_uint(QW[rA8 + k8 + fc + 4]);
            #pragma unroll
            for (int jn = 0; jn < 4; jn++) {
                const int ncol = wc*32 + jn*8 + fr;
                uint32_t bfr[2];
                bfr[0] = __float_as_uint(KT[ncol*68 + k8 + fc]);
                bfr[1] = __float_as_uint(KT[ncol*68 + k8 + fc + 4]);
                mma_tf32(s1[jn], a, bfr);
            }
        }

        // ---- assemble S (log2 domain) + per-warp row max
        float sv[4][4];
        float rmx[2] = {-1e30f, -1e30f};
        #pragma unroll
        for (int jn = 0; jn < 4; jn++) {
            #pragma unroll
            for (int q = 0; q < 4; q++) {
                const int ll = wr*16 + fr + (q >> 1)*8;
                const int mc = wc*32 + jn*8 + fc*2 + (q & 1);
                const int u  = mc - ll + 63;
                float x = (s1[jn][q] + G2s[u*66 + ll]) * SC_LOG2 + maskv[mc];
                sv[jn][q] = x;
                rmx[q >> 1] = fmaxf(rmx[q >> 1], x);
            }
        }
        #pragma unroll
        for (int r = 0; r < 2; r++) {
            rmx[r] = fmaxf(rmx[r], __shfl_xor_sync(0xffffffffu, rmx[r], 1));
            rmx[r] = fmaxf(rmx[r], __shfl_xor_sync(0xffffffffu, rmx[r], 2));
        }
        if (fc == 0) {
            rmaxs[wc*64 + wr*16 + fr]     = rmx[0];
            rmaxs[wc*64 + wr*16 + fr + 8] = rmx[1];
        }
        __syncthreads();   // row maxes ready; all G2s gathers done

        // ---- softmax: exp2, P store (tf32-rounded), partial sums
        float nm[2], al[2], psum[2];
        #pragma unroll
        for (int r = 0; r < 2; r++) {
            const int row = wr*16 + fr + r*8;
            const float tm = fmaxf(rmaxs[row], rmaxs[64 + row]);
            nm[r] = fmaxf(mi[r], tm);
            al[r] = ex2f(mi[r] - nm[r]);
            mi[r] = nm[r];
            psum[r] = 0.f;
        }
        #pragma unroll
        for (int jn = 0; jn < 4; jn++) {
            #pragma unroll
            for (int r = 0; r < 2; r++) {
                float p0 = ex2f(sv[jn][r*2 + 0] - nm[r]);
                float p1 = ex2f(sv[jn][r*2 + 1] - nm[r]);
                psum[r] += p0 + p1;
                const int ll = wr*16 + fr + r*8;
                const int mc = wc*32 + jn*8 + fc*2;
                *reinterpret_cast<float2*>(&Ps[ll*68 + mc]) =
                    make_float2(tf32r(p0), tf32r(p1));
            }
        }
        #pragma unroll
        for (int r = 0; r < 2; r++) {
            psum[r] += __shfl_xor_sync(0xffffffffu, psum[r], 1);
            psum[r] += __shfl_xor_sync(0xffffffffu, psum[r], 2);
        }
        if (fc == 0) {
            rsums[wc*64 + wr*16 + fr]     = psum[0];
            rsums[wc*64 + wr*16 + fr + 8] = psum[1];
        }
        __syncthreads();   // Ps + Vs + sums ready

        // ---- li update, O rescale, PV mma
        #pragma unroll
        for (int r = 0; r < 2; r++) {
            const int row = wr*16 + fr + r*8;
            li[r] = li[r]*al[r] + (rsums[row] + rsums[64 + row]);
        }
        #pragma unroll
        for (int jn = 0; jn < 4; jn++) {
            O[jn][0] *= al[0]; O[jn][1] *= al[0];
            O[jn][2] *= al[1]; O[jn][3] *= al[1];
        }
        #pragma unroll
        for (int k8 = 0; k8 < 64; k8 += 8) {
            uint32_t a[4];
            a[0] = __float_as_uint(Ps[rA  + k8 + fc]);
            a[1] = __float_as_uint(Ps[rA8 + k8 + fc]);
            a[2] = __float_as_uint(Ps[rA  + k8 + fc + 4]);
            a[3] = __float_as_uint(Ps[rA8 + k8 + fc + 4]);
            #pragma unroll
            for (int jn = 0; jn < 4; jn++) {
                const int ncol = wc*32 + jn*8 + fr;
                uint32_t bfr[2];
                bfr[0] = __float_as_uint(Vs[(k8 + fc)*68 + ncol]);
                bfr[1] = __float_as_uint(Vs[(k8 + fc + 4)*68 + ncol]);
                mma_tf32(O[jn], a, bfr);
            }
        }
    }

    // ---- final: normalize, round (feeds POST GEMM), write
    const float inv0 = 1.0f / li[0];
    const float inv1 = 1.0f / li[1];
    #pragma unroll
    for (int jn = 0; jn < 4; jn++) {
        const int col = wc*32 + jn*8 + fc*2;
        const int lr0 = l0 + wr*16 + fr;
        *reinterpret_cast<float2*>(op + (long)lr0*64 + col) =
            make_float2(tf32r(O[jn][0]*inv0), tf32r(O[jn][1]*inv0));
        *reinterpret_cast<float2*>(op + (long)(lr0 + 8)*64 + col) =
            make_float2(tf32r(O[jn][2]*inv1), tf32r(O[jn][3]*inv1));
    }
}

// ---------------- layernorm over D per (b,l) row -----------------------------
__global__ __launch_bounds__(256)
void ln_kernel(const float* __restrict__ lng, const float* __restrict__ lnb,
               float* __restrict__ out)
{
    __shared__ float red[256];
    const int row = blockIdx.x;
    const int tid = threadIdx.x;
    const float* x = g_x + (long)row * DD;

    float v[4]; float s = 0.f;
    #pragma unroll
    for (int i = 0; i < 4; i++) { v[i] = x[tid + i*256]; s += v[i]; }
    red[tid] = s; __syncthreads();
    #pragma unroll
    for (int off = 128; off > 0; off >>= 1) {
        if (tid < off) red[tid] += red[tid + off];
        __syncthreads();
    }
    const float mu = red[0] * (1.f / DD);
    __syncthreads();

    float vs = 0.f;
    #pragma unroll
    for (int i = 0; i < 4; i++) { const float d = v[i] - mu; vs += d*d; }
    red[tid] = vs; __syncthreads();
    #pragma unroll
    for (int off = 128; off > 0; off >>= 1) {
        if (tid < off) red[tid] += red[tid + off];
        __syncthreads();
    }
    const float inv = rsqrtf(red[0] * (1.f / DD) + 1e-5f);

    #pragma unroll
    for (int i = 0; i < 4; i++) {
        const int d0 = tid + i*256;
        out[(long)row*DD + d0] = (v[i] - mu) * inv * lng[d0] + lnb[d0];
    }
}

// ---------------- launcher ---------------------------------------------------
extern "C" void kernel_launch(void* const* d_in, const int* in_sizes, int n_in,
                              void* d_out, int out_size)
{
    const float* q   = (const float*)d_in[0];
    const float* k   = (const float*)d_in[1];
    const float* v   = (const float*)d_in[2];
    const float* pe  = (const float*)d_in[3];
    const int*   pad = (const int*)d_in[4];
    const float* q_w = (const float*)d_in[5];
    const float* k_w = (const float*)d_in[6];
    const float* k_b = (const float*)d_in[7];
    const float* v_w = (const float*)d_in[8];
    const float* v_b = (const float*)d_in[9];
    const float* rwb = (const float*)d_in[10];
    const float* rrb = (const float*)d_in[11];
    const float* rk  = (const float*)d_in[12];
    const float* pw  = (const float*)d_in[13];
    const float* pb  = (const float*)d_in[14];
    const float* lng = (const float*)d_in[15];
    const float* lnb = (const float*)d_in[16];

    void *p_qh, *p_kh, *p_vh, *p_r, *p_o, *p_x;
    void *p_tq, *p_tk, *p_tv, *p_tpe, *p_tqw, *p_tkw, *p_tvw, *p_trk, *p_tpw;
    cudaGetSymbolAddress(&p_qh, g_qh);
    cudaGetSymbolAddress(&p_kh, g_kh);
    cudaGetSymbolAddress(&p_vh, g_vh);
    cudaGetSymbolAddress(&p_r,  g_r);
    cudaGetSymbolAddress(&p_o,  g_o);
    cudaGetSymbolAddress(&p_x,  g_x);
    cudaGetSymbolAddress(&p_tq,  g_tq);
    cudaGetSymbolAddress(&p_tk,  g_tk);
    cudaGetSymbolAddress(&p_tv,  g_tv);
    cudaGetSymbolAddress(&p_tpe, g_tpe);
    cudaGetSymbolAddress(&p_tqw, g_tqw);
    cudaGetSymbolAddress(&p_tkw, g_tkw);
    cudaGetSymbolAddress(&p_tvw, g_tvw);
    cudaGetSymbolAddress(&p_trk, g_trk);
    cudaGetSymbolAddress(&p_tpw, g_tpw);

    const dim3 blk(256);

    // ---- pass 1: tf32-round all GEMM operands
    R9 r;
    r.in[0]=q;   r.out[0]=(float*)p_tq;  r.n[0]=BB*LL*DD;
    r.in[1]=k;   r.out[1]=(float*)p_tk;  r.n[1]=BB*LL*DD;
    r.in[2]=v;   r.out[2]=(float*)p_tv;  r.n[2]=BB*LL*DD;
    r.in[3]=pe;  r.out[3]=(float*)p_tpe; r.n[3]=RR*DD;
    r.in[4]=q_w; r.out[4]=(float*)p_tqw; r.n[4]=DD*NN*HH;
    r.in[5]=k_w; r.out[5]=(float*)p_tkw; r.n[5]=DD*NN*HH;
    r.in[6]=v_w; r.out[6]=(float*)p_tvw; r.n[6]=DD*NN*HH;
    r.in[7]=rk;  r.out[7]=(float*)p_trk; r.n[7]=NN*DD*HH;
    r.in[8]=pw;  r.out[8]=(float*)p_tpw; r.n[8]=NN*HH*DD;
    roundk<<<dim3(1024, 9), blk>>>(r);

    // ---- pass 2: projections + rpos (outputs tf32-rounded for attention)
    cudaFuncSetAttribute(gemm_tf32<MODE_PROJ>, cudaFuncAttributeMaxDynamicSharedMemorySize, GEMM_SMEM);
    cudaFuncSetAttribute(gemm_tf32<MODE_RPOS>, cudaFuncAttributeMaxDynamicSharedMemorySize, GEMM_SMEM);
    cudaFuncSetAttribute(gemm_tf32<MODE_POST>, cudaFuncAttributeMaxDynamicSharedMemorySize, GEMM_SMEM);

    GemmArgs gq = { (const float*)p_tq, (const float*)p_tqw, nullptr, nullptr, (float*)p_qh };
    GemmArgs gk = { (const float*)p_tk, (const float*)p_tkw, k_b,     nullptr, (float*)p_kh };
    GemmArgs gv = { (const float*)p_tv, (const float*)p_tvw, v_b,     nullptr, (float*)p_vh };
    gemm_tf32<MODE_PROJ><<<dim3(8, 32, 3), blk, GEMM_SMEM>>>(gq, gk, gv);

    GemmArgs gr = { (const float*)p_tpe, (const float*)p_trk, nullptr, nullptr, (float*)p_r };
    gemm_tf32<MODE_RPOS><<<dim3(8, 16, 1), blk, GEMM_SMEM>>>(gr, gr, gr);

    // ---- pass 3: fused attention (tf32 tensor cores + log2 softmax)
    const int att_smem = ATT_FLOATS * 4;
    cudaFuncSetAttribute(attn_mma, cudaFuncAttributeMaxDynamicSharedMemorySize, att_smem);
    attn_mma<<<dim3(LL/64, BB*NN), blk, att_smem>>>(pad, rwb, rrb);

    // ---- pass 4: post GEMM (+bias +residual)
    GemmArgs gp = { (const float*)p_o, (const float*)p_tpw, pb, q, (float*)p_x };
    gemm_tf32<MODE_POST><<<dim3(8, 32, 1), blk, GEMM_SMEM>>>(gp, gp, gp);

    // ---- pass 5: layernorm
    ln_kernel<<<BB*LL, blk>>>(lng, lnb, (float*)d_out);
}

// round 9
// speedup vs baseline: 7.3407x; 1.3355x over previous
#include <cuda_runtime.h>
#include <cuda_bf16.h>
#include <math.h>
#include <stdint.h>

#define BB 4
#define LL 1024
#define DD 1024
#define NN 16
#define HH 64
#define RR 2048

// ---------------- scratch (static device globals: no allocations allowed) ---
__device__ float g_qh[BB*NN*LL*HH];   // [b][n][l][h] (tf32-rounded)
__device__ float g_kh[BB*NN*LL*HH];   // (tf32-rounded, k_b added)
__device__ float g_vh[BB*NN*LL*HH];   // (tf32-rounded, v_b added)
__device__ float g_r [NN*RR*HH];      // [n][j][h] (tf32-rounded)
__device__ float g_o [BB*NN*LL*HH];   // attention output (tf32-rounded)
__device__ float g_x [BB*LL*DD];      // pre-layernorm residual sum

// tf32-rounded operand copies
__device__ float g_tq [BB*LL*DD];
__device__ float g_tk [BB*LL*DD];
__device__ float g_tv [BB*LL*DD];
__device__ float g_tpe[RR*DD];
__device__ float g_tqw[DD*NN*HH];
__device__ float g_tkw[DD*NN*HH];
__device__ float g_tvw[DD*NN*HH];
__device__ float g_trk[NN*DD*HH];
__device__ float g_tpw[NN*HH*DD];

// ---------------- helpers ---------------------------------------------------
__device__ __forceinline__ float tf32r(float x) {
    uint32_t u;
    asm("cvt.rna.tf32.f32 %0, %1;" : "=r"(u) : "f"(x));
    return __uint_as_float(u);
}
__device__ __forceinline__ float ex2f(float x) {
    float y;
    asm("ex2.approx.ftz.f32 %0, %1;" : "=f"(y) : "f"(x));
    return y;
}
// pack (lo=a, hi=b) into bf16x2
__device__ __forceinline__ uint32_t bf2(float a, float b) {
    uint32_t r;
    asm("cvt.rn.bf16x2.f32 %0, %1, %2;" : "=r"(r) : "f"(b), "f"(a));
    return r;
}

__device__ __forceinline__ void mma_tf32(float* d, const uint32_t* a, const uint32_t* b) {
    asm volatile(
        "mma.sync.aligned.m16n8k8.row.col.f32.tf32.tf32.f32 "
        "{%0,%1,%2,%3}, {%4,%5,%6,%7}, {%8,%9}, {%0,%1,%2,%3};\n"
        : "+f"(d[0]), "+f"(d[1]), "+f"(d[2]), "+f"(d[3])
        : "r"(a[0]), "r"(a[1]), "r"(a[2]), "r"(a[3]), "r"(b[0]), "r"(b[1]));
}
__device__ __forceinline__ void mma_bf16(float* d, const uint32_t* a, const uint32_t* b) {
    asm volatile(
        "mma.sync.aligned.m16n8k16.row.col.f32.bf16.bf16.f32 "
        "{%0,%1,%2,%3}, {%4,%5,%6,%7}, {%8,%9}, {%0,%1,%2,%3};\n"
        : "+f"(d[0]), "+f"(d[1]), "+f"(d[2]), "+f"(d[3])
        : "r"(a[0]), "r"(a[1]), "r"(a[2]), "r"(a[3]), "r"(b[0]), "r"(b[1]));
}
__device__ __forceinline__ void ldsm_x4(uint32_t& r0, uint32_t& r1, uint32_t& r2, uint32_t& r3, uint32_t addr) {
    asm volatile("ldmatrix.sync.aligned.m8n8.x4.shared.b16 {%0,%1,%2,%3}, [%4];"
                 : "=r"(r0), "=r"(r1), "=r"(r2), "=r"(r3) : "r"(addr));
}
__device__ __forceinline__ void ldsm_x2(uint32_t& r0, uint32_t& r1, uint32_t addr) {
    asm volatile("ldmatrix.sync.aligned.m8n8.x2.shared.b16 {%0,%1}, [%2];"
                 : "=r"(r0), "=r"(r1) : "r"(addr));
}
__device__ __forceinline__ void ldsm_x2t(uint32_t& r0, uint32_t& r1, uint32_t addr) {
    asm volatile("ldmatrix.sync.aligned.m8n8.x2.trans.shared.b16 {%0,%1}, [%2];"
                 : "=r"(r0), "=r"(r1) : "r"(addr));
}

// ---------------- fused tf32 rounding pass (all GEMM operands) --------------
struct R9 {
    const float* in[9];
    float*       out[9];
    int          n[9];
};

__global__ __launch_bounds__(256)
void roundk(R9 r)
{
    const int seg = blockIdx.y;
    const float* in  = r.in[seg];
    float*       out = r.out[seg];
    const int n = r.n[seg];
    for (int i = (blockIdx.x*256 + threadIdx.x)*4; i < n; i += gridDim.x*256*4) {
        float4 v = *reinterpret_cast<const float4*>(in + i);
        v.x = tf32r(v.x); v.y = tf32r(v.y); v.z = tf32r(v.z); v.w = tf32r(v.w);
        *reinterpret_cast<float4*>(out + i) = v;
    }
}

// ---------------- tf32 tensor-core GEMM (128x128 tile, K=1024) --------------
enum { MODE_PROJ = 0, MODE_RPOS = 1, MODE_POST = 2 };

struct GemmArgs {
    const float* A;
    const float* W;
    const float* bias;
    const float* resid;
    float*       C;
};

#define AS_STRIDE 36
#define BS_STRIDE 136
#define AS_FLOATS (128*AS_STRIDE)
#define BS_FLOATS (32*BS_STRIDE)
#define GEMM_SMEM ((2*AS_FLOATS + 2*BS_FLOATS)*4)

template<int MODE>
__device__ __forceinline__ void stage_copy(
    const float* __restrict__ A, const float* __restrict__ W,
    uint32_t asB, uint32_t bsB, int row0, int col0, int k0, int tid)
{
    #pragma unroll
    for (int i = 0; i < 4; i++) {
        const int c = tid + i*256;
        const int arow = c >> 3, akc = (c & 7) * 4;
        const float* srcA;
        if (MODE == MODE_POST) {
            const int row = row0 + arow, k = k0 + akc;
            srcA = A + (long)(row >> 10)*(NN*LL*HH) + (long)(k >> 6)*(LL*HH)
                     + (long)(row & 1023)*HH + (k & 63);
        } else {
            srcA = A + (long)(row0 + arow)*1024 + k0 + akc;
        }
        asm volatile("cp.async.cg.shared.global [%0], [%1], 16;\n"
                     :: "r"(asB + (uint32_t)((arow*AS_STRIDE + akc)*4)), "l"(srcA));
        const int bk = c >> 5, bnc = (c & 31) * 4;
        const float* srcB;
        if (MODE == MODE_RPOS) {
            const int col = col0 + bnc;
            srcB = W + (long)(col >> 6)*(DD*HH) + (long)(k0 + bk)*HH + (col & 63);
        } else {
            srcB = W + (long)(k0 + bk)*1024 + col0 + bnc;
        }
        asm volatile("cp.async.cg.shared.global [%0], [%1], 16;\n"
                     :: "r"(bsB + (uint32_t)((bk*BS_STRIDE + bnc)*4)), "l"(srcB));
    }
    asm volatile("cp.async.commit_group;\n");
}

template<int MODE>
__global__ __launch_bounds__(256, 2)
void gemm_tf32(GemmArgs g0, GemmArgs g1, GemmArgs g2)
{
    const GemmArgs ga = (blockIdx.z == 0) ? g0 : (blockIdx.z == 1) ? g1 : g2;
    extern __shared__ float smem[];
    float* As = smem;
    float* Bs = smem + 2*AS_FLOATS;

    const int tid  = threadIdx.x;
    const int lane = tid & 31;
    const int w    = tid >> 5;
    const int wm   = w & 1;
    const int wn   = w >> 1;
    const int row0 = blockIdx.y * 128;
    const int col0 = blockIdx.x * 128;

    const uint32_t asB = (uint32_t)__cvta_generic_to_shared(As);
    const uint32_t bsB = (uint32_t)__cvta_generic_to_shared(Bs);

    float acc[4][4][4];
    #pragma unroll
    for (int i = 0; i < 4; i++)
        #pragma unroll
        for (int j = 0; j < 4; j++)
            #pragma unroll
            for (int q = 0; q < 4; q++) acc[i][j][q] = 0.f;

    stage_copy<MODE>(ga.A, ga.W, asB, bsB, row0, col0, 0, tid);

    const int NIT = 1024/32;
    for (int it = 0; it < NIT; it++) {
        const int s = it & 1;
        if (it + 1 < NIT) {
            stage_copy<MODE>(ga.A, ga.W,
                             asB + (uint32_t)((s^1)*AS_FLOATS*4),
                             bsB + (uint32_t)((s^1)*BS_FLOATS*4),
                             row0, col0, (it+1)*32, tid);
            asm volatile("cp.async.wait_group 1;\n");
        } else {
            asm volatile("cp.async.wait_group 0;\n");
        }
        __syncthreads();

        const float* as = As + s*AS_FLOATS;
        const float* bs = Bs + s*BS_FLOATS;
        #pragma unroll
        for (int k8 = 0; k8 < 32; k8 += 8) {
            uint32_t af[4][4], bf[4][2];
            const int fr = lane >> 2;
            const int fc = lane & 3;
            #pragma unroll
            for (int im = 0; im < 4; im++) {
                const int r = wm*64 + im*16 + fr;
                const int c = k8 + fc;
                af[im][0] = __float_as_uint(as[r*AS_STRIDE + c]);
                af[im][1] = __float_as_uint(as[(r+8)*AS_STRIDE + c]);
                af[im][2] = __float_as_uint(as[r*AS_STRIDE + c + 4]);
                af[im][3] = __float_as_uint(as[(r+8)*AS_STRIDE + c + 4]);
            }
            #pragma unroll
            for (int jn = 0; jn < 4; jn++) {
                const int nn = wn*32 + jn*8 + fr;
                const int kk = k8 + fc;
                bf[jn][0] = __float_as_uint(bs[kk*BS_STRIDE + nn]);
                bf[jn][1] = __float_as_uint(bs[(kk+4)*BS_STRIDE + nn]);
            }
            #pragma unroll
            for (int im = 0; im < 4; im++)
                #pragma unroll
                for (int jn = 0; jn < 4; jn++)
                    mma_tf32(acc[im][jn], af[im], bf[jn]);
        }
        __syncthreads();
    }

    const int fr = lane >> 2;
    const int fc = lane & 3;
    #pragma unroll
    for (int jn = 0; jn < 4; jn++) {
        const int colp = col0 + wn*32 + jn*8 + fc*2;
        float b0 = 0.f, b1 = 0.f;
        if (MODE != MODE_RPOS && ga.bias != nullptr) {
            b0 = ga.bias[colp]; b1 = ga.bias[colp + 1];
        }
        #pragma unroll
        for (int im = 0; im < 4; im++) {
            #pragma unroll
            for (int half = 0; half < 2; half++) {
                const int row = row0 + wm*64 + im*16 + fr + half*8;
                float v0 = acc[im][jn][half*2 + 0] + b0;
                float v1 = acc[im][jn][half*2 + 1] + b1;
                if (MODE == MODE_PROJ) {
                    long o = (long)((row >> 10)*NN + (colp >> 6))*(LL*HH)
                           + (long)(row & 1023)*HH + (colp & 63);
                    *reinterpret_cast<float2*>(ga.C + o) = make_float2(tf32r(v0), tf32r(v1));
                } else if (MODE == MODE_RPOS) {
                    long o = (long)(colp >> 6)*(RR*HH) + (long)row*HH + (colp & 63);
                    *reinterpret_cast<float2*>(ga.C + o) = make_float2(tf32r(v0), tf32r(v1));
                } else {
                    long o = (long)row*1024 + colp;
                    float2 rr = *reinterpret_cast<const float2*>(ga.resid + o);
                    *reinterpret_cast<float2*>(ga.C + o) = make_float2(v0 + rr.x, v1 + rr.y);
                }
            }
        }
    }
}

// ---------------- fused attention: bf16 mma + ldmatrix + log2 softmax -------
// block 256 (8 warps: 4 warp-rows x 2 warp-cols), grid (16 l-tiles, 64 bn)
// bf16 operand tiles use 144-byte row stride (9 x 16B): the 8 ldmatrix row
// pointers land in distinct 16B phases -> conflict-free (incl. .trans).
// smem byte layout:
//   QW  [64][72]  bf16  q+rwb      @ 0      (9216)
//   QD  [64][72]  bf16  q+rrb      @ 9216   (9216)
//   KT  [64][72]  bf16  m-major    @ 18432  (9216)
//   RB  [128][72] bf16  u-major    @ 27648  (18432)   Vs[64][72] union
//   G2s [128][66] fp32            @ 46080  (33792)   Ps[64][72] bf16 union
//   maskv[64] f32 @ 79872, rmaxs[2][64] @ 80128, rsums[2][64] @ 80640
#define QW_OFF   0
#define QD_OFF   9216
#define KT_OFF   18432
#define RB_OFF   27648
#define VS_OFF   27648
#define G2_OFF   46080
#define PS_OFF   46080
#define MK_OFF   79872
#define RM_OFF   80128
#define RS_OFF   80640
#define ATT_SMEM 81152
#define SC_LOG2 0.18033688011112042f   // 0.125 * log2(e)
#define MASK_LOG2 -1442695.04f         // -1e6 * log2(e)

__global__ __launch_bounds__(256, 2)
void attn_mma(const int* __restrict__ padding,
              const float* __restrict__ rwb,
              const float* __restrict__ rrb)
{
    extern __shared__ char smB[];
    const uint32_t s0 = (uint32_t)__cvta_generic_to_shared(smB);
    float* G2s   = reinterpret_cast<float*>(smB + G2_OFF);
    float* maskv = reinterpret_cast<float*>(smB + MK_OFF);
    float* rmaxs = reinterpret_cast<float*>(smB + RM_OFF);
    float* rsums = reinterpret_cast<float*>(smB + RS_OFF);

    const int tid  = threadIdx.x;
    const int lane = tid & 31;
    const int w    = tid >> 5;
    const int wr   = w >> 1;                  // 0..3
    const int wc   = w & 1;                   // 0..1
    const int fr   = lane >> 2;               // 0..7
    const int fc   = lane & 3;                // 0..3
    const int bn   = blockIdx.y;
    const int l0   = blockIdx.x * 64;
    const int b    = bn >> 4;
    const int n    = bn & 15;

    const float* qh = g_qh + (long)bn * (LL*HH);
    const float* kh = g_kh + (long)bn * (LL*HH);
    const float* vh = g_vh + (long)bn * (LL*HH);
    const float* rp = g_r  + (long)n  * (RR*HH);
    float*       op = g_o  + (long)bn * (LL*HH);

    // ---- prologue: QW = bf16(q + rwb), QD = bf16(q + rrb)
    #pragma unroll
    for (int i = 0; i < 4; i++) {
        const int idx = tid + i*256;
        const int l = idx >> 4, hc = (idx & 15)*4;
        float4 v = *reinterpret_cast<const float4*>(qh + (long)(l0 + l)*64 + hc);
        float bw0 = rwb[n*64 + hc + 0], bw1 = rwb[n*64 + hc + 1];
        float bw2 = rwb[n*64 + hc + 2], bw3 = rwb[n*64 + hc + 3];
        float br0 = rrb[n*64 + hc + 0], br1 = rrb[n*64 + hc + 1];
        float br2 = rrb[n*64 + hc + 2], br3 = rrb[n*64 + hc + 3];
        uint2 pw = make_uint2(bf2(v.x + bw0, v.y + bw1), bf2(v.z + bw2, v.w + bw3));
        uint2 pd = make_uint2(bf2(v.x + br0, v.y + br1), bf2(v.z + br2, v.w + br3));
        *reinterpret_cast<uint2*>(smB + QW_OFF + l*144 + hc*2) = pw;
        *reinterpret_cast<uint2*>(smB + QD_OFF + l*144 + hc*2) = pd;
    }

    // lane-static ldmatrix address components
    const int gA   = lane >> 3;               // 0..3
    const int rA   = lane & 7;
    const int rowA = wr*16 + (gA & 1)*8 + rA; // A row for this lane
    const int colA = (gA >> 1)*8;             // A k-offset
    const uint32_t aQW = s0 + QW_OFF + rowA*144 + colA*2;
    const uint32_t aQD = s0 + QD_OFF + rowA*144 + colA*2;
    const uint32_t aPS = s0 + PS_OFF + rowA*144 + colA*2;
    const int rB   = lane & 7;                // B row within group
    const int hB   = (lane >> 3) & 1;         // B k-half (0/1)

    float O[4][4];
    float mi[2], li[2];
    #pragma unroll
    for (int jn = 0; jn < 4; jn++)
        #pragma unroll
        for (int q = 0; q < 4; q++) O[jn][q] = 0.f;
    mi[0] = mi[1] = -1e30f;
    li[0] = li[1] = 0.f;

    for (int m0 = 0; m0 < LL; m0 += 64) {
        __syncthreads();   // prior tile's G1/PV done before overwriting KT/RB/Ps

        // ---- loads: KT (bf16 m-major), RB band (bf16 u-major), maskv
        #pragma unroll
        for (int i = 0; i < 4; i++) {
            const int idx = tid + i*256;
            const int m = idx >> 4, hc = (idx & 15)*4;
            float4 v = *reinterpret_cast<const float4*>(kh + (long)(m0 + m)*64 + hc);
            *reinterpret_cast<uint2*>(smB + KT_OFF + m*144 + hc*2) =
                make_uint2(bf2(v.x, v.y), bf2(v.z, v.w));
        }
        const int jmin = LL + m0 - l0 - 63;
        #pragma unroll
        for (int i = 0; i < 8; i++) {
            const int idx = tid + i*256;
            const int u = idx >> 4, hc = (idx & 15)*4;
            float4 v = make_float4(0.f,0.f,0.f,0.f);
            if (u < 127)
                v = *reinterpret_cast<const float4*>(rp + (long)(jmin + u)*64 + hc);
            *reinterpret_cast<uint2*>(smB + RB_OFF + u*144 + hc*2) =
                make_uint2(bf2(v.x, v.y), bf2(v.z, v.w));
        }
        if (tid < 64)
            maskv[tid] = (padding[b*LL + m0 + tid] != 0) ? MASK_LOG2 : 0.0f;
        __syncthreads();

        // ---- G2 mma: 64x128 band (A=QD), two 64-col halves
        #pragma unroll
        for (int jh = 0; jh < 2; jh++) {
            float g2[4][4];
            #pragma unroll
            for (int jn = 0; jn < 4; jn++)
                #pragma unroll
                for (int q = 0; q < 4; q++) g2[jn][q] = 0.f;
            #pragma unroll
            for (int k0 = 0; k0 < 64; k0 += 16) {
                uint32_t a[4];
                ldsm_x4(a[0], a[1], a[2], a[3], aQD + k0*2);
                #pragma unroll
                for (int jn = 0; jn < 4; jn++) {
                    const int ub = wc*64 + jh*32 + jn*8;
                    uint32_t bfr[2];
                    ldsm_x2(bfr[0], bfr[1],
                            s0 + RB_OFF + (ub + rB)*144 + (k0 + hB*8)*2);
                    mma_bf16(g2[jn], a, bfr);
                }
            }
            #pragma unroll
            for (int jn = 0; jn < 4; jn++) {
                const int ub = wc*64 + jh*32 + jn*8 + fc*2;
                const int lb = wr*16 + fr;
                G2s[(ub+0)*66 + lb]     = g2[jn][0];
                G2s[(ub+1)*66 + lb]     = g2[jn][1];
                G2s[(ub+0)*66 + lb + 8] = g2[jn][2];
                G2s[(ub+1)*66 + lb + 8] = g2[jn][3];
            }
        }
        __syncthreads();   // G2s complete; RB free for Vs

        // ---- Vs load (bf16 m-major, over RB union)
        #pragma unroll
        for (int i = 0; i < 4; i++) {
            const int idx = tid + i*256;
            const int m = idx >> 4, hc = (idx & 15)*4;
            float4 v = *reinterpret_cast<const float4*>(vh + (long)(m0 + m)*64 + hc);
            *reinterpret_cast<uint2*>(smB + VS_OFF + m*144 + hc*2) =
                make_uint2(bf2(v.x, v.y), bf2(v.z, v.w));
        }

        // ---- G1 mma: 64x64 scores (A=QW, B=KT)
        float s1[4][4];
        #pragma unroll
        for (int jn = 0; jn < 4; jn++)
            #pragma unroll
            for (int q = 0; q < 4; q++) s1[jn][q] = 0.f;
        #pragma unroll
        for (int k0 = 0; k0 < 64; k0 += 16) {
            uint32_t a[4];
            ldsm_x4(a[0], a[1], a[2], a[3], aQW + k0*2);
            #pragma unroll
            for (int jn = 0; jn < 4; jn++) {
                const int nb = wc*32 + jn*8;
                uint32_t bfr[2];
                ldsm_x2(bfr[0], bfr[1],
                        s0 + KT_OFF + (nb + rB)*144 + (k0 + hB*8)*2);
                mma_bf16(s1[jn], a, bfr);
            }
        }

        // ---- assemble S (log2 domain) + per-warp row max
        float sv[4][4];
        float rmx[2] = {-1e30f, -1e30f};
        #pragma unroll
        for (int jn = 0; jn < 4; jn++) {
            #pragma unroll
            for (int q = 0; q < 4; q++) {
                const int ll = wr*16 + fr + (q >> 1)*8;
                const int mc = wc*32 + jn*8 + fc*2 + (q & 1);
                const int u  = mc - ll + 63;
                float x = (s1[jn][q] + G2s[u*66 + ll]) * SC_LOG2 + maskv[mc];
                sv[jn][q] = x;
                rmx[q >> 1] = fmaxf(rmx[q >> 1], x);
            }
        }
        #pragma unroll
        for (int r = 0; r < 2; r++) {
            rmx[r] = fmaxf(rmx[r], __shfl_xor_sync(0xffffffffu, rmx[r], 1));
            rmx[r] = fmaxf(rmx[r], __shfl_xor_sync(0xffffffffu, rmx[r], 2));
        }
        if (fc == 0) {
            rmaxs[wc*64 + wr*16 + fr]     = rmx[0];
            rmaxs[wc*64 + wr*16 + fr + 8] = rmx[1];
        }
        __syncthreads();   // row maxes ready; all G2s gathers done

        // ---- softmax: exp2, P store (bf16), partial sums
        float nm[2], al[2], psum[2];
        #pragma unroll
        for (int r = 0; r < 2; r++) {
            const int row = wr*16 + fr + r*8;
            const float tm = fmaxf(rmaxs[row], rmaxs[64 + row]);
            nm[r] = fmaxf(mi[r], tm);
            al[r] = ex2f(mi[r] - nm[r]);
            mi[r] = nm[r];
            psum[r] = 0.f;
        }
        #pragma unroll
        for (int jn = 0; jn < 4; jn++) {
            #pragma unroll
            for (int r = 0; r < 2; r++) {
                float p0 = ex2f(sv[jn][r*2 + 0] - nm[r]);
                float p1 = ex2f(sv[jn][r*2 + 1] - nm[r]);
                psum[r] += p0 + p1;
                const int ll = wr*16 + fr + r*8;
                const int mc = wc*32 + jn*8 + fc*2;
                *reinterpret_cast<uint32_t*>(smB + PS_OFF + ll*144 + mc*2) = bf2(p0, p1);
            }
        }
        #pragma unroll
        for (int r = 0; r < 2; r++) {
            psum[r] += __shfl_xor_sync(0xffffffffu, psum[r], 1);
            psum[r] += __shfl_xor_sync(0xffffffffu, psum[r], 2);
        }
        if (fc == 0) {
            rsums[wc*64 + wr*16 + fr]     = psum[0];
            rsums[wc*64 + wr*16 + fr + 8] = psum[1];
        }
        __syncthreads();   // Ps + Vs + sums ready

        // ---- li update, O rescale, PV mma (A=Ps, B=Vs via ldmatrix.trans)
        #pragma unroll
        for (int r = 0; r < 2; r++) {
            const int row = wr*16 + fr + r*8;
            li[r] = li[r]*al[r] + (rsums[row] + rsums[64 + row]);
        }
        #pragma unroll
        for (int jn = 0; jn < 4; jn++) {
            O[jn][0] *= al[0]; O[jn][1] *= al[0];
            O[jn][2] *= al[1]; O[jn][3] *= al[1];
        }
        #pragma unroll
        for (int k0 = 0; k0 < 64; k0 += 16) {
            uint32_t a[4];
            ldsm_x4(a[0], a[1], a[2], a[3], aPS + k0*2);
            #pragma unroll
            for (int jn = 0; jn < 4; jn++) {
                const int hb = wc*32 + jn*8;
                uint32_t bfr[2];
                ldsm_x2t(bfr[0], bfr[1],
                         s0 + VS_OFF + (k0 + rB + hB*8)*144 + hb*2);
                mma_bf16(O[jn], a, bfr);
            }
        }
    }

    // ---- final: normalize, round (feeds tf32 POST GEMM), write
    const float inv0 = 1.0f / li[0];
    const float inv1 = 1.0f / li[1];
    #pragma unroll
    for (int jn = 0; jn < 4; jn++) {
        const int col = wc*32 + jn*8 + fc*2;
        const int lr0 = l0 + wr*16 + fr;
        *reinterpret_cast<float2*>(op + (long)lr0*64 + col) =
            make_float2(tf32r(O[jn][0]*inv0), tf32r(O[jn][1]*inv0));
        *reinterpret_cast<float2*>(op + (long)(lr0 + 8)*64 + col) =
            make_float2(tf32r(O[jn][2]*inv1), tf32r(O[jn][3]*inv1));
    }
}

// ---------------- layernorm over D per (b,l) row -----------------------------
__global__ __launch_bounds__(256)
void ln_kernel(const float* __restrict__ lng, const float* __restrict__ lnb,
               float* __restrict__ out)
{
    __shared__ float red[256];
    const int row = blockIdx.x;
    const int tid = threadIdx.x;
    const float* x = g_x + (long)row * DD;

    float v[4]; float s = 0.f;
    #pragma unroll
    for (int i = 0; i < 4; i++) { v[i] = x[tid + i*256]; s += v[i]; }
    red[tid] = s; __syncthreads();
    #pragma unroll
    for (int off = 128; off > 0; off >>= 1) {
        if (tid < off) red[tid] += red[tid + off];
        __syncthreads();
    }
    const float mu = red[0] * (1.f / DD);
    __syncthreads();

    float vs = 0.f;
    #pragma unroll
    for (int i = 0; i < 4; i++) { const float d = v[i] - mu; vs += d*d; }
    red[tid] = vs; __syncthreads();
    #pragma unroll
    for (int off = 128; off > 0; off >>= 1) {
        if (tid < off) red[tid] += red[tid + off];
        __syncthreads();
    }
    const float inv = rsqrtf(red[0] * (1.f / DD) + 1e-5f);

    #pragma unroll
    for (int i = 0; i < 4; i++) {
        const int d0 = tid + i*256;
        out[(long)row*DD + d0] = (v[i] - mu) * inv * lng[d0] + lnb[d0];
    }
}

// ---------------- launcher ---------------------------------------------------
extern "C" void kernel_launch(void* const* d_in, const int* in_sizes, int n_in,
                              void* d_out, int out_size)
{
    const float* q   = (const float*)d_in[0];
    const float* k   = (const float*)d_in[1];
    const float* v   = (const float*)d_in[2];
    const float* pe  = (const float*)d_in[3];
    const int*   pad = (const int*)d_in[4];
    const float* q_w = (const float*)d_in[5];
    const float* k_w = (const float*)d_in[6];
    const float* k_b = (const float*)d_in[7];
    const float* v_w = (const float*)d_in[8];
    const float* v_b = (const float*)d_in[9];
    const float* rwb = (const float*)d_in[10];
    const float* rrb = (const float*)d_in[11];
    const float* rk  = (const float*)d_in[12];
    const float* pw  = (const float*)d_in[13];
    const float* pb  = (const float*)d_in[14];
    const float* lng = (const float*)d_in[15];
    const float* lnb = (const float*)d_in[16];

    void *p_qh, *p_kh, *p_vh, *p_r, *p_o, *p_x;
    void *p_tq, *p_tk, *p_tv, *p_tpe, *p_tqw, *p_tkw, *p_tvw, *p_trk, *p_tpw;
    cudaGetSymbolAddress(&p_qh, g_qh);
    cudaGetSymbolAddress(&p_kh, g_kh);
    cudaGetSymbolAddress(&p_vh, g_vh);
    cudaGetSymbolAddress(&p_r,  g_r);
    cudaGetSymbolAddress(&p_o,  g_o);
    cudaGetSymbolAddress(&p_x,  g_x);
    cudaGetSymbolAddress(&p_tq,  g_tq);
    cudaGetSymbolAddress(&p_tk,  g_tk);
    cudaGetSymbolAddress(&p_tv,  g_tv);
    cudaGetSymbolAddress(&p_tpe, g_tpe);
    cudaGetSymbolAddress(&p_tqw, g_tqw);
    cudaGetSymbolAddress(&p_tkw, g_tkw);
    cudaGetSymbolAddress(&p_tvw, g_tvw);
    cudaGetSymbolAddress(&p_trk, g_trk);
    cudaGetSymbolAddress(&p_tpw, g_tpw);

    const dim3 blk(256);

    // ---- pass 1: tf32-round all GEMM operands
    R9 r;
    r.in[0]=q;   r.out[0]=(float*)p_tq;  r.n[0]=BB*LL*DD;
    r.in[1]=k;   r.out[1]=(float*)p_tk;  r.n[1]=BB*LL*DD;
    r.in[2]=v;   r.out[2]=(float*)p_tv;  r.n[2]=BB*LL*DD;
    r.in[3]=pe;  r.out[3]=(float*)p_tpe; r.n[3]=RR*DD;
    r.in[4]=q_w; r.out[4]=(float*)p_tqw; r.n[4]=DD*NN*HH;
    r.in[5]=k_w; r.out[5]=(float*)p_tkw; r.n[5]=DD*NN*HH;
    r.in[6]=v_w; r.out[6]=(float*)p_tvw; r.n[6]=DD*NN*HH;
    r.in[7]=rk;  r.out[7]=(float*)p_trk; r.n[7]=NN*DD*HH;
    r.in[8]=pw;  r.out[8]=(float*)p_tpw; r.n[8]=NN*HH*DD;
    roundk<<<dim3(1024, 9), blk>>>(r);

    // ---- pass 2: projections + rpos (outputs tf32-rounded for attention)
    cudaFuncSetAttribute(gemm_tf32<MODE_PROJ>, cudaFuncAttributeMaxDynamicSharedMemorySize, GEMM_SMEM);
    cudaFuncSetAttribute(gemm_tf32<MODE_RPOS>, cudaFuncAttributeMaxDynamicSharedMemorySize, GEMM_SMEM);
    cudaFuncSetAttribute(gemm_tf32<MODE_POST>, cudaFuncAttributeMaxDynamicSharedMemorySize, GEMM_SMEM);

    GemmArgs gq = { (const float*)p_tq, (const float*)p_tqw, nullptr, nullptr, (float*)p_qh };
    GemmArgs gk = { (const float*)p_tk, (const float*)p_tkw, k_b,     nullptr, (float*)p_kh };
    GemmArgs gv = { (const float*)p_tv, (const float*)p_tvw, v_b,     nullptr, (float*)p_vh };
    gemm_tf32<MODE_PROJ><<<dim3(8, 32, 3), blk, GEMM_SMEM>>>(gq, gk, gv);

    GemmArgs gr = { (const float*)p_tpe, (const float*)p_trk, nullptr, nullptr, (float*)p_r };
    gemm_tf32<MODE_RPOS><<<dim3(8, 16, 1), blk, GEMM_SMEM>>>(gr, gr, gr);

    // ---- pass 3: fused attention (bf16 tensor cores + ldmatrix)
    cudaFuncSetAttribute(attn_mma, cudaFuncAttributeMaxDynamicSharedMemorySize, ATT_SMEM);
    attn_mma<<<dim3(LL/64, BB*NN), blk, ATT_SMEM>>>(pad, rwb, rrb);

    // ---- pass 4: post GEMM (+bias +residual)
    GemmArgs gp = { (const float*)p_o, (const float*)p_tpw, pb, q, (float*)p_x };
    gemm_tf32<MODE_POST><<<dim3(8, 32, 1), blk, GEMM_SMEM>>>(gp, gp, gp);

    // ---- pass 5: layernorm
    ln_kernel<<<BB*LL, blk>>>(lng, lnb, (float*)d_out);
}

// round 10
// speedup vs baseline: 7.7760x; 1.0593x over previous
#include <cuda_runtime.h>
#include <cuda_bf16.h>
#include <math.h>
#include <stdint.h>

#define BB 4
#define LL 1024
#define DD 1024
#define NN 16
#define HH 64
#define RR 2048

// ---------------- scratch (static device globals: no allocations allowed) ---
__device__ float g_qh[BB*NN*LL*HH];   // [b][n][l][h] (tf32-rounded)
__device__ float g_kh[BB*NN*LL*HH];   // (tf32-rounded, k_b added)
__device__ float g_vh[BB*NN*LL*HH];   // (tf32-rounded, v_b added)
__device__ float g_r [NN*RR*HH];      // [n][j][h] (tf32-rounded)
__device__ float g_cu[NN*RR + 128];   // c[n][j] = (rrb-rwb)[n] . r[n][j]  (+pad)
__device__ float g_o [BB*NN*LL*HH];   // attention output (tf32-rounded)
__device__ float g_x [BB*LL*DD];      // pre-layernorm residual sum

// tf32-rounded operand copies
__device__ float g_tq [BB*LL*DD];
__device__ float g_tk [BB*LL*DD];
__device__ float g_tv [BB*LL*DD];
__device__ float g_tpe[RR*DD];
__device__ float g_tqw[DD*NN*HH];
__device__ float g_tkw[DD*NN*HH];
__device__ float g_tvw[DD*NN*HH];
__device__ float g_trk[NN*DD*HH];
__device__ float g_tpw[NN*HH*DD];

// ---------------- helpers ---------------------------------------------------
__device__ __forceinline__ float tf32r(float x) {
    uint32_t u;
    asm("cvt.rna.tf32.f32 %0, %1;" : "=r"(u) : "f"(x));
    return __uint_as_float(u);
}
__device__ __forceinline__ float ex2f(float x) {
    float y;
    asm("ex2.approx.ftz.f32 %0, %1;" : "=f"(y) : "f"(x));
    return y;
}
// pack (lo=a, hi=b) into bf16x2
__device__ __forceinline__ uint32_t bf2(float a, float b) {
    uint32_t r;
    asm("cvt.rn.bf16x2.f32 %0, %1, %2;" : "=r"(r) : "f"(b), "f"(a));
    return r;
}

__device__ __forceinline__ void mma_tf32(float* d, const uint32_t* a, const uint32_t* b) {
    asm volatile(
        "mma.sync.aligned.m16n8k8.row.col.f32.tf32.tf32.f32 "
        "{%0,%1,%2,%3}, {%4,%5,%6,%7}, {%8,%9}, {%0,%1,%2,%3};\n"
        : "+f"(d[0]), "+f"(d[1]), "+f"(d[2]), "+f"(d[3])
        : "r"(a[0]), "r"(a[1]), "r"(a[2]), "r"(a[3]), "r"(b[0]), "r"(b[1]));
}
__device__ __forceinline__ void mma_bf16(float* d, const uint32_t* a, const uint32_t* b) {
    asm volatile(
        "mma.sync.aligned.m16n8k16.row.col.f32.bf16.bf16.f32 "
        "{%0,%1,%2,%3}, {%4,%5,%6,%7}, {%8,%9}, {%0,%1,%2,%3};\n"
        : "+f"(d[0]), "+f"(d[1]), "+f"(d[2]), "+f"(d[3])
        : "r"(a[0]), "r"(a[1]), "r"(a[2]), "r"(a[3]), "r"(b[0]), "r"(b[1]));
}
__device__ __forceinline__ void ldsm_x4(uint32_t& r0, uint32_t& r1, uint32_t& r2, uint32_t& r3, uint32_t addr) {
    asm volatile("ldmatrix.sync.aligned.m8n8.x4.shared.b16 {%0,%1,%2,%3}, [%4];"
                 : "=r"(r0), "=r"(r1), "=r"(r2), "=r"(r3) : "r"(addr));
}
__device__ __forceinline__ void ldsm_x4t(uint32_t& r0, uint32_t& r1, uint32_t& r2, uint32_t& r3, uint32_t addr) {
    asm volatile("ldmatrix.sync.aligned.m8n8.x4.trans.shared.b16 {%0,%1,%2,%3}, [%4];"
                 : "=r"(r0), "=r"(r1), "=r"(r2), "=r"(r3) : "r"(addr));
}

// ---------------- fused tf32 rounding pass (all GEMM operands) --------------
struct R9 {
    const float* in[9];
    float*       out[9];
    int          n[9];
};

__global__ __launch_bounds__(256)
void roundk(R9 r)
{
    const int seg = blockIdx.y;
    const float* in  = r.in[seg];
    float*       out = r.out[seg];
    const int n = r.n[seg];
    for (int i = (blockIdx.x*256 + threadIdx.x)*4; i < n; i += gridDim.x*256*4) {
        float4 v = *reinterpret_cast<const float4*>(in + i);
        v.x = tf32r(v.x); v.y = tf32r(v.y); v.z = tf32r(v.z); v.w = tf32r(v.w);
        *reinterpret_cast<float4*>(out + i) = v;
    }
}

// ---------------- c_u precompute: g_cu[n][j] = (rrb-rwb)[n] . g_r[n][j] -----
__global__ __launch_bounds__(256)
void cu_kernel(const float* __restrict__ rwb, const float* __restrict__ rrb)
{
    const int idx = blockIdx.x*256 + threadIdx.x;   // 32768 total
    const int n = idx >> 11;
    const int j = idx & 2047;
    const float* rr = g_r + ((long)n*RR + j)*HH;
    const float* dw = rwb + n*64;
    const float* dr = rrb + n*64;
    float acc = 0.f;
    #pragma unroll
    for (int h = 0; h < 64; h += 4) {
        float4 rv = *reinterpret_cast<const float4*>(rr + h);
        acc += (dr[h+0]-dw[h+0])*rv.x + (dr[h+1]-dw[h+1])*rv.y
             + (dr[h+2]-dw[h+2])*rv.z + (dr[h+3]-dw[h+3])*rv.w;
    }
    g_cu[idx] = acc;
}

// ---------------- tf32 tensor-core GEMM machinery ---------------------------
enum { MODE_PROJ = 0, MODE_RPOS = 1, MODE_POST = 2 };

struct GemmArgs {
    const float* A;
    const float* W;
    const float* bias;
    const float* resid;
    float*       C;
};

#define AS_STRIDE 36
#define BS_STRIDE 136
#define AS_FLOATS (128*AS_STRIDE)
#define BS_FLOATS (32*BS_STRIDE)
#define GEMM_SMEM ((2*AS_FLOATS + 2*BS_FLOATS)*4)

// runtime-mode stage copy (A row-major; B: rpos picks r_kernel gather)
__device__ __forceinline__ void stage_copy_rt(
    const float* __restrict__ A, const float* __restrict__ W, bool rpos,
    uint32_t asB, uint32_t bsB, int row0, int col0, int k0, int tid)
{
    #pragma unroll
    for (int i = 0; i < 4; i++) {
        const int c = tid + i*256;
        const int arow = c >> 3, akc = (c & 7) * 4;
        const float* srcA = A + (long)(row0 + arow)*1024 + k0 + akc;
        asm volatile("cp.async.cg.shared.global [%0], [%1], 16;\n"
                     :: "r"(asB + (uint32_t)((arow*AS_STRIDE + akc)*4)), "l"(srcA));
        const int bk = c >> 5, bnc = (c & 31) * 4;
        const float* srcB;
        if (rpos) {
            const int col = col0 + bnc;
            srcB = W + (long)(col >> 6)*(DD*HH) + (long)(k0 + bk)*HH + (col & 63);
        } else {
            srcB = W + (long)(k0 + bk)*1024 + col0 + bnc;
        }
        asm volatile("cp.async.cg.shared.global [%0], [%1], 16;\n"
                     :: "r"(bsB + (uint32_t)((bk*BS_STRIDE + bnc)*4)), "l"(srcB));
    }
    asm volatile("cp.async.commit_group;\n");
}

// merged q/k/v projections + rpos in one launch (grid.z = 0..3)
__global__ __launch_bounds__(256, 2)
void gemm_qkvr(GemmArgs g0, GemmArgs g1, GemmArgs g2, GemmArgs g3)
{
    const int z = blockIdx.z;
    const bool rpos = (z == 3);
    if (rpos && blockIdx.y >= 16) return;
    const GemmArgs ga = (z==0)?g0 : (z==1)?g1 : (z==2)?g2 : g3;

    extern __shared__ float smem[];
    float* As = smem;
    float* Bs = smem + 2*AS_FLOATS;

    const int tid  = threadIdx.x;
    const int lane = tid & 31;
    const int w    = tid >> 5;
    const int wm   = w & 1;
    const int wn   = w >> 1;
    const int row0 = blockIdx.y * 128;
    const int col0 = blockIdx.x * 128;

    const uint32_t asB = (uint32_t)__cvta_generic_to_shared(As);
    const uint32_t bsB = (uint32_t)__cvta_generic_to_shared(Bs);

    float acc[4][4][4];
    #pragma unroll
    for (int i = 0; i < 4; i++)
        #pragma unroll
        for (int j = 0; j < 4; j++)
            #pragma unroll
            for (int q = 0; q < 4; q++) acc[i][j][q] = 0.f;

    stage_copy_rt(ga.A, ga.W, rpos, asB, bsB, row0, col0, 0, tid);

    const int NIT = 1024/32;
    for (int it = 0; it < NIT; it++) {
        const int s = it & 1;
        if (it + 1 < NIT) {
            stage_copy_rt(ga.A, ga.W, rpos,
                          asB + (uint32_t)((s^1)*AS_FLOATS*4),
                          bsB + (uint32_t)((s^1)*BS_FLOATS*4),
                          row0, col0, (it+1)*32, tid);
            asm volatile("cp.async.wait_group 1;\n");
        } else {
            asm volatile("cp.async.wait_group 0;\n");
        }
        __syncthreads();

        const float* as = As + s*AS_FLOATS;
        const float* bs = Bs + s*BS_FLOATS;
        #pragma unroll
        for (int k8 = 0; k8 < 32; k8 += 8) {
            uint32_t af[4][4], bf[4][2];
            const int fr = lane >> 2;
            const int fc = lane & 3;
            #pragma unroll
            for (int im = 0; im < 4; im++) {
                const int r = wm*64 + im*16 + fr;
                const int c = k8 + fc;
                af[im][0] = __float_as_uint(as[r*AS_STRIDE + c]);
                af[im][1] = __float_as_uint(as[(r+8)*AS_STRIDE + c]);
                af[im][2] = __float_as_uint(as[r*AS_STRIDE + c + 4]);
                af[im][3] = __float_as_uint(as[(r+8)*AS_STRIDE + c + 4]);
            }
            #pragma unroll
            for (int jn = 0; jn < 4; jn++) {
                const int nn = wn*32 + jn*8 + fr;
                const int kk = k8 + fc;
                bf[jn][0] = __float_as_uint(bs[kk*BS_STRIDE + nn]);
                bf[jn][1] = __float_as_uint(bs[(kk+4)*BS_STRIDE + nn]);
            }
            #pragma unroll
            for (int im = 0; im < 4; im++)
                #pragma unroll
                for (int jn = 0; jn < 4; jn++)
                    mma_tf32(acc[im][jn], af[im], bf[jn]);
        }
        __syncthreads();
    }

    const int fr = lane >> 2;
    const int fc = lane & 3;
    #pragma unroll
    for (int jn = 0; jn < 4; jn++) {
        const int colp = col0 + wn*32 + jn*8 + fc*2;
        float b0 = 0.f, b1 = 0.f;
        if (!rpos && ga.bias != nullptr) {
            b0 = ga.bias[colp]; b1 = ga.bias[colp + 1];
        }
        #pragma unroll
        for (int im = 0; im < 4; im++) {
            #pragma unroll
            for (int half = 0; half < 2; half++) {
                const int row = row0 + wm*64 + im*16 + fr + half*8;
                float v0 = acc[im][jn][half*2 + 0] + b0;
                float v1 = acc[im][jn][half*2 + 1] + b1;
                if (rpos) {
                    long o = (long)(colp >> 6)*(RR*HH) + (long)row*HH + (colp & 63);
                    *reinterpret_cast<float2*>(ga.C + o) = make_float2(tf32r(v0), tf32r(v1));
                } else {
                    long o = (long)((row >> 10)*NN + (colp >> 6))*(LL*HH)
                           + (long)(row & 1023)*HH + (colp & 63);
                    *reinterpret_cast<float2*>(ga.C + o) = make_float2(tf32r(v0), tf32r(v1));
                }
            }
        }
    }
}

// POST gemm keeps templated path (A = g_o gather, row-major W, +bias+resid)
template<int MODE>
__device__ __forceinline__ void stage_copy(
    const float* __restrict__ A, const float* __restrict__ W,
    uint32_t asB, uint32_t bsB, int row0, int col0, int k0, int tid)
{
    #pragma unroll
    for (int i = 0; i < 4; i++) {
        const int c = tid + i*256;
        const int arow = c >> 3, akc = (c & 7) * 4;
        const float* srcA;
        if (MODE == MODE_POST) {
            const int row = row0 + arow, k = k0 + akc;
            srcA = A + (long)(row >> 10)*(NN*LL*HH) + (long)(k >> 6)*(LL*HH)
                     + (long)(row & 1023)*HH + (k & 63);
        } else {
            srcA = A + (long)(row0 + arow)*1024 + k0 + akc;
        }
        asm volatile("cp.async.cg.shared.global [%0], [%1], 16;\n"
                     :: "r"(asB + (uint32_t)((arow*AS_STRIDE + akc)*4)), "l"(srcA));
        const int bk = c >> 5, bnc = (c & 31) * 4;
        const float* srcB = W + (long)(k0 + bk)*1024 + col0 + bnc;
        asm volatile("cp.async.cg.shared.global [%0], [%1], 16;\n"
                     :: "r"(bsB + (uint32_t)((bk*BS_STRIDE + bnc)*4)), "l"(srcB));
    }
    asm volatile("cp.async.commit_group;\n");
}

template<int MODE>
__global__ __launch_bounds__(256, 2)
void gemm_tf32(GemmArgs ga)
{
    extern __shared__ float smem[];
    float* As = smem;
    float* Bs = smem + 2*AS_FLOATS;

    const int tid  = threadIdx.x;
    const int lane = tid & 31;
    const int w    = tid >> 5;
    const int wm   = w & 1;
    const int wn   = w >> 1;
    const int row0 = blockIdx.y * 128;
    const int col0 = blockIdx.x * 128;

    const uint32_t asB = (uint32_t)__cvta_generic_to_shared(As);
    const uint32_t bsB = (uint32_t)__cvta_generic_to_shared(Bs);

    float acc[4][4][4];
    #pragma unroll
    for (int i = 0; i < 4; i++)
        #pragma unroll
        for (int j = 0; j < 4; j++)
            #pragma unroll
            for (int q = 0; q < 4; q++) acc[i][j][q] = 0.f;

    stage_copy<MODE>(ga.A, ga.W, asB, bsB, row0, col0, 0, tid);

    const int NIT = 1024/32;
    for (int it = 0; it < NIT; it++) {
        const int s = it & 1;
        if (it + 1 < NIT) {
            stage_copy<MODE>(ga.A, ga.W,
                             asB + (uint32_t)((s^1)*AS_FLOATS*4),
                             bsB + (uint32_t)((s^1)*BS_FLOATS*4),
                             row0, col0, (it+1)*32, tid);
            asm volatile("cp.async.wait_group 1;\n");
        } else {
            asm volatile("cp.async.wait_group 0;\n");
        }
        __syncthreads();

        const float* as = As + s*AS_FLOATS;
        const float* bs = Bs + s*BS_FLOATS;
        #pragma unroll
        for (int k8 = 0; k8 < 32; k8 += 8) {
            uint32_t af[4][4], bf[4][2];
            const int fr = lane >> 2;
            const int fc = lane & 3;
            #pragma unroll
            for (int im = 0; im < 4; im++) {
                const int r = wm*64 + im*16 + fr;
                const int c = k8 + fc;
                af[im][0] = __float_as_uint(as[r*AS_STRIDE + c]);
                af[im][1] = __float_as_uint(as[(r+8)*AS_STRIDE + c]);
                af[im][2] = __float_as_uint(as[r*AS_STRIDE + c + 4]);
                af[im][3] = __float_as_uint(as[(r+8)*AS_STRIDE + c + 4]);
            }
            #pragma unroll
            for (int jn = 0; jn < 4; jn++) {
                const int nn = wn*32 + jn*8 + fr;
                const int kk = k8 + fc;
                bf[jn][0] = __float_as_uint(bs[kk*BS_STRIDE + nn]);
                bf[jn][1] = __float_as_uint(bs[(kk+4)*BS_STRIDE + nn]);
            }
            #pragma unroll
            for (int im = 0; im < 4; im++)
                #pragma unroll
                for (int jn = 0; jn < 4; jn++)
                    mma_tf32(acc[im][jn], af[im], bf[jn]);
        }
        __syncthreads();
    }

    const int fr = lane >> 2;
    const int fc = lane & 3;
    #pragma unroll
    for (int jn = 0; jn < 4; jn++) {
        const int colp = col0 + wn*32 + jn*8 + fc*2;
        float b0 = ga.bias[colp], b1 = ga.bias[colp + 1];
        #pragma unroll
        for (int im = 0; im < 4; im++) {
            #pragma unroll
            for (int half = 0; half < 2; half++) {
                const int row = row0 + wm*64 + im*16 + fr + half*8;
                float v0 = acc[im][jn][half*2 + 0] + b0;
                float v1 = acc[im][jn][half*2 + 1] + b1;
                long o = (long)row*1024 + colp;
                float2 rr = *reinterpret_cast<const float2*>(ga.resid + o);
                *reinterpret_cast<float2*>(ga.C + o) = make_float2(v0 + rr.x, v1 + rr.y);
            }
        }
    }
}

// ---------------- fused attention: bf16 mma + ldmatrix + log2 softmax -------
// block 256 (8 warps: 4 warp-rows x 2 warp-cols), grid (16 l-tiles, 64 bn)
// c_u trick: G2 = QW.R + c_u  (c_u precomputed in g_cu) -> single A operand.
// smem byte layout:
//   QW  [64][72]  bf16  q+rwb          @ 0      (9216)
//   KT  [64][72]  bf16  m-major        @ 9216   (9216)
//   RB  [128][72] bf16  u-major        @ 18432  (18432)  Vs[64][72] union
//   G2s [64][132] fp32 [l][u]          @ 36864  (33792)  Ps[64][72] bf16 union
//   maskv[64] @ 70656, rmaxs[2][64] @ 70912, rsums[2][64] @ 71424, cu[128] @ 71936
#define QW_OFF   0
#define KT_OFF   9216
#define RB_OFF   18432
#define VS_OFF   18432
#define G2_OFF   36864
#define PS_OFF   36864
#define MK_OFF   70656
#define RM_OFF   70912
#define RS_OFF   71424
#define CU_OFF   71936
#define ATT_SMEM 72448
#define SC_LOG2 0.18033688011112042f   // 0.125 * log2(e)
#define MASK_LOG2 -1442695.04f         // -1e6 * log2(e)

__global__ __launch_bounds__(256, 2)
void attn_mma(const int* __restrict__ padding,
              const float* __restrict__ rwb)
{
    extern __shared__ char smB[];
    const uint32_t s0 = (uint32_t)__cvta_generic_to_shared(smB);
    float* G2s   = reinterpret_cast<float*>(smB + G2_OFF);
    float* maskv = reinterpret_cast<float*>(smB + MK_OFF);
    float* rmaxs = reinterpret_cast<float*>(smB + RM_OFF);
    float* rsums = reinterpret_cast<float*>(smB + RS_OFF);
    float* cu_s  = reinterpret_cast<float*>(smB + CU_OFF);

    const int tid  = threadIdx.x;
    const int lane = tid & 31;
    const int w    = tid >> 5;
    const int wr   = w >> 1;                  // 0..3
    const int wc   = w & 1;                   // 0..1
    const int fr   = lane >> 2;               // 0..7
    const int fc   = lane & 3;                // 0..3
    const int bn   = blockIdx.y;
    const int l0   = blockIdx.x * 64;
    const int b    = bn >> 4;
    const int n    = bn & 15;

    const float* qh = g_qh + (long)bn * (LL*HH);
    const float* kh = g_kh + (long)bn * (LL*HH);
    const float* vh = g_vh + (long)bn * (LL*HH);
    const float* rp = g_r  + (long)n  * (RR*HH);
    const float* cp = g_cu + (long)n  * RR;
    float*       op = g_o  + (long)bn * (LL*HH);

    // ---- prologue: QW = bf16(q + rwb)
    #pragma unroll
    for (int i = 0; i < 4; i++) {
        const int idx = tid + i*256;
        const int l = idx >> 4, hc = (idx & 15)*4;
        float4 v = *reinterpret_cast<const float4*>(qh + (long)(l0 + l)*64 + hc);
        float bw0 = rwb[n*64 + hc + 0], bw1 = rwb[n*64 + hc + 1];
        float bw2 = rwb[n*64 + hc + 2], bw3 = rwb[n*64 + hc + 3];
        *reinterpret_cast<uint2*>(smB + QW_OFF + l*144 + hc*2) =
            make_uint2(bf2(v.x + bw0, v.y + bw1), bf2(v.z + bw2, v.w + bw3));
    }

    // lane-static ldmatrix address components
    const int gA   = lane >> 3;
    const int rA   = lane & 7;
    const int rowA = wr*16 + (gA & 1)*8 + rA;
    const int colA = (gA >> 1)*8;
    const uint32_t aQW = s0 + QW_OFF + rowA*144 + colA*2;
    const uint32_t aPS = s0 + PS_OFF + rowA*144 + colA*2;
    const int nsel = (lane & 7) + ((lane & 16) >> 1);   // B x4: n offset
    const int ksel = (lane & 8);                        // B x4: k offset
    const int tsel = (lane & 15);                       // B x4t: k row
    const int csel = ((lane & 16) >> 1);                // B x4t: col offset

    float O[4][4];
    float mi[2], li[2];
    #pragma unroll
    for (int jn = 0; jn < 4; jn++)
        #pragma unroll
        for (int q = 0; q < 4; q++) O[jn][q] = 0.f;
    mi[0] = mi[1] = -1e30f;
    li[0] = li[1] = 0.f;

    for (int m0 = 0; m0 < LL; m0 += 64) {
        __syncthreads();   // prior tile's PV done before overwriting KT/RB/Ps

        // ---- stage: KT (bf16 m-major), RB band (bf16 u-major), maskv, cu
        #pragma unroll
        for (int i = 0; i < 4; i++) {
            const int idx = tid + i*256;
            const int m = idx >> 4, hc = (idx & 15)*4;
            float4 v = *reinterpret_cast<const float4*>(kh + (long)(m0 + m)*64 + hc);
            *reinterpret_cast<uint2*>(smB + KT_OFF + m*144 + hc*2) =
                make_uint2(bf2(v.x, v.y), bf2(v.z, v.w));
        }
        const int jmin = LL + m0 - l0 - 63;
        #pragma unroll
        for (int i = 0; i < 8; i++) {
            const int idx = tid + i*256;
            const int u = idx >> 4, hc = (idx & 15)*4;
            float4 v = make_float4(0.f,0.f,0.f,0.f);
            if (u < 127)
                v = *reinterpret_cast<const float4*>(rp + (long)(jmin + u)*64 + hc);
            *reinterpret_cast<uint2*>(smB + RB_OFF + u*144 + hc*2) =
                make_uint2(bf2(v.x, v.y), bf2(v.z, v.w));
        }
        if (tid < 64)
            maskv[tid] = (padding[b*LL + m0 + tid] != 0) ? MASK_LOG2 : 0.0f;
        if (tid < 128)
            cu_s[tid] = cp[jmin + tid];
        __syncthreads();

        // ---- loop1: G1 (s1) + G2 first half (g2a), single A per k-chunk
        float s1[4][4], g2[4][4];
        #pragma unroll
        for (int jn = 0; jn < 4; jn++)
            #pragma unroll
            for (int q = 0; q < 4; q++) { s1[jn][q] = 0.f; g2[jn][q] = 0.f; }
        #pragma unroll
        for (int k0 = 0; k0 < 64; k0 += 16) {
            uint32_t a[4];
            ldsm_x4(a[0], a[1], a[2], a[3], aQW + k0*2);
            #pragma unroll
            for (int p = 0; p < 2; p++) {
                uint32_t b4[4];
                ldsm_x4(b4[0], b4[1], b4[2], b4[3],
                        s0 + KT_OFF + (wc*32 + p*16 + nsel)*144 + (k0 + ksel)*2);
                mma_bf16(s1[p*2],   a, b4);
                mma_bf16(s1[p*2+1], a, b4 + 2);
            }
            #pragma unroll
            for (int p = 0; p < 2; p++) {
                uint32_t b4[4];
                ldsm_x4(b4[0], b4[1], b4[2], b4[3],
                        s0 + RB_OFF + (wc*64 + p*16 + nsel)*144 + (k0 + ksel)*2);
                mma_bf16(g2[p*2],   a, b4);
                mma_bf16(g2[p*2+1], a, b4 + 2);
            }
        }
        // spill g2a (+cu) -> G2s[l][u]
        {
            const int lb = (wr*16 + fr)*132;
            #pragma unroll
            for (int jn = 0; jn < 4; jn++) {
                const int ub = wc*64 + jn*8 + fc*2;
                float2 cc = *reinterpret_cast<const float2*>(&cu_s[ub]);
                *reinterpret_cast<float2*>(&G2s[lb + ub]) =
                    make_float2(g2[jn][0] + cc.x, g2[jn][1] + cc.y);
                *reinterpret_cast<float2*>(&G2s[lb + 8*132 + ub]) =
                    make_float2(g2[jn][2] + cc.x, g2[jn][3] + cc.y);
            }
        }
        // ---- loop2: G2 second half
        #pragma unroll
        for (int jn = 0; jn < 4; jn++)
            #pragma unroll
            for (int q = 0; q < 4; q++) g2[jn][q] = 0.f;
        #pragma unroll
        for (int k0 = 0; k0 < 64; k0 += 16) {
            uint32_t a[4];
            ldsm_x4(a[0], a[1], a[2], a[3], aQW + k0*2);
            #pragma unroll
            for (int p = 0; p < 2; p++) {
                uint32_t b4[4];
                ldsm_x4(b4[0], b4[1], b4[2], b4[3],
                        s0 + RB_OFF + (wc*64 + 32 + p*16 + nsel)*144 + (k0 + ksel)*2);
                mma_bf16(g2[p*2],   a, b4);
                mma_bf16(g2[p*2+1], a, b4 + 2);
            }
        }
        {
            const int lb = (wr*16 + fr)*132;
            #pragma unroll
            for (int jn = 0; jn < 4; jn++) {
                const int ub = wc*64 + 32 + jn*8 + fc*2;
                float2 cc = *reinterpret_cast<const float2*>(&cu_s[ub]);
                *reinterpret_cast<float2*>(&G2s[lb + ub]) =
                    make_float2(g2[jn][0] + cc.x, g2[jn][1] + cc.y);
                *reinterpret_cast<float2*>(&G2s[lb + 8*132 + ub]) =
                    make_float2(g2[jn][2] + cc.x, g2[jn][3] + cc.y);
            }
        }
        __syncthreads();   // G2s complete; RB reads done -> Vs may overwrite

        // ---- Vs load (bf16 m-major, over RB union) + gather + row max
        #pragma unroll
        for (int i = 0; i < 4; i++) {
            const int idx = tid + i*256;
            const int m = idx >> 4, hc = (idx & 15)*4;
            float4 v = *reinterpret_cast<const float4*>(vh + (long)(m0 + m)*64 + hc);
            *reinterpret_cast<uint2*>(smB + VS_OFF + m*144 + hc*2) =
                make_uint2(bf2(v.x, v.y), bf2(v.z, v.w));
        }

        float sv[4][4];
        float rmx[2] = {-1e30f, -1e30f};
        #pragma unroll
        for (int jn = 0; jn < 4; jn++) {
            #pragma unroll
            for (int q = 0; q < 4; q++) {
                const int ll = wr*16 + fr + (q >> 1)*8;
                const int mc = wc*32 + jn*8 + fc*2 + (q & 1);
                const int u  = mc - ll + 63;
                float x = (s1[jn][q] + G2s[ll*132 + u]) * SC_LOG2 + maskv[mc];
                sv[jn][q] = x;
                rmx[q >> 1] = fmaxf(rmx[q >> 1], x);
            }
        }
        #pragma unroll
        for (int r = 0; r < 2; r++) {
            rmx[r] = fmaxf(rmx[r], __shfl_xor_sync(0xffffffffu, rmx[r], 1));
            rmx[r] = fmaxf(rmx[r], __shfl_xor_sync(0xffffffffu, rmx[r], 2));
        }
        if (fc == 0) {
            rmaxs[wc*64 + wr*16 + fr]     = rmx[0];
            rmaxs[wc*64 + wr*16 + fr + 8] = rmx[1];
        }
        __syncthreads();   // row maxes ready

        // ---- softmax: exp2, P store (bf16), partial sums
        float nm[2], al[2], psum[2];
        #pragma unroll
        for (int r = 0; r < 2; r++) {
            const int row = wr*16 + fr + r*8;
            const float tm = fmaxf(rmaxs[row], rmaxs[64 + row]);
            nm[r] = fmaxf(mi[r], tm);
            al[r] = ex2f(mi[r] - nm[r]);
            mi[r] = nm[r];
            psum[r] = 0.f;
        }
        #pragma unroll
        for (int jn = 0; jn < 4; jn++) {
            #pragma unroll
            for (int r = 0; r < 2; r++) {
                float p0 = ex2f(sv[jn][r*2 + 0] - nm[r]);
                float p1 = ex2f(sv[jn][r*2 + 1] - nm[r]);
                psum[r] += p0 + p1;
                const int ll = wr*16 + fr + r*8;
                const int mc = wc*32 + jn*8 + fc*2;
                *reinterpret_cast<uint32_t*>(smB + PS_OFF + ll*144 + mc*2) = bf2(p0, p1);
            }
        }
        #pragma unroll
        for (int r = 0; r < 2; r++) {
            psum[r] += __shfl_xor_sync(0xffffffffu, psum[r], 1);
            psum[r] += __shfl_xor_sync(0xffffffffu, psum[r], 2);
        }
        if (fc == 0) {
            rsums[wc*64 + wr*16 + fr]     = psum[0];
            rsums[wc*64 + wr*16 + fr + 8] = psum[1];
        }
        __syncthreads();   // Ps + Vs + sums ready

        // ---- li update, O rescale, PV mma
        #pragma unroll
        for (int r = 0; r < 2; r++) {
            const int row = wr*16 + fr + r*8;
            li[r] = li[r]*al[r] + (rsums[row] + rsums[64 + row]);
        }
        #pragma unroll
        for (int jn = 0; jn < 4; jn++) {
            O[jn][0] *= al[0]; O[jn][1] *= al[0];
            O[jn][2] *= al[1]; O[jn][3] *= al[1];
        }
        #pragma unroll
        for (int k0 = 0; k0 < 64; k0 += 16) {
            uint32_t a[4];
            ldsm_x4(a[0], a[1], a[2], a[3], aPS + k0*2);
            #pragma unroll
            for (int p = 0; p < 2; p++) {
                uint32_t b4[4];
                ldsm_x4t(b4[0], b4[1], b4[2], b4[3],
                         s0 + VS_OFF + (k0 + tsel)*144 + (wc*32 + p*16 + csel)*2);
                mma_bf16(O[p*2],   a, b4);
                mma_bf16(O[p*2+1], a, b4 + 2);
            }
        }
    }

    // ---- final: normalize, round (feeds tf32 POST GEMM), write
    const float inv0 = 1.0f / li[0];
    const float inv1 = 1.0f / li[1];
    #pragma unroll
    for (int jn = 0; jn < 4; jn++) {
        const int col = wc*32 + jn*8 + fc*2;
        const int lr0 = l0 + wr*16 + fr;
        *reinterpret_cast<float2*>(op + (long)lr0*64 + col) =
            make_float2(tf32r(O[jn][0]*inv0), tf32r(O[jn][1]*inv0));
        *reinterpret_cast<float2*>(op + (long)(lr0 + 8)*64 + col) =
            make_float2(tf32r(O[jn][2]*inv1), tf32r(O[jn][3]*inv1));
    }
}

// ---------------- layernorm over D per (b,l) row (shuffle reduce) -----------
__global__ __launch_bounds__(256)
void ln_kernel(const float* __restrict__ lng, const float* __restrict__ lnb,
               float* __restrict__ out)
{
    __shared__ float part[8];
    __shared__ float bcast;
    const int row = blockIdx.x;
    const int tid = threadIdx.x;
    const int lane = tid & 31;
    const int wid = tid >> 5;
    const float* x = g_x + (long)row * DD;

    float4 v = reinterpret_cast<const float4*>(x)[tid];
    float s = v.x + v.y + v.z + v.w;
    #pragma unroll
    for (int off = 16; off > 0; off >>= 1)
        s += __shfl_xor_sync(0xffffffffu, s, off);
    if (lane == 0) part[wid] = s;
    __syncthreads();
    if (tid == 0) {
        float t = 0.f;
        #pragma unroll
        for (int i = 0; i < 8; i++) t += part[i];
        bcast = t * (1.f / DD);
    }
    __syncthreads();
    const float mu = bcast;

    float dx = v.x - mu, dy = v.y - mu, dz = v.z - mu, dw = v.w - mu;
    float vs = dx*dx + dy*dy + dz*dz + dw*dw;
    #pragma unroll
    for (int off = 16; off > 0; off >>= 1)
        vs += __shfl_xor_sync(0xffffffffu, vs, off);
    if (lane == 0) part[wid] = vs;
    __syncthreads();
    if (tid == 0) {
        float t = 0.f;
        #pragma unroll
        for (int i = 0; i < 8; i++) t += part[i];
        bcast = rsqrtf(t * (1.f / DD) + 1e-5f);
    }
    __syncthreads();
    const float inv = bcast;

    float4 g = reinterpret_cast<const float4*>(lng)[tid];
    float4 be = reinterpret_cast<const float4*>(lnb)[tid];
    float4 o;
    o.x = dx * inv * g.x + be.x;
    o.y = dy * inv * g.y + be.y;
    o.z = dz * inv * g.z + be.z;
    o.w = dw * inv * g.w + be.w;
    reinterpret_cast<float4*>(out + (long)row*DD)[tid] = o;
}

// ---------------- launcher ---------------------------------------------------
extern "C" void kernel_launch(void* const* d_in, const int* in_sizes, int n_in,
                              void* d_out, int out_size)
{
    const float* q   = (const float*)d_in[0];
    const float* k   = (const float*)d_in[1];
    const float* v   = (const float*)d_in[2];
    const float* pe  = (const float*)d_in[3];
    const int*   pad = (const int*)d_in[4];
    const float* q_w = (const float*)d_in[5];
    const float* k_w = (const float*)d_in[6];
    const float* k_b = (const float*)d_in[7];
    const float* v_w = (const float*)d_in[8];
    const float* v_b = (const float*)d_in[9];
    const float* rwb = (const float*)d_in[10];
    const float* rrb = (const float*)d_in[11];
    const float* rk  = (const float*)d_in[12];
    const float* pw  = (const float*)d_in[13];
    const float* pb  = (const float*)d_in[14];
    const float* lng = (const float*)d_in[15];
    const float* lnb = (const float*)d_in[16];

    void *p_qh, *p_kh, *p_vh, *p_r, *p_o, *p_x;
    void *p_tq, *p_tk, *p_tv, *p_tpe, *p_tqw, *p_tkw, *p_tvw, *p_trk, *p_tpw;
    cudaGetSymbolAddress(&p_qh, g_qh);
    cudaGetSymbolAddress(&p_kh, g_kh);
    cudaGetSymbolAddress(&p_vh, g_vh);
    cudaGetSymbolAddress(&p_r,  g_r);
    cudaGetSymbolAddress(&p_o,  g_o);
    cudaGetSymbolAddress(&p_x,  g_x);
    cudaGetSymbolAddress(&p_tq,  g_tq);
    cudaGetSymbolAddress(&p_tk,  g_tk);
    cudaGetSymbolAddress(&p_tv,  g_tv);
    cudaGetSymbolAddress(&p_tpe, g_tpe);
    cudaGetSymbolAddress(&p_tqw, g_tqw);
    cudaGetSymbolAddress(&p_tkw, g_tkw);
    cudaGetSymbolAddress(&p_tvw, g_tvw);
    cudaGetSymbolAddress(&p_trk, g_trk);
    cudaGetSymbolAddress(&p_tpw, g_tpw);

    const dim3 blk(256);

    // ---- pass 1: tf32-round all GEMM operands
    R9 r;
    r.in[0]=q;   r.out[0]=(float*)p_tq;  r.n[0]=BB*LL*DD;
    r.in[1]=k;   r.out[1]=(float*)p_tk;  r.n[1]=BB*LL*DD;
    r.in[2]=v;   r.out[2]=(float*)p_tv;  r.n[2]=BB*LL*DD;
    r.in[3]=pe;  r.out[3]=(float*)p_tpe; r.n[3]=RR*DD;
    r.in[4]=q_w; r.out[4]=(float*)p_tqw; r.n[4]=DD*NN*HH;
    r.in[5]=k_w; r.out[5]=(float*)p_tkw; r.n[5]=DD*NN*HH;
    r.in[6]=v_w; r.out[6]=(float*)p_tvw; r.n[6]=DD*NN*HH;
    r.in[7]=rk;  r.out[7]=(float*)p_trk; r.n[7]=NN*DD*HH;
    r.in[8]=pw;  r.out[8]=(float*)p_tpw; r.n[8]=NN*HH*DD;
    roundk<<<dim3(1024, 9), blk>>>(r);

    // ---- pass 2: q/k/v projections + rpos in ONE launch (grid.z = 0..3)
    cudaFuncSetAttribute(gemm_qkvr, cudaFuncAttributeMaxDynamicSharedMemorySize, GEMM_SMEM);
    cudaFuncSetAttribute(gemm_tf32<MODE_POST>, cudaFuncAttributeMaxDynamicSharedMemorySize, GEMM_SMEM);

    GemmArgs gq = { (const float*)p_tq,  (const float*)p_tqw, nullptr, nullptr, (float*)p_qh };
    GemmArgs gk = { (const float*)p_tk,  (const float*)p_tkw, k_b,     nullptr, (float*)p_kh };
    GemmArgs gv = { (const float*)p_tv,  (const float*)p_tvw, v_b,     nullptr, (float*)p_vh };
    GemmArgs gr = { (const float*)p_tpe, (const float*)p_trk, nullptr, nullptr, (float*)p_r  };
    gemm_qkvr<<<dim3(8, 32, 4), blk, GEMM_SMEM>>>(gq, gk, gv, gr);

    // ---- pass 2b: c_u = (rrb-rwb).r  (depends on g_r)
    cu_kernel<<<dim3(128), blk>>>(rwb, rrb);

    // ---- pass 3: fused attention
    cudaFuncSetAttribute(attn_mma, cudaFuncAttributeMaxDynamicSharedMemorySize, ATT_SMEM);
    attn_mma<<<dim3(LL/64, BB*NN), blk, ATT_SMEM>>>(pad, rwb);

    // ---- pass 4: post GEMM (+bias +residual)
    GemmArgs gp = { (const float*)p_o, (const float*)p_tpw, pb, q, (float*)p_x };
    gemm_tf32<MODE_POST><<<dim3(8, 32, 1), blk, GEMM_SMEM>>>(gp);

    // ---- pass 5: layernorm
    ln_kernel<<<BB*LL, blk>>>(lng, lnb, (float*)d_out);
}

// round 11
// speedup vs baseline: 8.2728x; 1.0639x over previous
#include <cuda_runtime.h>
#include <cuda_bf16.h>
#include <math.h>
#include <stdint.h>

#define BB 4
#define LL 1024
#define DD 1024
#define NN 16
#define HH 64
#define RR 2048

// ---------------- scratch (static device globals: no allocations allowed) ---
__device__ float g_qh[BB*NN*LL*HH];   // [b][n][l][h] (tf32-rounded)
__device__ float g_r [NN*RR*HH];      // [n][j][h] f32 (for cu_kernel)
__device__ float g_cu[NN*RR + 128];   // c[n][j] = (rrb-rwb)[n] . r[n][j]
__device__ float g_o [BB*NN*LL*HH];   // attention output (tf32-rounded)
__device__ float g_x [BB*LL*DD];      // pre-layernorm residual sum

// bf16 attention operands (written by projection epilogues)
__device__ __nv_bfloat16 g_khb[BB*NN*LL*HH];  // [b][n][m][h]
__device__ __nv_bfloat16 g_vhb[BB*NN*LL*HH];
__device__ __nv_bfloat16 g_rb [NN*RR*HH];     // [n][j][h]

// tf32-rounded operand copies
__device__ float g_tq [BB*LL*DD];
__device__ float g_tk [BB*LL*DD];
__device__ float g_tv [BB*LL*DD];
__device__ float g_tpe[RR*DD];
__device__ float g_tqw[DD*NN*HH];
__device__ float g_tkw[DD*NN*HH];
__device__ float g_tvw[DD*NN*HH];
__device__ float g_trk[NN*DD*HH];
__device__ float g_tpw[NN*HH*DD];

// ---------------- helpers ---------------------------------------------------
__device__ __forceinline__ float tf32r(float x) {
    uint32_t u;
    asm("cvt.rna.tf32.f32 %0, %1;" : "=r"(u) : "f"(x));
    return __uint_as_float(u);
}
__device__ __forceinline__ float ex2f(float x) {
    float y;
    asm("ex2.approx.ftz.f32 %0, %1;" : "=f"(y) : "f"(x));
    return y;
}
// pack (lo=a, hi=b) into bf16x2
__device__ __forceinline__ uint32_t bf2(float a, float b) {
    uint32_t r;
    asm("cvt.rn.bf16x2.f32 %0, %1, %2;" : "=r"(r) : "f"(b), "f"(a));
    return r;
}
__device__ __forceinline__ void cpa16(uint32_t dst, const void* src) {
    asm volatile("cp.async.cg.shared.global [%0], [%1], 16;\n" :: "r"(dst), "l"(src));
}

__device__ __forceinline__ void mma_tf32(float* d, const uint32_t* a, const uint32_t* b) {
    asm volatile(
        "mma.sync.aligned.m16n8k8.row.col.f32.tf32.tf32.f32 "
        "{%0,%1,%2,%3}, {%4,%5,%6,%7}, {%8,%9}, {%0,%1,%2,%3};\n"
        : "+f"(d[0]), "+f"(d[1]), "+f"(d[2]), "+f"(d[3])
        : "r"(a[0]), "r"(a[1]), "r"(a[2]), "r"(a[3]), "r"(b[0]), "r"(b[1]));
}
__device__ __forceinline__ void mma_bf16(float* d, const uint32_t* a, const uint32_t* b) {
    asm volatile(
        "mma.sync.aligned.m16n8k16.row.col.f32.bf16.bf16.f32 "
        "{%0,%1,%2,%3}, {%4,%5,%6,%7}, {%8,%9}, {%0,%1,%2,%3};\n"
        : "+f"(d[0]), "+f"(d[1]), "+f"(d[2]), "+f"(d[3])
        : "r"(a[0]), "r"(a[1]), "r"(a[2]), "r"(a[3]), "r"(b[0]), "r"(b[1]));
}
__device__ __forceinline__ void ldsm_x4(uint32_t& r0, uint32_t& r1, uint32_t& r2, uint32_t& r3, uint32_t addr) {
    asm volatile("ldmatrix.sync.aligned.m8n8.x4.shared.b16 {%0,%1,%2,%3}, [%4];"
                 : "=r"(r0), "=r"(r1), "=r"(r2), "=r"(r3) : "r"(addr));
}
__device__ __forceinline__ void ldsm_x4t(uint32_t& r0, uint32_t& r1, uint32_t& r2, uint32_t& r3, uint32_t addr) {
    asm volatile("ldmatrix.sync.aligned.m8n8.x4.trans.shared.b16 {%0,%1,%2,%3}, [%4];"
                 : "=r"(r0), "=r"(r1), "=r"(r2), "=r"(r3) : "r"(addr));
}

// ---------------- fused tf32 rounding pass (all GEMM operands) --------------
struct R9 {
    const float* in[9];
    float*       out[9];
    int          n[9];
};

__global__ __launch_bounds__(256)
void roundk(R9 r)
{
    const int seg = blockIdx.y;
    const float* in  = r.in[seg];
    float*       out = r.out[seg];
    const int n = r.n[seg];
    for (int i = (blockIdx.x*256 + threadIdx.x)*4; i < n; i += gridDim.x*256*4) {
        float4 v = *reinterpret_cast<const float4*>(in + i);
        v.x = tf32r(v.x); v.y = tf32r(v.y); v.z = tf32r(v.z); v.w = tf32r(v.w);
        *reinterpret_cast<float4*>(out + i) = v;
    }
}

// ---------------- c_u precompute: g_cu[n][j] = (rrb-rwb)[n] . g_r[n][j] -----
__global__ __launch_bounds__(256)
void cu_kernel(const float* __restrict__ rwb, const float* __restrict__ rrb)
{
    const int idx = blockIdx.x*256 + threadIdx.x;   // 32768 total
    const int n = idx >> 11;
    const int j = idx & 2047;
    const float* rr = g_r + ((long)n*RR + j)*HH;
    const float* dw = rwb + n*64;
    const float* dr = rrb + n*64;
    float acc = 0.f;
    #pragma unroll
    for (int h = 0; h < 64; h += 4) {
        float4 rv = *reinterpret_cast<const float4*>(rr + h);
        acc += (dr[h+0]-dw[h+0])*rv.x + (dr[h+1]-dw[h+1])*rv.y
             + (dr[h+2]-dw[h+2])*rv.z + (dr[h+3]-dw[h+3])*rv.w;
    }
    g_cu[idx] = acc;
}

// ---------------- tf32 tensor-core GEMM machinery ---------------------------
struct GemmArgs {
    const float* A;
    const float* W;
    const float* bias;
    const float* resid;
    float*       C;
};

#define AS_STRIDE 36
#define BS_STRIDE 136
#define AS_FLOATS (128*AS_STRIDE)
#define BS_FLOATS (32*BS_STRIDE)
#define GEMM_SMEM ((2*AS_FLOATS + 2*BS_FLOATS)*4)

// runtime-mode stage copy (A row-major; B: rpos picks r_kernel gather)
__device__ __forceinline__ void stage_copy_rt(
    const float* __restrict__ A, const float* __restrict__ W, bool rpos,
    uint32_t asB, uint32_t bsB, int row0, int col0, int k0, int tid)
{
    #pragma unroll
    for (int i = 0; i < 4; i++) {
        const int c = tid + i*256;
        const int arow = c >> 3, akc = (c & 7) * 4;
        const float* srcA = A + (long)(row0 + arow)*1024 + k0 + akc;
        asm volatile("cp.async.cg.shared.global [%0], [%1], 16;\n"
                     :: "r"(asB + (uint32_t)((arow*AS_STRIDE + akc)*4)), "l"(srcA));
        const int bk = c >> 5, bnc = (c & 31) * 4;
        const float* srcB;
        if (rpos) {
            const int col = col0 + bnc;
            srcB = W + (long)(col >> 6)*(DD*HH) + (long)(k0 + bk)*HH + (col & 63);
        } else {
            srcB = W + (long)(k0 + bk)*1024 + col0 + bnc;
        }
        asm volatile("cp.async.cg.shared.global [%0], [%1], 16;\n"
                     :: "r"(bsB + (uint32_t)((bk*BS_STRIDE + bnc)*4)), "l"(srcB));
    }
    asm volatile("cp.async.commit_group;\n");
}

// merged q/k/v projections + rpos in one launch (grid.z = 0..3)
// epilogues: z=0 -> g_qh f32; z=1 -> g_khb bf16; z=2 -> g_vhb bf16;
//            z=3 -> g_r f32 AND g_rb bf16
__global__ __launch_bounds__(256, 2)
void gemm_qkvr(GemmArgs g0, GemmArgs g1, GemmArgs g2, GemmArgs g3)
{
    const int z = blockIdx.z;
    const bool rpos = (z == 3);
    if (rpos && blockIdx.y >= 16) return;
    const GemmArgs ga = (z==0)?g0 : (z==1)?g1 : (z==2)?g2 : g3;

    extern __shared__ float smem[];
    float* As = smem;
    float* Bs = smem + 2*AS_FLOATS;

    const int tid  = threadIdx.x;
    const int lane = tid & 31;
    const int w    = tid >> 5;
    const int wm   = w & 1;
    const int wn   = w >> 1;
    const int row0 = blockIdx.y * 128;
    const int col0 = blockIdx.x * 128;

    const uint32_t asB = (uint32_t)__cvta_generic_to_shared(As);
    const uint32_t bsB = (uint32_t)__cvta_generic_to_shared(Bs);

    float acc[4][4][4];
    #pragma unroll
    for (int i = 0; i < 4; i++)
        #pragma unroll
        for (int j = 0; j < 4; j++)
            #pragma unroll
            for (int q = 0; q < 4; q++) acc[i][j][q] = 0.f;

    stage_copy_rt(ga.A, ga.W, rpos, asB, bsB, row0, col0, 0, tid);

    const int NIT = 1024/32;
    for (int it = 0; it < NIT; it++) {
        const int s = it & 1;
        if (it + 1 < NIT) {
            stage_copy_rt(ga.A, ga.W, rpos,
                          asB + (uint32_t)((s^1)*AS_FLOATS*4),
                          bsB + (uint32_t)((s^1)*BS_FLOATS*4),
                          row0, col0, (it+1)*32, tid);
            asm volatile("cp.async.wait_group 1;\n");
        } else {
            asm volatile("cp.async.wait_group 0;\n");
        }
        __syncthreads();

        const float* as = As + s*AS_FLOATS;
        const float* bs = Bs + s*BS_FLOATS;
        #pragma unroll
        for (int k8 = 0; k8 < 32; k8 += 8) {
            uint32_t af[4][4], bf[4][2];
            const int fr = lane >> 2;
            const int fc = lane & 3;
            #pragma unroll
            for (int im = 0; im < 4; im++) {
                const int r = wm*64 + im*16 + fr;
                const int c = k8 + fc;
                af[im][0] = __float_as_uint(as[r*AS_STRIDE + c]);
                af[im][1] = __float_as_uint(as[(r+8)*AS_STRIDE + c]);
                af[im][2] = __float_as_uint(as[r*AS_STRIDE + c + 4]);
                af[im][3] = __float_as_uint(as[(r+8)*AS_STRIDE + c + 4]);
            }
            #pragma unroll
            for (int jn = 0; jn < 4; jn++) {
                const int nn = wn*32 + jn*8 + fr;
                const int kk = k8 + fc;
                bf[jn][0] = __float_as_uint(bs[kk*BS_STRIDE + nn]);
                bf[jn][1] = __float_as_uint(bs[(kk+4)*BS_STRIDE + nn]);
            }
            #pragma unroll
            for (int im = 0; im < 4; im++)
                #pragma unroll
                for (int jn = 0; jn < 4; jn++)
                    mma_tf32(acc[im][jn], af[im], bf[jn]);
        }
        __syncthreads();
    }

    const int fr = lane >> 2;
    const int fc = lane & 3;
    #pragma unroll
    for (int jn = 0; jn < 4; jn++) {
        const int colp = col0 + wn*32 + jn*8 + fc*2;
        float b0 = 0.f, b1 = 0.f;
        if (!rpos && ga.bias != nullptr) {
            b0 = ga.bias[colp]; b1 = ga.bias[colp + 1];
        }
        #pragma unroll
        for (int im = 0; im < 4; im++) {
            #pragma unroll
            for (int half = 0; half < 2; half++) {
                const int row = row0 + wm*64 + im*16 + fr + half*8;
                float v0 = acc[im][jn][half*2 + 0] + b0;
                float v1 = acc[im][jn][half*2 + 1] + b1;
                if (rpos) {
                    long o = (long)(colp >> 6)*(RR*HH) + (long)row*HH + (colp & 63);
                    *reinterpret_cast<float2*>(g_r + o) = make_float2(tf32r(v0), tf32r(v1));
                    *reinterpret_cast<uint32_t*>(g_rb + o) = bf2(v0, v1);
                } else {
                    long o = (long)((row >> 10)*NN + (colp >> 6))*(LL*HH)
                           + (long)(row & 1023)*HH + (colp & 63);
                    if (z == 0)
                        *reinterpret_cast<float2*>(g_qh + o) = make_float2(tf32r(v0), tf32r(v1));
                    else if (z == 1)
                        *reinterpret_cast<uint32_t*>(g_khb + o) = bf2(v0, v1);
                    else
                        *reinterpret_cast<uint32_t*>(g_vhb + o) = bf2(v0, v1);
                }
            }
        }
    }
}

// POST gemm: A = g_o gather, row-major W, +bias +resid
__device__ __forceinline__ void stage_copy_post(
    const float* __restrict__ A, const float* __restrict__ W,
    uint32_t asB, uint32_t bsB, int row0, int col0, int k0, int tid)
{
    #pragma unroll
    for (int i = 0; i < 4; i++) {
        const int c = tid + i*256;
        const int arow = c >> 3, akc = (c & 7) * 4;
        const int row = row0 + arow, k = k0 + akc;
        const float* srcA = A + (long)(row >> 10)*(NN*LL*HH) + (long)(k >> 6)*(LL*HH)
                              + (long)(row & 1023)*HH + (k & 63);
        asm volatile("cp.async.cg.shared.global [%0], [%1], 16;\n"
                     :: "r"(asB + (uint32_t)((arow*AS_STRIDE + akc)*4)), "l"(srcA));
        const int bk = c >> 5, bnc = (c & 31) * 4;
        const float* srcB = W + (long)(k0 + bk)*1024 + col0 + bnc;
        asm volatile("cp.async.cg.shared.global [%0], [%1], 16;\n"
                     :: "r"(bsB + (uint32_t)((bk*BS_STRIDE + bnc)*4)), "l"(srcB));
    }
    asm volatile("cp.async.commit_group;\n");
}

__global__ __launch_bounds__(256, 2)
void gemm_post(GemmArgs ga)
{
    extern __shared__ float smem[];
    float* As = smem;
    float* Bs = smem + 2*AS_FLOATS;

    const int tid  = threadIdx.x;
    const int lane = tid & 31;
    const int w    = tid >> 5;
    const int wm   = w & 1;
    const int wn   = w >> 1;
    const int row0 = blockIdx.y * 128;
    const int col0 = blockIdx.x * 128;

    const uint32_t asB = (uint32_t)__cvta_generic_to_shared(As);
    const uint32_t bsB = (uint32_t)__cvta_generic_to_shared(Bs);

    float acc[4][4][4];
    #pragma unroll
    for (int i = 0; i < 4; i++)
        #pragma unroll
        for (int j = 0; j < 4; j++)
            #pragma unroll
            for (int q = 0; q < 4; q++) acc[i][j][q] = 0.f;

    stage_copy_post(ga.A, ga.W, asB, bsB, row0, col0, 0, tid);

    const int NIT = 1024/32;
    for (int it = 0; it < NIT; it++) {
        const int s = it & 1;
        if (it + 1 < NIT) {
            stage_copy_post(ga.A, ga.W,
                            asB + (uint32_t)((s^1)*AS_FLOATS*4),
                            bsB + (uint32_t)((s^1)*BS_FLOATS*4),
                            row0, col0, (it+1)*32, tid);
            asm volatile("cp.async.wait_group 1;\n");
        } else {
            asm volatile("cp.async.wait_group 0;\n");
        }
        __syncthreads();

        const float* as = As + s*AS_FLOATS;
        const float* bs = Bs + s*BS_FLOATS;
        #pragma unroll
        for (int k8 = 0; k8 < 32; k8 += 8) {
            uint32_t af[4][4], bf[4][2];
            const int fr = lane >> 2;
            const int fc = lane & 3;
            #pragma unroll
            for (int im = 0; im < 4; im++) {
                const int r = wm*64 + im*16 + fr;
                const int c = k8 + fc;
                af[im][0] = __float_as_uint(as[r*AS_STRIDE + c]);
                af[im][1] = __float_as_uint(as[(r+8)*AS_STRIDE + c]);
                af[im][2] = __float_as_uint(as[r*AS_STRIDE + c + 4]);
                af[im][3] = __float_as_uint(as[(r+8)*AS_STRIDE + c + 4]);
            }
            #pragma unroll
            for (int jn = 0; jn < 4; jn++) {
                const int nn = wn*32 + jn*8 + fr;
                const int kk = k8 + fc;
                bf[jn][0] = __float_as_uint(bs[kk*BS_STRIDE + nn]);
                bf[jn][1] = __float_as_uint(bs[(kk+4)*BS_STRIDE + nn]);
            }
            #pragma unroll
            for (int im = 0; im < 4; im++)
                #pragma unroll
                for (int jn = 0; jn < 4; jn++)
                    mma_tf32(acc[im][jn], af[im], bf[jn]);
        }
        __syncthreads();
    }

    const int fr = lane >> 2;
    const int fc = lane & 3;
    #pragma unroll
    for (int jn = 0; jn < 4; jn++) {
        const int colp = col0 + wn*32 + jn*8 + fc*2;
        float b0 = ga.bias[colp], b1 = ga.bias[colp + 1];
        #pragma unroll
        for (int im = 0; im < 4; im++) {
            #pragma unroll
            for (int half = 0; half < 2; half++) {
                const int row = row0 + wm*64 + im*16 + fr + half*8;
                float v0 = acc[im][jn][half*2 + 0] + b0;
                float v1 = acc[im][jn][half*2 + 1] + b1;
                long o = (long)row*1024 + colp;
                float2 rr = *reinterpret_cast<const float2*>(ga.resid + o);
                *reinterpret_cast<float2*>(ga.C + o) = make_float2(v0 + rr.x, v1 + rr.y);
            }
        }
    }
}

// ---------------- fused attention: bf16 mma + ldmatrix + cp.async staging ---
// block 256 (8 warps: 4 warp-rows x 2 warp-cols), grid (16 l-tiles, 64 bn)
// K/V/R staged straight from bf16 gmem via cp.async.cg (L1-bypassing, no
// register path); Vs in its own buffer, prefetched in a 2nd commit group so
// its arrival overlaps the G1/G2 mma work.
// smem byte layout (144-byte strides, conflict-free ldmatrix phases):
//   QW  [64][72]  bf16  q+rwb          @ 0      (9216)
//   KT  [64][72]  bf16  m-major        @ 9216   (9216)
//   RB  [128][72] bf16  u-major        @ 18432  (18432)  (row 127 zeroed once)
//   VS  [64][72]  bf16  m-major        @ 36864  (9216)
//   G2s [64][132] fp32 [l][u]          @ 46080  (33792)  Ps[64][72] bf16 union
//   maskv @ 79872, rmaxs @ 80128, rsums @ 80640, cu @ 81152
#define QW_OFF   0
#define KT_OFF   9216
#define RB_OFF   18432
#define VS_OFF   36864
#define G2_OFF   46080
#define PS_OFF   46080
#define MK_OFF   79872
#define RM_OFF   80128
#define RS_OFF   80640
#define CU_OFF   81152
#define ATT_SMEM 81664
#define SC_LOG2 0.18033688011112042f   // 0.125 * log2(e)
#define MASK_LOG2 -1442695.04f         // -1e6 * log2(e)

__global__ __launch_bounds__(256, 2)
void attn_mma(const int* __restrict__ padding,
              const float* __restrict__ rwb)
{
    extern __shared__ char smB[];
    const uint32_t s0 = (uint32_t)__cvta_generic_to_shared(smB);
    float* G2s   = reinterpret_cast<float*>(smB + G2_OFF);
    float* maskv = reinterpret_cast<float*>(smB + MK_OFF);
    float* rmaxs = reinterpret_cast<float*>(smB + RM_OFF);
    float* rsums = reinterpret_cast<float*>(smB + RS_OFF);
    float* cu_s  = reinterpret_cast<float*>(smB + CU_OFF);

    const int tid  = threadIdx.x;
    const int lane = tid & 31;
    const int w    = tid >> 5;
    const int wr   = w >> 1;                  // 0..3
    const int wc   = w & 1;                   // 0..1
    const int fr   = lane >> 2;               // 0..7
    const int fc   = lane & 3;                // 0..3
    const int bn   = blockIdx.y;
    const int l0   = blockIdx.x * 64;
    const int b    = bn >> 4;
    const int n    = bn & 15;

    const float* qh = g_qh + (long)bn * (LL*HH);
    const __nv_bfloat16* khb = g_khb + (long)bn * (LL*HH);
    const __nv_bfloat16* vhb = g_vhb + (long)bn * (LL*HH);
    const __nv_bfloat16* rbp = g_rb  + (long)n  * (RR*HH);
    const float* cp = g_cu + (long)n  * RR;
    float*       op = g_o  + (long)bn * (LL*HH);

    // ---- prologue: QW = bf16(q + rwb); zero RB row 127 (never re-written)
    #pragma unroll
    for (int i = 0; i < 4; i++) {
        const int idx = tid + i*256;
        const int l = idx >> 4, hc = (idx & 15)*4;
        float4 v = *reinterpret_cast<const float4*>(qh + (long)(l0 + l)*64 + hc);
        float bw0 = rwb[n*64 + hc + 0], bw1 = rwb[n*64 + hc + 1];
        float bw2 = rwb[n*64 + hc + 2], bw3 = rwb[n*64 + hc + 3];
        *reinterpret_cast<uint2*>(smB + QW_OFF + l*144 + hc*2) =
            make_uint2(bf2(v.x + bw0, v.y + bw1), bf2(v.z + bw2, v.w + bw3));
    }
    if (tid < 36)
        reinterpret_cast<float*>(smB + RB_OFF + 127*144)[tid] = 0.f;

    // lane-static ldmatrix address components
    const int gA   = lane >> 3;
    const int rA   = lane & 7;
    const int rowA = wr*16 + (gA & 1)*8 + rA;
    const int colA = (gA >> 1)*8;
    const uint32_t aQW = s0 + QW_OFF + rowA*144 + colA*2;
    const uint32_t aPS = s0 + PS_OFF + rowA*144 + colA*2;
    const int nsel = (lane & 7) + ((lane & 16) >> 1);   // B x4: n offset
    const int ksel = (lane & 8);                        // B x4: k offset
    const int tsel = (lane & 15);                       // B x4t: k row
    const int csel = ((lane & 16) >> 1);                // B x4t: col offset

    float O[4][4];
    float mi[2], li[2];
    #pragma unroll
    for (int jn = 0; jn < 4; jn++)
        #pragma unroll
        for (int q = 0; q < 4; q++) O[jn][q] = 0.f;
    mi[0] = mi[1] = -1e30f;
    li[0] = li[1] = 0.f;

    for (int m0 = 0; m0 < LL; m0 += 64) {
        __syncthreads();   // prior tile's reads done before rewriting buffers

        // ---- cp.async staging: group1 = KT+RB, group2 = VS (overlaps mma)
        const int jmin = LL + m0 - l0 - 63;
        #pragma unroll
        for (int i = 0; i < 2; i++) {
            const int idx = tid + i*256;           // 512 chunks
            const int row = idx >> 3, c = (idx & 7)*8;
            cpa16(s0 + KT_OFF + row*144 + c*2, khb + (long)(m0 + row)*64 + c);
        }
        #pragma unroll
        for (int i = 0; i < 4; i++) {
            const int idx = tid + i*256;           // 1016 chunks (rows 0..126)
            if (idx < 1016) {
                const int row = idx >> 3, c = (idx & 7)*8;
                cpa16(s0 + RB_OFF + row*144 + c*2, rbp + (long)(jmin + row)*64 + c);
            }
        }
        asm volatile("cp.async.commit_group;\n");
        #pragma unroll
        for (int i = 0; i < 2; i++) {
            const int idx = tid + i*256;
            const int row = idx >> 3, c = (idx & 7)*8;
            cpa16(s0 + VS_OFF + row*144 + c*2, vhb + (long)(m0 + row)*64 + c);
        }
        asm volatile("cp.async.commit_group;\n");

        if (tid < 64)
            maskv[tid] = (padding[b*LL + m0 + tid] != 0) ? MASK_LOG2 : 0.0f;
        if (tid < 128)
            cu_s[tid] = cp[jmin + tid];

        asm volatile("cp.async.wait_group 1;\n");   // KT+RB landed (VS in flight)
        __syncthreads();

        // ---- loop1: G1 (s1) + G2 first half, single A per k-chunk
        float s1[4][4], g2[4][4];
        #pragma unroll
        for (int jn = 0; jn < 4; jn++)
            #pragma unroll
            for (int q = 0; q < 4; q++) { s1[jn][q] = 0.f; g2[jn][q] = 0.f; }
        #pragma unroll
        for (int k0 = 0; k0 < 64; k0 += 16) {
            uint32_t a[4];
            ldsm_x4(a[0], a[1], a[2], a[3], aQW + k0*2);
            #pragma unroll
            for (int p = 0; p < 2; p++) {
                uint32_t b4[4];
                ldsm_x4(b4[0], b4[1], b4[2], b4[3],
                        s0 + KT_OFF + (wc*32 + p*16 + nsel)*144 + (k0 + ksel)*2);
                mma_bf16(s1[p*2],   a, b4);
                mma_bf16(s1[p*2+1], a, b4 + 2);
            }
            #pragma unroll
            for (int p = 0; p < 2; p++) {
                uint32_t b4[4];
                ldsm_x4(b4[0], b4[1], b4[2], b4[3],
                        s0 + RB_OFF + (wc*64 + p*16 + nsel)*144 + (k0 + ksel)*2);
                mma_bf16(g2[p*2],   a, b4);
                mma_bf16(g2[p*2+1], a, b4 + 2);
            }
        }
        // spill g2 half A (+cu) -> G2s[l][u]
        {
            const int lb = (wr*16 + fr)*132;
            #pragma unroll
            for (int jn = 0; jn < 4; jn++) {
                const int ub = wc*64 + jn*8 + fc*2;
                float2 cc = *reinterpret_cast<const float2*>(&cu_s[ub]);
                *reinterpret_cast<float2*>(&G2s[lb + ub]) =
                    make_float2(g2[jn][0] + cc.x, g2[jn][1] + cc.y);
                *reinterpret_cast<float2*>(&G2s[lb + 8*132 + ub]) =
                    make_float2(g2[jn][2] + cc.x, g2[jn][3] + cc.y);
            }
        }
        // ---- loop2: G2 second half
        #pragma unroll
        for (int jn = 0; jn < 4; jn++)
            #pragma unroll
            for (int q = 0; q < 4; q++) g2[jn][q] = 0.f;
        #pragma unroll
        for (int k0 = 0; k0 < 64; k0 += 16) {
            uint32_t a[4];
            ldsm_x4(a[0], a[1], a[2], a[3], aQW + k0*2);
            #pragma unroll
            for (int p = 0; p < 2; p++) {
                uint32_t b4[4];
                ldsm_x4(b4[0], b4[1], b4[2], b4[3],
                        s0 + RB_OFF + (wc*64 + 32 + p*16 + nsel)*144 + (k0 + ksel)*2);
                mma_bf16(g2[p*2],   a, b4);
                mma_bf16(g2[p*2+1], a, b4 + 2);
            }
        }
        {
            const int lb = (wr*16 + fr)*132;
            #pragma unroll
            for (int jn = 0; jn < 4; jn++) {
                const int ub = wc*64 + 32 + jn*8 + fc*2;
                float2 cc = *reinterpret_cast<const float2*>(&cu_s[ub]);
                *reinterpret_cast<float2*>(&G2s[lb + ub]) =
                    make_float2(g2[jn][0] + cc.x, g2[jn][1] + cc.y);
                *reinterpret_cast<float2*>(&G2s[lb + 8*132 + ub]) =
                    make_float2(g2[jn][2] + cc.x, g2[jn][3] + cc.y);
            }
        }
        __syncthreads();   // G2s complete

        // ---- diagonal gather + row max
        float sv[4][4];
        float rmx[2] = {-1e30f, -1e30f};
        #pragma unroll
        for (int jn = 0; jn < 4; jn++) {
            #pragma unroll
            for (int q = 0; q < 4; q++) {
                const int ll = wr*16 + fr + (q >> 1)*8;
                const int mc = wc*32 + jn*8 + fc*2 + (q & 1);
                const int u  = mc - ll + 63;
                float x = (s1[jn][q] + G2s[ll*132 + u]) * SC_LOG2 + maskv[mc];
                sv[jn][q] = x;
                rmx[q >> 1] = fmaxf(rmx[q >> 1], x);
            }
        }
        #pragma unroll
        for (int r = 0; r < 2; r++) {
            rmx[r] = fmaxf(rmx[r], __shfl_xor_sync(0xffffffffu, rmx[r], 1));
            rmx[r] = fmaxf(rmx[r], __shfl_xor_sync(0xffffffffu, rmx[r], 2));
        }
        if (fc == 0) {
            rmaxs[wc*64 + wr*16 + fr]     = rmx[0];
            rmaxs[wc*64 + wr*16 + fr + 8] = rmx[1];
        }
        __syncthreads();   // row maxes ready; all G2s gathers done

        // ---- softmax: exp2, P store (bf16), partial sums
        float nm[2], al[2], psum[2];
        #pragma unroll
        for (int r = 0; r < 2; r++) {
            const int row = wr*16 + fr + r*8;
            const float tm = fmaxf(rmaxs[row], rmaxs[64 + row]);
            nm[r] = fmaxf(mi[r], tm);
            al[r] = ex2f(mi[r] - nm[r]);
            mi[r] = nm[r];
            psum[r] = 0.f;
        }
        #pragma unroll
        for (int jn = 0; jn < 4; jn++) {
            #pragma unroll
            for (int r = 0; r < 2; r++) {
                float p0 = ex2f(sv[jn][r*2 + 0] - nm[r]);
                float p1 = ex2f(sv[jn][r*2 + 1] - nm[r]);
                psum[r] += p0 + p1;
                const int ll = wr*16 + fr + r*8;
                const int mc = wc*32 + jn*8 + fc*2;
                *reinterpret_cast<uint32_t*>(smB + PS_OFF + ll*144 + mc*2) = bf2(p0, p1);
            }
        }
        #pragma unroll
        for (int r = 0; r < 2; r++) {
            psum[r] += __shfl_xor_sync(0xffffffffu, psum[r], 1);
            psum[r] += __shfl_xor_sync(0xffffffffu, psum[r], 2);
        }
        if (fc == 0) {
            rsums[wc*64 + wr*16 + fr]     = psum[0];
            rsums[wc*64 + wr*16 + fr + 8] = psum[1];
        }
        asm volatile("cp.async.wait_group 0;\n");   // VS landed
        __syncthreads();   // Ps + Vs + sums ready

        // ---- li update, O rescale, PV mma
        #pragma unroll
        for (int r = 0; r < 2; r++) {
            const int row = wr*16 + fr + r*8;
            li[r] = li[r]*al[r] + (rsums[row] + rsums[64 + row]);
        }
        #pragma unroll
        for (int jn = 0; jn < 4; jn++) {
            O[jn][0] *= al[0]; O[jn][1] *= al[0];
            O[jn][2] *= al[1]; O[jn][3] *= al[1];
        }
        #pragma unroll
        for (int k0 = 0; k0 < 64; k0 += 16) {
            uint32_t a[4];
            ldsm_x4(a[0], a[1], a[2], a[3], aPS + k0*2);
            #pragma unroll
            for (int p = 0; p < 2; p++) {
                uint32_t b4[4];
                ldsm_x4t(b4[0], b4[1], b4[2], b4[3],
                         s0 + VS_OFF + (k0 + tsel)*144 + (wc*32 + p*16 + csel)*2);
                mma_bf16(O[p*2],   a, b4);
                mma_bf16(O[p*2+1], a, b4 + 2);
            }
        }
    }

    // ---- final: normalize, round (feeds tf32 POST GEMM), write
    const float inv0 = 1.0f / li[0];
    const float inv1 = 1.0f / li[1];
    #pragma unroll
    for (int jn = 0; jn < 4; jn++) {
        const int col = wc*32 + jn*8 + fc*2;
        const int lr0 = l0 + wr*16 + fr;
        *reinterpret_cast<float2*>(op + (long)lr0*64 + col) =
            make_float2(tf32r(O[jn][0]*inv0), tf32r(O[jn][1]*inv0));
        *reinterpret_cast<float2*>(op + (long)(lr0 + 8)*64 + col) =
            make_float2(tf32r(O[jn][2]*inv1), tf32r(O[jn][3]*inv1));
    }
}

// ---------------- layernorm over D per (b,l) row (shuffle reduce) -----------
__global__ __launch_bounds__(256)
void ln_kernel(const float* __restrict__ lng, const float* __restrict__ lnb,
               float* __restrict__ out)
{
    __shared__ float part[8];
    __shared__ float bcast;
    const int row = blockIdx.x;
    const int tid = threadIdx.x;
    const int lane = tid & 31;
    const int wid = tid >> 5;
    const float* x = g_x + (long)row * DD;

    float4 v = reinterpret_cast<const float4*>(x)[tid];
    float s = v.x + v.y + v.z + v.w;
    #pragma unroll
    for (int off = 16; off > 0; off >>= 1)
        s += __shfl_xor_sync(0xffffffffu, s, off);
    if (lane == 0) part[wid] = s;
    __syncthreads();
    if (tid == 0) {
        float t = 0.f;
        #pragma unroll
        for (int i = 0; i < 8; i++) t += part[i];
        bcast = t * (1.f / DD);
    }
    __syncthreads();
    const float mu = bcast;

    float dx = v.x - mu, dy = v.y - mu, dz = v.z - mu, dw = v.w - mu;
    float vs = dx*dx + dy*dy + dz*dz + dw*dw;
    #pragma unroll
    for (int off = 16; off > 0; off >>= 1)
        vs += __shfl_xor_sync(0xffffffffu, vs, off);
    if (lane == 0) part[wid] = vs;
    __syncthreads();
    if (tid == 0) {
        float t = 0.f;
        #pragma unroll
        for (int i = 0; i < 8; i++) t += part[i];
        bcast = rsqrtf(t * (1.f / DD) + 1e-5f);
    }
    __syncthreads();
    const float inv = bcast;

    float4 g = reinterpret_cast<const float4*>(lng)[tid];
    float4 be = reinterpret_cast<const float4*>(lnb)[tid];
    float4 o;
    o.x = dx * inv * g.x + be.x;
    o.y = dy * inv * g.y + be.y;
    o.z = dz * inv * g.z + be.z;
    o.w = dw * inv * g.w + be.w;
    reinterpret_cast<float4*>(out + (long)row*DD)[tid] = o;
}

// ---------------- launcher ---------------------------------------------------
extern "C" void kernel_launch(void* const* d_in, const int* in_sizes, int n_in,
                              void* d_out, int out_size)
{
    const float* q   = (const float*)d_in[0];
    const float* k   = (const float*)d_in[1];
    const float* v   = (const float*)d_in[2];
    const float* pe  = (const float*)d_in[3];
    const int*   pad = (const int*)d_in[4];
    const float* q_w = (const float*)d_in[5];
    const float* k_w = (const float*)d_in[6];
    const float* k_b = (const float*)d_in[7];
    const float* v_w = (const float*)d_in[8];
    const float* v_b = (const float*)d_in[9];
    const float* rwb = (const float*)d_in[10];
    const float* rrb = (const float*)d_in[11];
    const float* rk  = (const float*)d_in[12];
    const float* pw  = (const float*)d_in[13];
    const float* pb  = (const float*)d_in[14];
    const float* lng = (const float*)d_in[15];
    const float* lnb = (const float*)d_in[16];

    void *p_qh, *p_o, *p_x;
    void *p_tq, *p_tk, *p_tv, *p_tpe, *p_tqw, *p_tkw, *p_tvw, *p_trk, *p_tpw;
    cudaGetSymbolAddress(&p_qh, g_qh);
    cudaGetSymbolAddress(&p_o,  g_o);
    cudaGetSymbolAddress(&p_x,  g_x);
    cudaGetSymbolAddress(&p_tq,  g_tq);
    cudaGetSymbolAddress(&p_tk,  g_tk);
    cudaGetSymbolAddress(&p_tv,  g_tv);
    cudaGetSymbolAddress(&p_tpe, g_tpe);
    cudaGetSymbolAddress(&p_tqw, g_tqw);
    cudaGetSymbolAddress(&p_tkw, g_tkw);
    cudaGetSymbolAddress(&p_tvw, g_tvw);
    cudaGetSymbolAddress(&p_trk, g_trk);
    cudaGetSymbolAddress(&p_tpw, g_tpw);

    const dim3 blk(256);

    // ---- pass 1: tf32-round all GEMM operands
    R9 r;
    r.in[0]=q;   r.out[0]=(float*)p_tq;  r.n[0]=BB*LL*DD;
    r.in[1]=k;   r.out[1]=(float*)p_tk;  r.n[1]=BB*LL*DD;
    r.in[2]=v;   r.out[2]=(float*)p_tv;  r.n[2]=BB*LL*DD;
    r.in[3]=pe;  r.out[3]=(float*)p_tpe; r.n[3]=RR*DD;
    r.in[4]=q_w; r.out[4]=(float*)p_tqw; r.n[4]=DD*NN*HH;
    r.in[5]=k_w; r.out[5]=(float*)p_tkw; r.n[5]=DD*NN*HH;
    r.in[6]=v_w; r.out[6]=(float*)p_tvw; r.n[6]=DD*NN*HH;
    r.in[7]=rk;  r.out[7]=(float*)p_trk; r.n[7]=NN*DD*HH;
    r.in[8]=pw;  r.out[8]=(float*)p_tpw; r.n[8]=NN*HH*DD;
    roundk<<<dim3(1024, 9), blk>>>(r);

    // ---- pass 2: q/k/v projections + rpos in ONE launch (grid.z = 0..3)
    cudaFuncSetAttribute(gemm_qkvr, cudaFuncAttributeMaxDynamicSharedMemorySize, GEMM_SMEM);
    cudaFuncSetAttribute(gemm_post, cudaFuncAttributeMaxDynamicSharedMemorySize, GEMM_SMEM);

    GemmArgs gq = { (const float*)p_tq,  (const float*)p_tqw, nullptr, nullptr, (float*)p_qh };
    GemmArgs gk = { (const float*)p_tk,  (const float*)p_tkw, k_b,     nullptr, (float*)p_qh };
    GemmArgs gv = { (const float*)p_tv,  (const float*)p_tvw, v_b,     nullptr, (float*)p_qh };
    GemmArgs gr = { (const float*)p_tpe, (const float*)p_trk, nullptr, nullptr, (float*)p_qh };
    gemm_qkvr<<<dim3(8, 32, 4), blk, GEMM_SMEM>>>(gq, gk, gv, gr);

    // ---- pass 2b: c_u = (rrb-rwb).r  (depends on g_r)
    cu_kernel<<<dim3(128), blk>>>(rwb, rrb);

    // ---- pass 3: fused attention
    cudaFuncSetAttribute(attn_mma, cudaFuncAttributeMaxDynamicSharedMemorySize, ATT_SMEM);
    attn_mma<<<dim3(LL/64, BB*NN), blk, ATT_SMEM>>>(pad, rwb);

    // ---- pass 4: post GEMM (+bias +residual)
    GemmArgs gp = { (const float*)p_o, (const float*)p_tpw, pb, q, (float*)p_x };
    gemm_post<<<dim3(8, 32, 1), blk, GEMM_SMEM>>>(gp);

    // ---- pass 5: layernorm
    ln_kernel<<<BB*LL, blk>>>(lng, lnb, (float*)d_out);
}